// round 10
// baseline (speedup 1.0000x reference)
#include <cuda_runtime.h>
#include <cuda_bf16.h>
#include <mma.h>
using namespace nvcuda;

#define NDST 100000
#define NDST_P 100032
#define NE   1000000
#define UN   200000
#define UE   100000
#define UE_P 100032
#define UT   100000
#define UT_P 100032
#define DN_  172
#define DT_  100
#define DO_  100
#define NEG_SLOPE 0.2f

#define NP_KV 208
#define NP_Q  112
#define KP_ND 176
#define KP_T  112
#define KP_OUT 288

// split-weight arena offsets (bf16 elements)
#define OFF_KVN_H 0
#define OFF_KVN_L (OFF_KVN_H + KP_ND * NP_KV)
#define OFF_KVE_H (OFF_KVN_L + KP_ND * NP_KV)
#define OFF_KVE_L (OFF_KVE_H + KP_ND * NP_KV)
#define OFF_KVT_H (OFF_KVE_L + KP_ND * NP_KV)
#define OFF_KVT_L (OFF_KVT_H + KP_T * NP_KV)
#define OFF_QN_H  (OFF_KVT_L + KP_T * NP_KV)
#define OFF_QN_L  (OFF_QN_H + KP_ND * NP_Q)
#define OFF_OUT_H (OFF_QN_L + KP_ND * NP_Q)
#define OFF_OUT_L (OFF_OUT_H + KP_OUT * NP_Q)
#define WSPLIT_TOTAL (OFF_OUT_L + KP_OUT * NP_Q)

// ---------------- scratch (device globals; no allocation) ----------------
__device__ float         g_Q   [NDST_P * NP_Q];
__device__ float         g_KVN [UN * NP_KV];
__device__ float         g_KVE [UE_P * NP_KV];
__device__ float         g_KVT [UT_P * NP_KV];
__device__ float         g_acc [NDST * DO_];
__device__ float         g_biasq[DO_];
__device__ __nv_bfloat16 g_WS  [WSPLIT_TOTAL];
__device__ int           g_cnt [NDST];
__device__ int           g_off [NDST + 1];
__device__ int           g_cur [NDST];
__device__ int4          g_pack[NE];

// ---------------- init ----------------
__global__ void init_kernel() {
    int idx = blockIdx.x * blockDim.x + threadIdx.x;
    int stride = gridDim.x * blockDim.x;
    for (int i = idx; i < NDST; i += stride) g_cnt[i] = 0;
}

__global__ void biasq_kernel(const float* __restrict__ time_b,
                             const float* __restrict__ Wqt,
                             const float* __restrict__ bqt,
                             const float* __restrict__ bqn) {
    int j = threadIdx.x;
    if (j >= DO_) return;
    float acc = bqt[j] + bqn[j];
    for (int k = 0; k < DT_; k++) acc += cosf(time_b[k]) * Wqt[k * DO_ + j];
    g_biasq[j] = acc;
}

// ---------------- weight split: rows 0..K-1 = W, row K = bias sum, rest 0 ----------------
__global__ void split_w(const float* __restrict__ W,
                        const float* __restrict__ b0, const float* __restrict__ b1,
                        const float* __restrict__ b2,
                        __nv_bfloat16* __restrict__ oh, __nv_bfloat16* __restrict__ ol,
                        int K, int N, int KP, int NP) {
    int idx = blockIdx.x * blockDim.x + threadIdx.x;
    if (idx >= KP * NP) return;
    int k = idx / NP, n = idx - k * NP;
    float val = 0.f;
    if (n < N) {
        if (k < K) val = W[(long)k * N + n];
        else if (k == K) {
            if (b0) val += b0[n];
            if (b1) val += b1[n];
            if (b2) val += b2[n];
        }
    }
    __nv_bfloat16 h = __float2bfloat16(val);
    oh[idx] = h;
    ol[idx] = __float2bfloat16(val - __bfloat162float(h));
}

// ---------------- CSR build ----------------
__global__ void hist_kernel(const int* __restrict__ dsti) {
    int idx = blockIdx.x * blockDim.x + threadIdx.x;
    int stride = gridDim.x * blockDim.x;
    for (int e = idx; e < NE; e += stride) atomicAdd(&g_cnt[dsti[e]], 1);
}

#define SCH ((NDST + 1023) / 1024)
__global__ __launch_bounds__(1024)
void scan_kernel() {
    __shared__ int ss[1024];
    int t = threadIdx.x;
    int base = t * SCH;
    int end = base + SCH < NDST ? base + SCH : NDST;
    int sum = 0;
    for (int i = base; i < end; i++) sum += g_cnt[i];
    ss[t] = sum;
    __syncthreads();
    for (int off = 1; off < 1024; off <<= 1) {
        int v = (t >= off) ? ss[t - off] : 0;
        __syncthreads();
        ss[t] += v;
        __syncthreads();
    }
    int run = (t == 0) ? 0 : ss[t - 1];
    for (int i = base; i < end; i++) {
        g_off[i] = run;
        g_cur[i] = run;
        run += g_cnt[i];
    }
    if (t == 1023) g_off[NDST] = NE;
}

__global__ void scatter_kernel(const int* __restrict__ dsti,
                               const int* __restrict__ node_inv,
                               const int* __restrict__ eids,
                               const int* __restrict__ tids) {
    int idx = blockIdx.x * blockDim.x + threadIdx.x;
    int stride = gridDim.x * blockDim.x;
    for (int e = idx; e < NE; e += stride) {
        int pos = atomicAdd(&g_cur[dsti[e]], 1);
        g_pack[pos] = make_int4(node_inv[e], eids[e], tids[e], 0);
    }
}

// ---------------- bf16x2 GEMM v4: single k-loop, 4 N-tiles/warp, double-buffered B ----------------
// 256 threads (8 warps = 2M x 4Ngroups), BM=64. A hi/lo staged once across full K.
// TIMEF: A[row,k] = cos(utd[row]*tw[k]+tb[k]) computed inline (kvt path).
template <bool GATHER, bool TIMEF>
__global__ __launch_bounds__(256)
void gemm_bf3(const float* __restrict__ A,
              const __nv_bfloat16* __restrict__ Wh, const __nv_bfloat16* __restrict__ Wl,
              float* __restrict__ C, const int* __restrict__ gidx,
              const float* __restrict__ utd, const float* __restrict__ tw,
              const float* __restrict__ tb,
              int M, int K, int KP, int NP) {
    extern __shared__ char smraw[];
    const int LDA = KP + 8;
    __nv_bfloat16* Ah = (__nv_bfloat16*)smraw;
    __nv_bfloat16* Al = Ah + 64 * LDA;
    int tid = threadIdx.x, wid = tid >> 5;
    int m0 = blockIdx.x * 64;

    // stage A hi/lo, zero-padded; col K = 1.0 (bias row selector)
    int nc4 = KP >> 2;
    for (int idx = tid; idx < 64 * nc4; idx += 256) {
        int r = idx / nc4, c4 = idx - r * nc4;
        int row = m0 + r;
        float4 v = make_float4(0.f, 0.f, 0.f, 0.f);
        if (row < M) {
            int k = c4 * 4;
            if (TIMEF) {
                if (k + 3 < K) {
                    float4 w4 = *(const float4*)(tw + k);
                    float4 b4 = *(const float4*)(tb + k);
                    float td = utd[row];
                    v.x = cosf(td * w4.x + b4.x);
                    v.y = cosf(td * w4.y + b4.y);
                    v.z = cosf(td * w4.z + b4.z);
                    v.w = cosf(td * w4.w + b4.w);
                } else if (K >= k && K < k + 4) {
                    ((float*)&v)[K - k] = 1.0f;
                }
            } else {
                long ab = (long)(GATHER ? gidx[row] : row) * K;
                if (k + 3 < K) {
                    v = *(const float4*)(A + ab + k);
                } else {
                    if (k + 0 < K) v.x = A[ab + k + 0];
                    if (k + 1 < K) v.y = A[ab + k + 1];
                    if (k + 2 < K) v.z = A[ab + k + 2];
                    if (k + 3 < K) v.w = A[ab + k + 3];
                }
                if (K >= k && K < k + 4) ((float*)&v)[K - k] = 1.0f;
            }
        }
        int off = r * LDA + c4 * 4;
        __nv_bfloat16 h; float x;
        x = v.x; h = __float2bfloat16(x); Ah[off + 0] = h; Al[off + 0] = __float2bfloat16(x - __bfloat162float(h));
        x = v.y; h = __float2bfloat16(x); Ah[off + 1] = h; Al[off + 1] = __float2bfloat16(x - __bfloat162float(h));
        x = v.z; h = __float2bfloat16(x); Ah[off + 2] = h; Al[off + 2] = __float2bfloat16(x - __bfloat162float(h));
        x = v.w; h = __float2bfloat16(x); Ah[off + 3] = h; Al[off + 3] = __float2bfloat16(x - __bfloat162float(h));
    }
    __syncthreads();

    int wm = (wid >> 2) * 32;   // 0 or 32
    int wt = wid & 3;           // N-group 0..3; tiles wt + 4t
    int NT = NP >> 4;           // 13 (kv) or 7 (q)

    wmma::fragment<wmma::accumulator, 16, 16, 16, float> acc[2][4];
#pragma unroll
    for (int i = 0; i < 2; i++)
#pragma unroll
        for (int t = 0; t < 4; t++) wmma::fill_fragment(acc[i][t], 0.f);

    for (int k0 = 0; k0 < KP; k0 += 16) {
        wmma::fragment<wmma::matrix_a, 16, 16, 16, __nv_bfloat16, wmma::row_major> ah0, ah1, al0, al1;
        wmma::load_matrix_sync(ah0, Ah + (wm +  0) * LDA + k0, LDA);
        wmma::load_matrix_sync(al0, Al + (wm +  0) * LDA + k0, LDA);
        wmma::load_matrix_sync(ah1, Ah + (wm + 16) * LDA + k0, LDA);
        wmma::load_matrix_sync(al1, Al + (wm + 16) * LDA + k0, LDA);

        wmma::fragment<wmma::matrix_b, 16, 16, 16, __nv_bfloat16, wmma::row_major> bh[2], bl[2];
        if (wt < NT) {
            wmma::load_matrix_sync(bh[0], Wh + (long)k0 * NP + wt * 16, NP);
            wmma::load_matrix_sync(bl[0], Wl + (long)k0 * NP + wt * 16, NP);
        }
#pragma unroll
        for (int t = 0; t < 4; t++) {
            int cur = t & 1;
            int ntn = wt + 4 * (t + 1);
            if (t < 3 && ntn < NT) {
                wmma::load_matrix_sync(bh[cur ^ 1], Wh + (long)k0 * NP + ntn * 16, NP);
                wmma::load_matrix_sync(bl[cur ^ 1], Wl + (long)k0 * NP + ntn * 16, NP);
            }
            int ntc = wt + 4 * t;
            if (ntc < NT) {
                wmma::mma_sync(acc[0][t], al0, bh[cur], acc[0][t]);
                wmma::mma_sync(acc[0][t], ah0, bl[cur], acc[0][t]);
                wmma::mma_sync(acc[0][t], ah0, bh[cur], acc[0][t]);
                wmma::mma_sync(acc[1][t], al1, bh[cur], acc[1][t]);
                wmma::mma_sync(acc[1][t], ah1, bl[cur], acc[1][t]);
                wmma::mma_sync(acc[1][t], ah1, bh[cur], acc[1][t]);
            }
        }
    }
#pragma unroll
    for (int t = 0; t < 4; t++) {
        int ntc = wt + 4 * t;
        if (ntc < NT) {
            wmma::store_matrix_sync(C + (long)(m0 + wm +  0) * NP + ntc * 16, acc[0][t], NP, wmma::mem_row_major);
            wmma::store_matrix_sync(C + (long)(m0 + wm + 16) * NP + ntc * 16, acc[1][t], NP, wmma::mem_row_major);
        }
    }
}

// ---------------- attention: one warp per dst, online softmax, 2-edge pipeline ----------------
__device__ __forceinline__ void load_edge(int4 p, int lane, bool act,
                                          float4& k1, float4& k2, float4& k3,
                                          float4& v1, float4& v2, float4& v3) {
    if (act) {
        const float4* kn = (const float4*)(g_KVN + (long)p.x * NP_KV);
        const float4* ke = (const float4*)(g_KVE + (long)p.y * NP_KV);
        const float4* kt = (const float4*)(g_KVT + (long)p.z * NP_KV);
        k1 = kn[lane];      k2 = ke[lane];      k3 = kt[lane];
        v1 = kn[25 + lane]; v2 = ke[25 + lane]; v3 = kt[25 + lane];
    }
}

__global__ __launch_bounds__(256)
void attn_kernel() {
    int w = (int)((blockIdx.x * (long)blockDim.x + threadIdx.x) >> 5);
    int lane = threadIdx.x & 31;
    if (w >= NDST) return;
    int beg = g_off[w], end = g_off[w + 1];

    bool act = lane < 25;
    int base = lane * 4;
    bool h0 = base + 0 < 50, h1 = base + 1 < 50, h2 = base + 2 < 50, h3 = base + 3 < 50;

    float4 q = make_float4(0.f, 0.f, 0.f, 0.f);
    if (act) q = ((const float4*)(g_Q + (long)w * NP_Q))[lane];

    float4 acc = make_float4(0.f, 0.f, 0.f, 0.f);
    float m0 = -1e30f, m1 = -1e30f, s0 = 0.f, s1 = 0.f;
    float4 z4 = make_float4(0.f, 0.f, 0.f, 0.f);

    int j = beg;
    for (; j + 1 < end; j += 2) {
        int4 pA = g_pack[j];
        int4 pB = g_pack[j + 1];
        float4 ka1 = z4, ka2 = z4, ka3 = z4, va1 = z4, va2 = z4, va3 = z4;
        float4 kb1 = z4, kb2 = z4, kb3 = z4, vb1 = z4, vb2 = z4, vb3 = z4;
        load_edge(pA, lane, act, ka1, ka2, ka3, va1, va2, va3);
        load_edge(pB, lane, act, kb1, kb2, kb3, vb1, vb2, vb3);

        float t0a = 0.f, t1a = 0.f, t0b = 0.f, t1b = 0.f;
        float4 vA = z4, vB = z4;
        if (act) {
            float ax = q.x * (ka1.x + ka2.x + ka3.x);
            float ay = q.y * (ka1.y + ka2.y + ka3.y);
            float az = q.z * (ka1.z + ka2.z + ka3.z);
            float aw = q.w * (ka1.w + ka2.w + ka3.w);
            t0a = (h0 ? ax : 0.f) + (h1 ? ay : 0.f) + (h2 ? az : 0.f) + (h3 ? aw : 0.f);
            t1a = (h0 ? 0.f : ax) + (h1 ? 0.f : ay) + (h2 ? 0.f : az) + (h3 ? 0.f : aw);
            float bx = q.x * (kb1.x + kb2.x + kb3.x);
            float by = q.y * (kb1.y + kb2.y + kb3.y);
            float bz = q.z * (kb1.z + kb2.z + kb3.z);
            float bw = q.w * (kb1.w + kb2.w + kb3.w);
            t0b = (h0 ? bx : 0.f) + (h1 ? by : 0.f) + (h2 ? bz : 0.f) + (h3 ? bw : 0.f);
            t1b = (h0 ? 0.f : bx) + (h1 ? 0.f : by) + (h2 ? 0.f : bz) + (h3 ? 0.f : bw);
            vA.x = va1.x + va2.x + va3.x; vA.y = va1.y + va2.y + va3.y;
            vA.z = va1.z + va2.z + va3.z; vA.w = va1.w + va2.w + va3.w;
            vB.x = vb1.x + vb2.x + vb3.x; vB.y = vb1.y + vb2.y + vb3.y;
            vB.z = vb1.z + vb2.z + vb3.z; vB.w = vb1.w + vb2.w + vb3.w;
        }
#pragma unroll
        for (int off = 16; off; off >>= 1) {
            t0a += __shfl_xor_sync(0xffffffffu, t0a, off);
            t1a += __shfl_xor_sync(0xffffffffu, t1a, off);
            t0b += __shfl_xor_sync(0xffffffffu, t0b, off);
            t1b += __shfl_xor_sync(0xffffffffu, t1b, off);
        }
        {
            float a0 = t0a > 0.f ? t0a : NEG_SLOPE * t0a;
            float a1 = t1a > 0.f ? t1a : NEG_SLOPE * t1a;
            float nm0 = fmaxf(m0, a0);
            float c0 = __expf(m0 - nm0), w0 = __expf(a0 - nm0);
            s0 = s0 * c0 + w0; m0 = nm0;
            float nm1 = fmaxf(m1, a1);
            float c1 = __expf(m1 - nm1), w1 = __expf(a1 - nm1);
            s1 = s1 * c1 + w1; m1 = nm1;
            acc.x = acc.x * (h0 ? c0 : c1) + (h0 ? w0 : w1) * vA.x;
            acc.y = acc.y * (h1 ? c0 : c1) + (h1 ? w0 : w1) * vA.y;
            acc.z = acc.z * (h2 ? c0 : c1) + (h2 ? w0 : w1) * vA.z;
            acc.w = acc.w * (h3 ? c0 : c1) + (h3 ? w0 : w1) * vA.w;
        }
        {
            float a0 = t0b > 0.f ? t0b : NEG_SLOPE * t0b;
            float a1 = t1b > 0.f ? t1b : NEG_SLOPE * t1b;
            float nm0 = fmaxf(m0, a0);
            float c0 = __expf(m0 - nm0), w0 = __expf(a0 - nm0);
            s0 = s0 * c0 + w0; m0 = nm0;
            float nm1 = fmaxf(m1, a1);
            float c1 = __expf(m1 - nm1), w1 = __expf(a1 - nm1);
            s1 = s1 * c1 + w1; m1 = nm1;
            acc.x = acc.x * (h0 ? c0 : c1) + (h0 ? w0 : w1) * vB.x;
            acc.y = acc.y * (h1 ? c0 : c1) + (h1 ? w0 : w1) * vB.y;
            acc.z = acc.z * (h2 ? c0 : c1) + (h2 ? w0 : w1) * vB.z;
            acc.w = acc.w * (h3 ? c0 : c1) + (h3 ? w0 : w1) * vB.w;
        }
    }
    if (j < end) {
        int4 p = g_pack[j];
        float4 k1 = z4, k2 = z4, k3 = z4, v1 = z4, v2 = z4, v3 = z4;
        load_edge(p, lane, act, k1, k2, k3, v1, v2, v3);
        float t0 = 0.f, t1 = 0.f;
        float4 vS = z4;
        if (act) {
            float px = q.x * (k1.x + k2.x + k3.x);
            float py = q.y * (k1.y + k2.y + k3.y);
            float pz = q.z * (k1.z + k2.z + k3.z);
            float pw = q.w * (k1.w + k2.w + k3.w);
            t0 = (h0 ? px : 0.f) + (h1 ? py : 0.f) + (h2 ? pz : 0.f) + (h3 ? pw : 0.f);
            t1 = (h0 ? 0.f : px) + (h1 ? 0.f : py) + (h2 ? 0.f : pz) + (h3 ? 0.f : pw);
            vS.x = v1.x + v2.x + v3.x; vS.y = v1.y + v2.y + v3.y;
            vS.z = v1.z + v2.z + v3.z; vS.w = v1.w + v2.w + v3.w;
        }
#pragma unroll
        for (int off = 16; off; off >>= 1) {
            t0 += __shfl_xor_sync(0xffffffffu, t0, off);
            t1 += __shfl_xor_sync(0xffffffffu, t1, off);
        }
        float a0 = t0 > 0.f ? t0 : NEG_SLOPE * t0;
        float a1 = t1 > 0.f ? t1 : NEG_SLOPE * t1;
        float nm0 = fmaxf(m0, a0);
        float c0 = __expf(m0 - nm0), w0 = __expf(a0 - nm0);
        s0 = s0 * c0 + w0; m0 = nm0;
        float nm1 = fmaxf(m1, a1);
        float c1 = __expf(m1 - nm1), w1 = __expf(a1 - nm1);
        s1 = s1 * c1 + w1; m1 = nm1;
        acc.x = acc.x * (h0 ? c0 : c1) + (h0 ? w0 : w1) * vS.x;
        acc.y = acc.y * (h1 ? c0 : c1) + (h1 ? w0 : w1) * vS.y;
        acc.z = acc.z * (h2 ? c0 : c1) + (h2 ? w0 : w1) * vS.z;
        acc.w = acc.w * (h3 ? c0 : c1) + (h3 ? w0 : w1) * vS.w;
    }

    if (act) {
        float r0 = s0 > 0.f ? 1.f / s0 : 0.f;
        float r1 = s1 > 0.f ? 1.f / s1 : 0.f;
        float4 o;
        o.x = acc.x * (h0 ? r0 : r1);
        o.y = acc.y * (h1 ? r0 : r1);
        o.z = acc.z * (h2 ? r0 : r1);
        o.w = acc.w * (h3 ? r0 : r1);
        ((float4*)(g_acc + (long)w * DO_))[lane] = o;
    }
}

// ---------------- finalize: bf16x2 concat-GEMM + relu + LayerNorm ----------------
#define FIN_LDA (KP_OUT + 8)   // 296
#define FIN_SMEM (64 * FIN_LDA * 2 * 2)   // Ah+Al bf16 = 75776 B
#define FIN_LDC 116
__global__ __launch_bounds__(256)
void finalize_bf(const float* __restrict__ nodeData,
                 const int* __restrict__ rev_nids,
                 const __nv_bfloat16* __restrict__ Wh, const __nv_bfloat16* __restrict__ Wl,
                 const float* __restrict__ ln_g, const float* __restrict__ ln_b,
                 float* __restrict__ out) {
    extern __shared__ char smraw[];
    __nv_bfloat16* Ah = (__nv_bfloat16*)smraw;
    __nv_bfloat16* Al = Ah + 64 * FIN_LDA;
    float* Cs = (float*)smraw;           // reused after mainloop (64 x FIN_LDC)
    int tid = threadIdx.x, wid = tid >> 5, lane = tid & 31;
    int m0 = blockIdx.x * 64;

    for (int idx = tid; idx < 64 * 72; idx += 256) {
        int r = idx / 72, c4 = idx - r * 72;
        int row = m0 + r;
        float4 v = make_float4(0.f, 0.f, 0.f, 0.f);
        if (row < NDST) {
            if (c4 < 25) {
                v = *(const float4*)(g_acc + (long)row * DO_ + c4 * 4);
            } else if (c4 < 68) {
                long nb = (long)rev_nids[row] * DN_;
                v = *(const float4*)(nodeData + nb + (c4 * 4 - 100));
            } else if (c4 == 68) {
                v.x = 1.0f;
            }
        }
        int off = r * FIN_LDA + c4 * 4;
        __nv_bfloat16 h; float x;
        x = v.x; h = __float2bfloat16(x); Ah[off + 0] = h; Al[off + 0] = __float2bfloat16(x - __bfloat162float(h));
        x = v.y; h = __float2bfloat16(x); Ah[off + 1] = h; Al[off + 1] = __float2bfloat16(x - __bfloat162float(h));
        x = v.z; h = __float2bfloat16(x); Ah[off + 2] = h; Al[off + 2] = __float2bfloat16(x - __bfloat162float(h));
        x = v.w; h = __float2bfloat16(x); Ah[off + 3] = h; Al[off + 3] = __float2bfloat16(x - __bfloat162float(h));
    }
    __syncthreads();

    int wm = (wid >> 2) * 32;
    int wn = (wid & 3) * 16;

    wmma::fragment<wmma::accumulator, 16, 16, 16, float> acc[2][2];
    bool act1 = (64 + wn + 16) <= NP_Q;
#pragma unroll
    for (int a = 0; a < 2; a++)
#pragma unroll
        for (int i = 0; i < 2; i++) wmma::fill_fragment(acc[a][i], 0.f);

    for (int k0 = 0; k0 < KP_OUT; k0 += 16) {
        wmma::fragment<wmma::matrix_a, 16, 16, 16, __nv_bfloat16, wmma::row_major> ah0, ah1, al0, al1;
        wmma::load_matrix_sync(ah0, Ah + (wm +  0) * FIN_LDA + k0, FIN_LDA);
        wmma::load_matrix_sync(ah1, Ah + (wm + 16) * FIN_LDA + k0, FIN_LDA);
        wmma::load_matrix_sync(al0, Al + (wm +  0) * FIN_LDA + k0, FIN_LDA);
        wmma::load_matrix_sync(al1, Al + (wm + 16) * FIN_LDA + k0, FIN_LDA);
        {
            wmma::fragment<wmma::matrix_b, 16, 16, 16, __nv_bfloat16, wmma::row_major> bh, bl;
            wmma::load_matrix_sync(bh, Wh + (long)k0 * NP_Q + wn, NP_Q);
            wmma::load_matrix_sync(bl, Wl + (long)k0 * NP_Q + wn, NP_Q);
            wmma::mma_sync(acc[0][0], al0, bh, acc[0][0]);
            wmma::mma_sync(acc[0][0], ah0, bl, acc[0][0]);
            wmma::mma_sync(acc[0][0], ah0, bh, acc[0][0]);
            wmma::mma_sync(acc[0][1], al1, bh, acc[0][1]);
            wmma::mma_sync(acc[0][1], ah1, bl, acc[0][1]);
            wmma::mma_sync(acc[0][1], ah1, bh, acc[0][1]);
        }
        if (act1) {
            wmma::fragment<wmma::matrix_b, 16, 16, 16, __nv_bfloat16, wmma::row_major> bh, bl;
            wmma::load_matrix_sync(bh, Wh + (long)k0 * NP_Q + 64 + wn, NP_Q);
            wmma::load_matrix_sync(bl, Wl + (long)k0 * NP_Q + 64 + wn, NP_Q);
            wmma::mma_sync(acc[1][0], al0, bh, acc[1][0]);
            wmma::mma_sync(acc[1][0], ah0, bl, acc[1][0]);
            wmma::mma_sync(acc[1][0], ah0, bh, acc[1][0]);
            wmma::mma_sync(acc[1][1], al1, bh, acc[1][1]);
            wmma::mma_sync(acc[1][1], ah1, bl, acc[1][1]);
            wmma::mma_sync(acc[1][1], ah1, bh, acc[1][1]);
        }
    }
    __syncthreads();

#pragma unroll
    for (int i = 0; i < 2; i++) {
        wmma::store_matrix_sync(Cs + (wm + i * 16) * FIN_LDC + wn, acc[0][i], FIN_LDC, wmma::mem_row_major);
        if (act1)
            wmma::store_matrix_sync(Cs + (wm + i * 16) * FIN_LDC + 64 + wn, acc[1][i], FIN_LDC, wmma::mem_row_major);
    }
    __syncthreads();

    float g0 = ln_g[lane], g1 = ln_g[lane + 32], g2 = ln_g[lane + 64];
    float g3 = lane < 4 ? ln_g[96 + lane] : 0.f;
    float be0 = ln_b[lane], be1 = ln_b[lane + 32], be2 = ln_b[lane + 64];
    float be3 = lane < 4 ? ln_b[96 + lane] : 0.f;

    for (int r = wid * 8; r < wid * 8 + 8; r++) {
        int row = m0 + r;
        if (row >= NDST) continue;
        float* cr = Cs + r * FIN_LDC;
        float x0 = cr[lane];        x0 = x0 > 0.f ? x0 : 0.f;
        float x1 = cr[lane + 32];   x1 = x1 > 0.f ? x1 : 0.f;
        float x2 = cr[lane + 64];   x2 = x2 > 0.f ? x2 : 0.f;
        float x3 = lane < 4 ? cr[96 + lane] : 0.f;  x3 = x3 > 0.f ? x3 : 0.f;
        float s = x0 + x1 + x2 + x3;
        float sq = x0 * x0 + x1 * x1 + x2 * x2 + x3 * x3;
#pragma unroll
        for (int off = 16; off; off >>= 1) {
            s  += __shfl_xor_sync(0xffffffffu, s, off);
            sq += __shfl_xor_sync(0xffffffffu, sq, off);
        }
        float mu = s * 0.01f;
        float var = sq * 0.01f - mu * mu;
        float inv = rsqrtf(var + 1e-5f);
        float* orow = out + (long)row * DO_;
        orow[lane]      = (x0 - mu) * inv * g0 + be0;
        orow[lane + 32] = (x1 - mu) * inv * g1 + be1;
        orow[lane + 64] = (x2 - mu) * inv * g2 + be2;
        if (lane < 4) orow[96 + lane] = (x3 - mu) * inv * g3 + be3;
    }
}

// ---------------- launch ----------------
extern "C" void kernel_launch(void* const* d_in, const int* in_sizes, int n_in,
                              void* d_out, int out_size) {
    const float* nodeData = (const float*)d_in[0];
    const float* efeat    = (const float*)d_in[1];
    const float* utd      = (const float*)d_in[2];
    const int*   rev_nids = (const int*)d_in[3];
    const int*   rev_eids = (const int*)d_in[4];
    const int*   rev_tids = (const int*)d_in[5];
    const int*   dstindex = (const int*)d_in[6];
    const float* time_w   = (const float*)d_in[8];
    const float* time_b   = (const float*)d_in[9];
    const float* Wqn      = (const float*)d_in[10];
    const float* bqn      = (const float*)d_in[11];
    const float* Wqt      = (const float*)d_in[12];
    const float* bqt      = (const float*)d_in[13];
    const float* Wkvn     = (const float*)d_in[14];
    const float* bkvn     = (const float*)d_in[15];
    const float* Wkve     = (const float*)d_in[16];
    const float* bkve     = (const float*)d_in[17];
    const float* Wkvt     = (const float*)d_in[18];
    const float* bkvt     = (const float*)d_in[19];
    const float* Wout     = (const float*)d_in[20];
    const float* bout     = (const float*)d_in[21];
    const float* ln_g     = (const float*)d_in[22];
    const float* ln_b     = (const float*)d_in[23];
    float* out = (float*)d_out;

    float *pQ, *pKVN, *pKVE, *pKVT, *pbiasq;
    __nv_bfloat16* pWS;
    cudaGetSymbolAddress((void**)&pQ,     g_Q);
    cudaGetSymbolAddress((void**)&pKVN,   g_KVN);
    cudaGetSymbolAddress((void**)&pKVE,   g_KVE);
    cudaGetSymbolAddress((void**)&pKVT,   g_KVT);
    cudaGetSymbolAddress((void**)&pbiasq, g_biasq);
    cudaGetSymbolAddress((void**)&pWS,    g_WS);

    const int* node_inv = rev_nids + NDST;

    const int sm_nd = 64 * (KP_ND + 8) * 2 * 2;   // 47104
    const int sm_t  = 64 * (KP_T  + 8) * 2 * 2;   // 30720
    cudaFuncSetAttribute((const void*)gemm_bf3<true,  false>, cudaFuncAttributeMaxDynamicSharedMemorySize, sm_nd);
    cudaFuncSetAttribute((const void*)gemm_bf3<false, false>, cudaFuncAttributeMaxDynamicSharedMemorySize, sm_nd);
    cudaFuncSetAttribute((const void*)gemm_bf3<false, true >, cudaFuncAttributeMaxDynamicSharedMemorySize, sm_nd);
    cudaFuncSetAttribute((const void*)finalize_bf, cudaFuncAttributeMaxDynamicSharedMemorySize, FIN_SMEM);

    init_kernel<<<512, 256>>>();
    hist_kernel<<<2048, 256>>>(dstindex);
    split_w<<<(KP_ND * NP_KV + 255) / 256, 256>>>(Wkvn, bkvn, bkve, bkvt,
        pWS + OFF_KVN_H, pWS + OFF_KVN_L, DN_, 2 * DO_, KP_ND, NP_KV);

    // 4th launch -> profiled
    gemm_bf3<false, false><<<UN / 64, 256, sm_nd>>>(
        nodeData, pWS + OFF_KVN_H, pWS + OFF_KVN_L, pKVN, nullptr,
        nullptr, nullptr, nullptr, UN, DN_, KP_ND, NP_KV);

    scan_kernel<<<1, 1024>>>();
    scatter_kernel<<<2048, 256>>>(dstindex, node_inv, rev_eids, rev_tids);
    biasq_kernel<<<1, 128>>>(time_b, Wqt, bqt, bqn);

    split_w<<<(KP_ND * NP_Q + 255) / 256, 256>>>(Wqn, pbiasq, nullptr, nullptr,
        pWS + OFF_QN_H, pWS + OFF_QN_L, DN_, DO_, KP_ND, NP_Q);
    split_w<<<(KP_ND * NP_KV + 255) / 256, 256>>>(Wkve, nullptr, nullptr, nullptr,
        pWS + OFF_KVE_H, pWS + OFF_KVE_L, DN_, 2 * DO_, KP_ND, NP_KV);
    split_w<<<(KP_T * NP_KV + 255) / 256, 256>>>(Wkvt, nullptr, nullptr, nullptr,
        pWS + OFF_KVT_H, pWS + OFF_KVT_L, DT_, 2 * DO_, KP_T, NP_KV);
    split_w<<<(KP_OUT * NP_Q + 255) / 256, 256>>>(Wout, bout, nullptr, nullptr,
        pWS + OFF_OUT_H, pWS + OFF_OUT_L, DN_ + DO_, DO_, KP_OUT, NP_Q);

    gemm_bf3<true, false><<<(NDST + 63) / 64, 256, sm_nd>>>(
        nodeData, pWS + OFF_QN_H, pWS + OFF_QN_L, pQ, rev_nids,
        nullptr, nullptr, nullptr, NDST, DN_, KP_ND, NP_Q);
    gemm_bf3<false, false><<<(UE + 63) / 64, 256, sm_nd>>>(
        efeat, pWS + OFF_KVE_H, pWS + OFF_KVE_L, pKVE, nullptr,
        nullptr, nullptr, nullptr, UE, DN_, KP_ND, NP_KV);
    gemm_bf3<false, true><<<(UT + 63) / 64, 256, sm_t>>>(
        nullptr, pWS + OFF_KVT_H, pWS + OFF_KVT_L, pKVT, nullptr,
        utd, time_w, time_b, UT, DT_, KP_T, NP_KV);

    attn_kernel<<<(NDST + 7) / 8, 256>>>();

    finalize_bf<<<(NDST + 63) / 64, 256, FIN_SMEM>>>(
        nodeData, rev_nids, pWS + OFF_OUT_H, pWS + OFF_OUT_L, ln_g, ln_b, out);
}

// round 11
// speedup vs baseline: 1.0448x; 1.0448x over previous
#include <cuda_runtime.h>
#include <cuda_bf16.h>
#include <mma.h>
using namespace nvcuda;

#define NDST 100000
#define NDST_P 100032
#define NE   1000000
#define UN   200000
#define UE   100000
#define UE_P 100032
#define UT   100000
#define UT_P 100032
#define DN_  172
#define DT_  100
#define DO_  100
#define NEG_SLOPE 0.2f

#define NP_KV 208
#define NP_Q  112
#define KP_ND 176
#define KP_T  112
#define KP_OUT 288

// split-weight arena offsets (bf16 elements)
#define OFF_KVN_H 0
#define OFF_KVN_L (OFF_KVN_H + KP_ND * NP_KV)
#define OFF_KVE_H (OFF_KVN_L + KP_ND * NP_KV)
#define OFF_KVE_L (OFF_KVE_H + KP_ND * NP_KV)
#define OFF_KVT_H (OFF_KVE_L + KP_ND * NP_KV)
#define OFF_KVT_L (OFF_KVT_H + KP_T * NP_KV)
#define OFF_QN_H  (OFF_KVT_L + KP_T * NP_KV)
#define OFF_QN_L  (OFF_QN_H + KP_ND * NP_Q)
#define OFF_OUT_H (OFF_QN_L + KP_ND * NP_Q)
#define OFF_OUT_L (OFF_OUT_H + KP_OUT * NP_Q)
#define WSPLIT_TOTAL (OFF_OUT_L + KP_OUT * NP_Q)

// ---------------- scratch (device globals; no allocation) ----------------
__device__ float         g_Q   [NDST_P * NP_Q];
__device__ float         g_KVN [UN * NP_KV];
__device__ float         g_KVE [UE_P * NP_KV];
__device__ float         g_KVT [UT_P * NP_KV];
__device__ float         g_acc [NDST * DO_];
__device__ float         g_biasq[DO_];
__device__ __nv_bfloat16 g_WS  [WSPLIT_TOTAL];
__device__ int           g_cnt [NDST];
__device__ int           g_off [NDST + 1];
__device__ int           g_cur [NDST];
__device__ int4          g_pack[NE];

// ---------------- init ----------------
__global__ void init_kernel() {
    int idx = blockIdx.x * blockDim.x + threadIdx.x;
    int stride = gridDim.x * blockDim.x;
    for (int i = idx; i < NDST; i += stride) g_cnt[i] = 0;
}

__global__ void biasq_kernel(const float* __restrict__ time_b,
                             const float* __restrict__ Wqt,
                             const float* __restrict__ bqt,
                             const float* __restrict__ bqn) {
    int j = threadIdx.x;
    if (j >= DO_) return;
    float acc = bqt[j] + bqn[j];
    for (int k = 0; k < DT_; k++) acc += cosf(time_b[k]) * Wqt[k * DO_ + j];
    g_biasq[j] = acc;
}

// ---------------- weight split: rows 0..K-1 = W, row K = bias sum, rest 0 ----------------
__global__ void split_w(const float* __restrict__ W,
                        const float* __restrict__ b0, const float* __restrict__ b1,
                        const float* __restrict__ b2,
                        __nv_bfloat16* __restrict__ oh, __nv_bfloat16* __restrict__ ol,
                        int K, int N, int KP, int NP) {
    int idx = blockIdx.x * blockDim.x + threadIdx.x;
    if (idx >= KP * NP) return;
    int k = idx / NP, n = idx - k * NP;
    float val = 0.f;
    if (n < N) {
        if (k < K) val = W[(long)k * N + n];
        else if (k == K) {
            if (b0) val += b0[n];
            if (b1) val += b1[n];
            if (b2) val += b2[n];
        }
    }
    __nv_bfloat16 h = __float2bfloat16(val);
    oh[idx] = h;
    ol[idx] = __float2bfloat16(val - __bfloat162float(h));
}

// ---------------- CSR build ----------------
__global__ void hist_kernel(const int* __restrict__ dsti) {
    int idx = blockIdx.x * blockDim.x + threadIdx.x;
    int stride = gridDim.x * blockDim.x;
    for (int e = idx; e < NE; e += stride) atomicAdd(&g_cnt[dsti[e]], 1);
}

#define SCH ((NDST + 1023) / 1024)
__global__ __launch_bounds__(1024)
void scan_kernel() {
    __shared__ int ss[1024];
    int t = threadIdx.x;
    int base = t * SCH;
    int end = base + SCH < NDST ? base + SCH : NDST;
    int sum = 0;
    for (int i = base; i < end; i++) sum += g_cnt[i];
    ss[t] = sum;
    __syncthreads();
    for (int off = 1; off < 1024; off <<= 1) {
        int v = (t >= off) ? ss[t - off] : 0;
        __syncthreads();
        ss[t] += v;
        __syncthreads();
    }
    int run = (t == 0) ? 0 : ss[t - 1];
    for (int i = base; i < end; i++) {
        g_off[i] = run;
        g_cur[i] = run;
        run += g_cnt[i];
    }
    if (t == 1023) g_off[NDST] = NE;
}

__global__ void scatter_kernel(const int* __restrict__ dsti,
                               const int* __restrict__ node_inv,
                               const int* __restrict__ eids,
                               const int* __restrict__ tids) {
    int idx = blockIdx.x * blockDim.x + threadIdx.x;
    int stride = gridDim.x * blockDim.x;
    for (int e = idx; e < NE; e += stride) {
        int pos = atomicAdd(&g_cur[dsti[e]], 1);
        g_pack[pos] = make_int4(node_inv[e], eids[e], tids[e], 0);
    }
}

// ---------------- bf16x2 GEMM v5: n-pass outer (2 passes), 2 N-tiles/warp, sync-free ----------------
// 256 threads (8 warps = 2M x 4Ngroups x 2 tiles), BM=64. A hi/lo staged once across full K.
// TIMEF: A[row,k] = cos(utd[row]*tw[k]+tb[k]) computed inline (kvt path).
template <bool GATHER, bool TIMEF>
__global__ __launch_bounds__(256, 3)
void gemm_bf5(const float* __restrict__ A,
              const __nv_bfloat16* __restrict__ Wh, const __nv_bfloat16* __restrict__ Wl,
              float* __restrict__ C, const int* __restrict__ gidx,
              const float* __restrict__ utd, const float* __restrict__ tw,
              const float* __restrict__ tb,
              int M, int K, int KP, int NP) {
    extern __shared__ char smraw[];
    const int LDA = KP + 8;
    __nv_bfloat16* Ah = (__nv_bfloat16*)smraw;
    __nv_bfloat16* Al = Ah + 64 * LDA;
    int tid = threadIdx.x, wid = tid >> 5;
    int m0 = blockIdx.x * 64;

    // stage A hi/lo, zero-padded; col K = 1.0 (bias row selector)
    int nc4 = KP >> 2;
    for (int idx = tid; idx < 64 * nc4; idx += 256) {
        int r = idx / nc4, c4 = idx - r * nc4;
        int row = m0 + r;
        float4 v = make_float4(0.f, 0.f, 0.f, 0.f);
        if (row < M) {
            int k = c4 * 4;
            if (TIMEF) {
                if (k + 3 < K) {
                    float4 w4 = *(const float4*)(tw + k);
                    float4 b4 = *(const float4*)(tb + k);
                    float td = utd[row];
                    v.x = cosf(td * w4.x + b4.x);
                    v.y = cosf(td * w4.y + b4.y);
                    v.z = cosf(td * w4.z + b4.z);
                    v.w = cosf(td * w4.w + b4.w);
                } else if (K >= k && K < k + 4) {
                    ((float*)&v)[K - k] = 1.0f;
                }
            } else {
                long ab = (long)(GATHER ? gidx[row] : row) * K;
                if (k + 3 < K) {
                    v = *(const float4*)(A + ab + k);
                } else {
                    if (k + 0 < K) v.x = A[ab + k + 0];
                    if (k + 1 < K) v.y = A[ab + k + 1];
                    if (k + 2 < K) v.z = A[ab + k + 2];
                    if (k + 3 < K) v.w = A[ab + k + 3];
                }
                if (K >= k && K < k + 4) ((float*)&v)[K - k] = 1.0f;
            }
        }
        int off = r * LDA + c4 * 4;
        __nv_bfloat16 h; float x;
        x = v.x; h = __float2bfloat16(x); Ah[off + 0] = h; Al[off + 0] = __float2bfloat16(x - __bfloat162float(h));
        x = v.y; h = __float2bfloat16(x); Ah[off + 1] = h; Al[off + 1] = __float2bfloat16(x - __bfloat162float(h));
        x = v.z; h = __float2bfloat16(x); Ah[off + 2] = h; Al[off + 2] = __float2bfloat16(x - __bfloat162float(h));
        x = v.w; h = __float2bfloat16(x); Ah[off + 3] = h; Al[off + 3] = __float2bfloat16(x - __bfloat162float(h));
    }
    __syncthreads();

    int wm = (wid >> 2) * 32;   // 0 or 32
    int wt = wid & 3;           // N-group 0..3
    int NT = NP >> 4;           // 13 (kv) or 7 (q)

    for (int pass = 0; pass < 2; pass++) {
        int ta = pass * 8 + wt * 2;     // this warp's first tile this pass
        if (ta >= NT) break;
        bool actB = (ta + 1) < NT;

        wmma::fragment<wmma::accumulator, 16, 16, 16, float> acc00, acc10, acc01, acc11;
        wmma::fill_fragment(acc00, 0.f);
        wmma::fill_fragment(acc10, 0.f);
        wmma::fill_fragment(acc01, 0.f);
        wmma::fill_fragment(acc11, 0.f);

        for (int k0 = 0; k0 < KP; k0 += 16) {
            wmma::fragment<wmma::matrix_a, 16, 16, 16, __nv_bfloat16, wmma::row_major> ah0, ah1, al0, al1;
            wmma::load_matrix_sync(ah0, Ah + (wm +  0) * LDA + k0, LDA);
            wmma::load_matrix_sync(al0, Al + (wm +  0) * LDA + k0, LDA);
            wmma::load_matrix_sync(ah1, Ah + (wm + 16) * LDA + k0, LDA);
            wmma::load_matrix_sync(al1, Al + (wm + 16) * LDA + k0, LDA);

            wmma::fragment<wmma::matrix_b, 16, 16, 16, __nv_bfloat16, wmma::row_major> bh0, bl0, bh1, bl1;
            wmma::load_matrix_sync(bh0, Wh + (long)k0 * NP + ta * 16, NP);
            wmma::load_matrix_sync(bl0, Wl + (long)k0 * NP + ta * 16, NP);
            if (actB) {
                wmma::load_matrix_sync(bh1, Wh + (long)k0 * NP + (ta + 1) * 16, NP);
                wmma::load_matrix_sync(bl1, Wl + (long)k0 * NP + (ta + 1) * 16, NP);
            }

            wmma::mma_sync(acc00, al0, bh0, acc00);
            wmma::mma_sync(acc00, ah0, bl0, acc00);
            wmma::mma_sync(acc00, ah0, bh0, acc00);
            wmma::mma_sync(acc10, al1, bh0, acc10);
            wmma::mma_sync(acc10, ah1, bl0, acc10);
            wmma::mma_sync(acc10, ah1, bh0, acc10);
            if (actB) {
                wmma::mma_sync(acc01, al0, bh1, acc01);
                wmma::mma_sync(acc01, ah0, bl1, acc01);
                wmma::mma_sync(acc01, ah0, bh1, acc01);
                wmma::mma_sync(acc11, al1, bh1, acc11);
                wmma::mma_sync(acc11, ah1, bl1, acc11);
                wmma::mma_sync(acc11, ah1, bh1, acc11);
            }
        }
        wmma::store_matrix_sync(C + (long)(m0 + wm +  0) * NP + ta * 16, acc00, NP, wmma::mem_row_major);
        wmma::store_matrix_sync(C + (long)(m0 + wm + 16) * NP + ta * 16, acc10, NP, wmma::mem_row_major);
        if (actB) {
            wmma::store_matrix_sync(C + (long)(m0 + wm +  0) * NP + (ta + 1) * 16, acc01, NP, wmma::mem_row_major);
            wmma::store_matrix_sync(C + (long)(m0 + wm + 16) * NP + (ta + 1) * 16, acc11, NP, wmma::mem_row_major);
        }
    }
}

// ---------------- attention: one warp per dst, online softmax, 2-edge pipeline ----------------
__device__ __forceinline__ void load_edge(int4 p, int lane, bool act,
                                          float4& k1, float4& k2, float4& k3,
                                          float4& v1, float4& v2, float4& v3) {
    if (act) {
        const float4* kn = (const float4*)(g_KVN + (long)p.x * NP_KV);
        const float4* ke = (const float4*)(g_KVE + (long)p.y * NP_KV);
        const float4* kt = (const float4*)(g_KVT + (long)p.z * NP_KV);
        k1 = kn[lane];      k2 = ke[lane];      k3 = kt[lane];
        v1 = kn[25 + lane]; v2 = ke[25 + lane]; v3 = kt[25 + lane];
    }
}

__global__ __launch_bounds__(256)
void attn_kernel() {
    int w = (int)((blockIdx.x * (long)blockDim.x + threadIdx.x) >> 5);
    int lane = threadIdx.x & 31;
    if (w >= NDST) return;
    int beg = g_off[w], end = g_off[w + 1];

    bool act = lane < 25;
    int base = lane * 4;
    bool h0 = base + 0 < 50, h1 = base + 1 < 50, h2 = base + 2 < 50, h3 = base + 3 < 50;

    float4 q = make_float4(0.f, 0.f, 0.f, 0.f);
    if (act) q = ((const float4*)(g_Q + (long)w * NP_Q))[lane];

    float4 acc = make_float4(0.f, 0.f, 0.f, 0.f);
    float m0 = -1e30f, m1 = -1e30f, s0 = 0.f, s1 = 0.f;
    float4 z4 = make_float4(0.f, 0.f, 0.f, 0.f);

    int j = beg;
    for (; j + 1 < end; j += 2) {
        int4 pA = g_pack[j];
        int4 pB = g_pack[j + 1];
        float4 ka1 = z4, ka2 = z4, ka3 = z4, va1 = z4, va2 = z4, va3 = z4;
        float4 kb1 = z4, kb2 = z4, kb3 = z4, vb1 = z4, vb2 = z4, vb3 = z4;
        load_edge(pA, lane, act, ka1, ka2, ka3, va1, va2, va3);
        load_edge(pB, lane, act, kb1, kb2, kb3, vb1, vb2, vb3);

        float t0a = 0.f, t1a = 0.f, t0b = 0.f, t1b = 0.f;
        float4 vA = z4, vB = z4;
        if (act) {
            float ax = q.x * (ka1.x + ka2.x + ka3.x);
            float ay = q.y * (ka1.y + ka2.y + ka3.y);
            float az = q.z * (ka1.z + ka2.z + ka3.z);
            float aw = q.w * (ka1.w + ka2.w + ka3.w);
            t0a = (h0 ? ax : 0.f) + (h1 ? ay : 0.f) + (h2 ? az : 0.f) + (h3 ? aw : 0.f);
            t1a = (h0 ? 0.f : ax) + (h1 ? 0.f : ay) + (h2 ? 0.f : az) + (h3 ? 0.f : aw);
            float bx = q.x * (kb1.x + kb2.x + kb3.x);
            float by = q.y * (kb1.y + kb2.y + kb3.y);
            float bz = q.z * (kb1.z + kb2.z + kb3.z);
            float bw = q.w * (kb1.w + kb2.w + kb3.w);
            t0b = (h0 ? bx : 0.f) + (h1 ? by : 0.f) + (h2 ? bz : 0.f) + (h3 ? bw : 0.f);
            t1b = (h0 ? 0.f : bx) + (h1 ? 0.f : by) + (h2 ? 0.f : bz) + (h3 ? 0.f : bw);
            vA.x = va1.x + va2.x + va3.x; vA.y = va1.y + va2.y + va3.y;
            vA.z = va1.z + va2.z + va3.z; vA.w = va1.w + va2.w + va3.w;
            vB.x = vb1.x + vb2.x + vb3.x; vB.y = vb1.y + vb2.y + vb3.y;
            vB.z = vb1.z + vb2.z + vb3.z; vB.w = vb1.w + vb2.w + vb3.w;
        }
#pragma unroll
        for (int off = 16; off; off >>= 1) {
            t0a += __shfl_xor_sync(0xffffffffu, t0a, off);
            t1a += __shfl_xor_sync(0xffffffffu, t1a, off);
            t0b += __shfl_xor_sync(0xffffffffu, t0b, off);
            t1b += __shfl_xor_sync(0xffffffffu, t1b, off);
        }
        {
            float a0 = t0a > 0.f ? t0a : NEG_SLOPE * t0a;
            float a1 = t1a > 0.f ? t1a : NEG_SLOPE * t1a;
            float nm0 = fmaxf(m0, a0);
            float c0 = __expf(m0 - nm0), w0 = __expf(a0 - nm0);
            s0 = s0 * c0 + w0; m0 = nm0;
            float nm1 = fmaxf(m1, a1);
            float c1 = __expf(m1 - nm1), w1 = __expf(a1 - nm1);
            s1 = s1 * c1 + w1; m1 = nm1;
            acc.x = acc.x * (h0 ? c0 : c1) + (h0 ? w0 : w1) * vA.x;
            acc.y = acc.y * (h1 ? c0 : c1) + (h1 ? w0 : w1) * vA.y;
            acc.z = acc.z * (h2 ? c0 : c1) + (h2 ? w0 : w1) * vA.z;
            acc.w = acc.w * (h3 ? c0 : c1) + (h3 ? w0 : w1) * vA.w;
        }
        {
            float a0 = t0b > 0.f ? t0b : NEG_SLOPE * t0b;
            float a1 = t1b > 0.f ? t1b : NEG_SLOPE * t1b;
            float nm0 = fmaxf(m0, a0);
            float c0 = __expf(m0 - nm0), w0 = __expf(a0 - nm0);
            s0 = s0 * c0 + w0; m0 = nm0;
            float nm1 = fmaxf(m1, a1);
            float c1 = __expf(m1 - nm1), w1 = __expf(a1 - nm1);
            s1 = s1 * c1 + w1; m1 = nm1;
            acc.x = acc.x * (h0 ? c0 : c1) + (h0 ? w0 : w1) * vB.x;
            acc.y = acc.y * (h1 ? c0 : c1) + (h1 ? w0 : w1) * vB.y;
            acc.z = acc.z * (h2 ? c0 : c1) + (h2 ? w0 : w1) * vB.z;
            acc.w = acc.w * (h3 ? c0 : c1) + (h3 ? w0 : w1) * vB.w;
        }
    }
    if (j < end) {
        int4 p = g_pack[j];
        float4 k1 = z4, k2 = z4, k3 = z4, v1 = z4, v2 = z4, v3 = z4;
        load_edge(p, lane, act, k1, k2, k3, v1, v2, v3);
        float t0 = 0.f, t1 = 0.f;
        float4 vS = z4;
        if (act) {
            float px = q.x * (k1.x + k2.x + k3.x);
            float py = q.y * (k1.y + k2.y + k3.y);
            float pz = q.z * (k1.z + k2.z + k3.z);
            float pw = q.w * (k1.w + k2.w + k3.w);
            t0 = (h0 ? px : 0.f) + (h1 ? py : 0.f) + (h2 ? pz : 0.f) + (h3 ? pw : 0.f);
            t1 = (h0 ? 0.f : px) + (h1 ? 0.f : py) + (h2 ? 0.f : pz) + (h3 ? 0.f : pw);
            vS.x = v1.x + v2.x + v3.x; vS.y = v1.y + v2.y + v3.y;
            vS.z = v1.z + v2.z + v3.z; vS.w = v1.w + v2.w + v3.w;
        }
#pragma unroll
        for (int off = 16; off; off >>= 1) {
            t0 += __shfl_xor_sync(0xffffffffu, t0, off);
            t1 += __shfl_xor_sync(0xffffffffu, t1, off);
        }
        float a0 = t0 > 0.f ? t0 : NEG_SLOPE * t0;
        float a1 = t1 > 0.f ? t1 : NEG_SLOPE * t1;
        float nm0 = fmaxf(m0, a0);
        float c0 = __expf(m0 - nm0), w0 = __expf(a0 - nm0);
        s0 = s0 * c0 + w0; m0 = nm0;
        float nm1 = fmaxf(m1, a1);
        float c1 = __expf(m1 - nm1), w1 = __expf(a1 - nm1);
        s1 = s1 * c1 + w1; m1 = nm1;
        acc.x = acc.x * (h0 ? c0 : c1) + (h0 ? w0 : w1) * vS.x;
        acc.y = acc.y * (h1 ? c0 : c1) + (h1 ? w0 : w1) * vS.y;
        acc.z = acc.z * (h2 ? c0 : c1) + (h2 ? w0 : w1) * vS.z;
        acc.w = acc.w * (h3 ? c0 : c1) + (h3 ? w0 : w1) * vS.w;
    }

    if (act) {
        float r0 = s0 > 0.f ? 1.f / s0 : 0.f;
        float r1 = s1 > 0.f ? 1.f / s1 : 0.f;
        float4 o;
        o.x = acc.x * (h0 ? r0 : r1);
        o.y = acc.y * (h1 ? r0 : r1);
        o.z = acc.z * (h2 ? r0 : r1);
        o.w = acc.w * (h3 ? r0 : r1);
        ((float4*)(g_acc + (long)w * DO_))[lane] = o;
    }
}

// ---------------- finalize: bf16x2 concat-GEMM + relu + LayerNorm ----------------
#define FIN_LDA (KP_OUT + 8)   // 296
#define FIN_SMEM (64 * FIN_LDA * 2 * 2)   // Ah+Al bf16 = 75776 B
#define FIN_LDC 116
__global__ __launch_bounds__(256)
void finalize_bf(const float* __restrict__ nodeData,
                 const int* __restrict__ rev_nids,
                 const __nv_bfloat16* __restrict__ Wh, const __nv_bfloat16* __restrict__ Wl,
                 const float* __restrict__ ln_g, const float* __restrict__ ln_b,
                 float* __restrict__ out) {
    extern __shared__ char smraw[];
    __nv_bfloat16* Ah = (__nv_bfloat16*)smraw;
    __nv_bfloat16* Al = Ah + 64 * FIN_LDA;
    float* Cs = (float*)smraw;           // reused after mainloop (64 x FIN_LDC)
    int tid = threadIdx.x, wid = tid >> 5, lane = tid & 31;
    int m0 = blockIdx.x * 64;

    for (int idx = tid; idx < 64 * 72; idx += 256) {
        int r = idx / 72, c4 = idx - r * 72;
        int row = m0 + r;
        float4 v = make_float4(0.f, 0.f, 0.f, 0.f);
        if (row < NDST) {
            if (c4 < 25) {
                v = *(const float4*)(g_acc + (long)row * DO_ + c4 * 4);
            } else if (c4 < 68) {
                long nb = (long)rev_nids[row] * DN_;
                v = *(const float4*)(nodeData + nb + (c4 * 4 - 100));
            } else if (c4 == 68) {
                v.x = 1.0f;
            }
        }
        int off = r * FIN_LDA + c4 * 4;
        __nv_bfloat16 h; float x;
        x = v.x; h = __float2bfloat16(x); Ah[off + 0] = h; Al[off + 0] = __float2bfloat16(x - __bfloat162float(h));
        x = v.y; h = __float2bfloat16(x); Ah[off + 1] = h; Al[off + 1] = __float2bfloat16(x - __bfloat162float(h));
        x = v.z; h = __float2bfloat16(x); Ah[off + 2] = h; Al[off + 2] = __float2bfloat16(x - __bfloat162float(h));
        x = v.w; h = __float2bfloat16(x); Ah[off + 3] = h; Al[off + 3] = __float2bfloat16(x - __bfloat162float(h));
    }
    __syncthreads();

    int wm = (wid >> 2) * 32;
    int wn = (wid & 3) * 16;

    wmma::fragment<wmma::accumulator, 16, 16, 16, float> acc[2][2];
    bool act1 = (64 + wn + 16) <= NP_Q;
#pragma unroll
    for (int a = 0; a < 2; a++)
#pragma unroll
        for (int i = 0; i < 2; i++) wmma::fill_fragment(acc[a][i], 0.f);

    for (int k0 = 0; k0 < KP_OUT; k0 += 16) {
        wmma::fragment<wmma::matrix_a, 16, 16, 16, __nv_bfloat16, wmma::row_major> ah0, ah1, al0, al1;
        wmma::load_matrix_sync(ah0, Ah + (wm +  0) * FIN_LDA + k0, FIN_LDA);
        wmma::load_matrix_sync(ah1, Ah + (wm + 16) * FIN_LDA + k0, FIN_LDA);
        wmma::load_matrix_sync(al0, Al + (wm +  0) * FIN_LDA + k0, FIN_LDA);
        wmma::load_matrix_sync(al1, Al + (wm + 16) * FIN_LDA + k0, FIN_LDA);
        {
            wmma::fragment<wmma::matrix_b, 16, 16, 16, __nv_bfloat16, wmma::row_major> bh, bl;
            wmma::load_matrix_sync(bh, Wh + (long)k0 * NP_Q + wn, NP_Q);
            wmma::load_matrix_sync(bl, Wl + (long)k0 * NP_Q + wn, NP_Q);
            wmma::mma_sync(acc[0][0], al0, bh, acc[0][0]);
            wmma::mma_sync(acc[0][0], ah0, bl, acc[0][0]);
            wmma::mma_sync(acc[0][0], ah0, bh, acc[0][0]);
            wmma::mma_sync(acc[0][1], al1, bh, acc[0][1]);
            wmma::mma_sync(acc[0][1], ah1, bl, acc[0][1]);
            wmma::mma_sync(acc[0][1], ah1, bh, acc[0][1]);
        }
        if (act1) {
            wmma::fragment<wmma::matrix_b, 16, 16, 16, __nv_bfloat16, wmma::row_major> bh, bl;
            wmma::load_matrix_sync(bh, Wh + (long)k0 * NP_Q + 64 + wn, NP_Q);
            wmma::load_matrix_sync(bl, Wl + (long)k0 * NP_Q + 64 + wn, NP_Q);
            wmma::mma_sync(acc[1][0], al0, bh, acc[1][0]);
            wmma::mma_sync(acc[1][0], ah0, bl, acc[1][0]);
            wmma::mma_sync(acc[1][0], ah0, bh, acc[1][0]);
            wmma::mma_sync(acc[1][1], al1, bh, acc[1][1]);
            wmma::mma_sync(acc[1][1], ah1, bl, acc[1][1]);
            wmma::mma_sync(acc[1][1], ah1, bh, acc[1][1]);
        }
    }
    __syncthreads();

#pragma unroll
    for (int i = 0; i < 2; i++) {
        wmma::store_matrix_sync(Cs + (wm + i * 16) * FIN_LDC + wn, acc[0][i], FIN_LDC, wmma::mem_row_major);
        if (act1)
            wmma::store_matrix_sync(Cs + (wm + i * 16) * FIN_LDC + 64 + wn, acc[1][i], FIN_LDC, wmma::mem_row_major);
    }
    __syncthreads();

    float g0 = ln_g[lane], g1 = ln_g[lane + 32], g2 = ln_g[lane + 64];
    float g3 = lane < 4 ? ln_g[96 + lane] : 0.f;
    float be0 = ln_b[lane], be1 = ln_b[lane + 32], be2 = ln_b[lane + 64];
    float be3 = lane < 4 ? ln_b[96 + lane] : 0.f;

    for (int r = wid * 8; r < wid * 8 + 8; r++) {
        int row = m0 + r;
        if (row >= NDST) continue;
        float* cr = Cs + r * FIN_LDC;
        float x0 = cr[lane];        x0 = x0 > 0.f ? x0 : 0.f;
        float x1 = cr[lane + 32];   x1 = x1 > 0.f ? x1 : 0.f;
        float x2 = cr[lane + 64];   x2 = x2 > 0.f ? x2 : 0.f;
        float x3 = lane < 4 ? cr[96 + lane] : 0.f;  x3 = x3 > 0.f ? x3 : 0.f;
        float s = x0 + x1 + x2 + x3;
        float sq = x0 * x0 + x1 * x1 + x2 * x2 + x3 * x3;
#pragma unroll
        for (int off = 16; off; off >>= 1) {
            s  += __shfl_xor_sync(0xffffffffu, s, off);
            sq += __shfl_xor_sync(0xffffffffu, sq, off);
        }
        float mu = s * 0.01f;
        float var = sq * 0.01f - mu * mu;
        float inv = rsqrtf(var + 1e-5f);
        float* orow = out + (long)row * DO_;
        orow[lane]      = (x0 - mu) * inv * g0 + be0;
        orow[lane + 32] = (x1 - mu) * inv * g1 + be1;
        orow[lane + 64] = (x2 - mu) * inv * g2 + be2;
        if (lane < 4) orow[96 + lane] = (x3 - mu) * inv * g3 + be3;
    }
}

// ---------------- launch ----------------
extern "C" void kernel_launch(void* const* d_in, const int* in_sizes, int n_in,
                              void* d_out, int out_size) {
    const float* nodeData = (const float*)d_in[0];
    const float* efeat    = (const float*)d_in[1];
    const float* utd      = (const float*)d_in[2];
    const int*   rev_nids = (const int*)d_in[3];
    const int*   rev_eids = (const int*)d_in[4];
    const int*   rev_tids = (const int*)d_in[5];
    const int*   dstindex = (const int*)d_in[6];
    const float* time_w   = (const float*)d_in[8];
    const float* time_b   = (const float*)d_in[9];
    const float* Wqn      = (const float*)d_in[10];
    const float* bqn      = (const float*)d_in[11];
    const float* Wqt      = (const float*)d_in[12];
    const float* bqt      = (const float*)d_in[13];
    const float* Wkvn     = (const float*)d_in[14];
    const float* bkvn     = (const float*)d_in[15];
    const float* Wkve     = (const float*)d_in[16];
    const float* bkve     = (const float*)d_in[17];
    const float* Wkvt     = (const float*)d_in[18];
    const float* bkvt     = (const float*)d_in[19];
    const float* Wout     = (const float*)d_in[20];
    const float* bout     = (const float*)d_in[21];
    const float* ln_g     = (const float*)d_in[22];
    const float* ln_b     = (const float*)d_in[23];
    float* out = (float*)d_out;

    float *pQ, *pKVN, *pKVE, *pKVT, *pbiasq;
    __nv_bfloat16* pWS;
    cudaGetSymbolAddress((void**)&pQ,     g_Q);
    cudaGetSymbolAddress((void**)&pKVN,   g_KVN);
    cudaGetSymbolAddress((void**)&pKVE,   g_KVE);
    cudaGetSymbolAddress((void**)&pKVT,   g_KVT);
    cudaGetSymbolAddress((void**)&pbiasq, g_biasq);
    cudaGetSymbolAddress((void**)&pWS,    g_WS);

    const int* node_inv = rev_nids + NDST;

    const int sm_nd = 64 * (KP_ND + 8) * 2 * 2;   // 47104
    const int sm_t  = 64 * (KP_T  + 8) * 2 * 2;   // 30720
    cudaFuncSetAttribute((const void*)gemm_bf5<true,  false>, cudaFuncAttributeMaxDynamicSharedMemorySize, sm_nd);
    cudaFuncSetAttribute((const void*)gemm_bf5<false, false>, cudaFuncAttributeMaxDynamicSharedMemorySize, sm_nd);
    cudaFuncSetAttribute((const void*)gemm_bf5<false, true >, cudaFuncAttributeMaxDynamicSharedMemorySize, sm_nd);
    cudaFuncSetAttribute((const void*)finalize_bf, cudaFuncAttributeMaxDynamicSharedMemorySize, FIN_SMEM);

    init_kernel<<<512, 256>>>();
    hist_kernel<<<2048, 256>>>(dstindex);
    split_w<<<(KP_ND * NP_KV + 255) / 256, 256>>>(Wkvn, bkvn, bkve, bkvt,
        pWS + OFF_KVN_H, pWS + OFF_KVN_L, DN_, 2 * DO_, KP_ND, NP_KV);

    // 4th launch -> profiled
    gemm_bf5<false, false><<<UN / 64, 256, sm_nd>>>(
        nodeData, pWS + OFF_KVN_H, pWS + OFF_KVN_L, pKVN, nullptr,
        nullptr, nullptr, nullptr, UN, DN_, KP_ND, NP_KV);

    scan_kernel<<<1, 1024>>>();
    scatter_kernel<<<2048, 256>>>(dstindex, node_inv, rev_eids, rev_tids);
    biasq_kernel<<<1, 128>>>(time_b, Wqt, bqt, bqn);

    split_w<<<(KP_ND * NP_Q + 255) / 256, 256>>>(Wqn, pbiasq, nullptr, nullptr,
        pWS + OFF_QN_H, pWS + OFF_QN_L, DN_, DO_, KP_ND, NP_Q);
    split_w<<<(KP_ND * NP_KV + 255) / 256, 256>>>(Wkve, nullptr, nullptr, nullptr,
        pWS + OFF_KVE_H, pWS + OFF_KVE_L, DN_, 2 * DO_, KP_ND, NP_KV);
    split_w<<<(KP_T * NP_KV + 255) / 256, 256>>>(Wkvt, nullptr, nullptr, nullptr,
        pWS + OFF_KVT_H, pWS + OFF_KVT_L, DT_, 2 * DO_, KP_T, NP_KV);
    split_w<<<(KP_OUT * NP_Q + 255) / 256, 256>>>(Wout, bout, nullptr, nullptr,
        pWS + OFF_OUT_H, pWS + OFF_OUT_L, DN_ + DO_, DO_, KP_OUT, NP_Q);

    gemm_bf5<true, false><<<(NDST + 63) / 64, 256, sm_nd>>>(
        nodeData, pWS + OFF_QN_H, pWS + OFF_QN_L, pQ, rev_nids,
        nullptr, nullptr, nullptr, NDST, DN_, KP_ND, NP_Q);
    gemm_bf5<false, false><<<(UE + 63) / 64, 256, sm_nd>>>(
        efeat, pWS + OFF_KVE_H, pWS + OFF_KVE_L, pKVE, nullptr,
        nullptr, nullptr, nullptr, UE, DN_, KP_ND, NP_KV);
    gemm_bf5<false, true><<<(UT + 63) / 64, 256, sm_t>>>(
        nullptr, pWS + OFF_KVT_H, pWS + OFF_KVT_L, pKVT, nullptr,
        utd, time_w, time_b, UT, DT_, KP_T, NP_KV);

    attn_kernel<<<(NDST + 7) / 8, 256>>>();

    finalize_bf<<<(NDST + 63) / 64, 256, FIN_SMEM>>>(
        nodeData, rev_nids, pWS + OFF_OUT_H, pWS + OFF_OUT_L, ln_g, ln_b, out);
}

// round 12
// speedup vs baseline: 1.1011x; 1.0538x over previous
#include <cuda_runtime.h>
#include <cuda_bf16.h>
#include <mma.h>
using namespace nvcuda;

#define NDST 100000
#define NE   1000000
#define UN   200000
#define UE   100000
#define UT   100000
#define DN_  172
#define DT_  100
#define DO_  100
#define NEG_SLOPE 0.2f

// padded row counts (multiples of 128)
#define UN_P  200064
#define M1_P  100096

#define NP_KV 208
#define NP_Q  112
#define KP_ND 176
#define KP_T  112
#define KP_OUT 288

// split-weight arena offsets (bf16 elements)
#define OFF_KVN_H 0
#define OFF_KVN_L (OFF_KVN_H + KP_ND * NP_KV)
#define OFF_KVE_H (OFF_KVN_L + KP_ND * NP_KV)
#define OFF_KVE_L (OFF_KVE_H + KP_ND * NP_KV)
#define OFF_KVT_H (OFF_KVE_L + KP_ND * NP_KV)
#define OFF_KVT_L (OFF_KVT_H + KP_T * NP_KV)
#define OFF_QN_H  (OFF_KVT_L + KP_T * NP_KV)
#define OFF_QN_L  (OFF_QN_H + KP_ND * NP_Q)
#define OFF_OUT_H (OFF_QN_L + KP_ND * NP_Q)
#define OFF_OUT_L (OFF_OUT_H + KP_OUT * NP_Q)
#define WSPLIT_TOTAL (OFF_OUT_L + KP_OUT * NP_Q)

// ---------------- scratch (device globals; no allocation) ----------------
__device__ float         g_Q   [M1_P * NP_Q];
__device__ float         g_KVN [UN_P * NP_KV];
__device__ float         g_KVE [M1_P * NP_KV];
__device__ float         g_KVT [M1_P * NP_KV];
__device__ float         g_acc [NDST * DO_];
__device__ float         g_biasq[DO_];
__device__ __nv_bfloat16 g_WS  [WSPLIT_TOTAL];
__device__ int           g_cnt [NDST];
__device__ int           g_off [NDST + 1];
__device__ int           g_cur [NDST];
__device__ int           g_bsum[128];
__device__ int           g_btop[128];
__device__ int4          g_pack[NE];

// ---------------- init ----------------
__global__ void init_kernel() {
    int idx = blockIdx.x * blockDim.x + threadIdx.x;
    int stride = gridDim.x * blockDim.x;
    for (int i = idx; i < NDST; i += stride) g_cnt[i] = 0;
}

__global__ void biasq_kernel(const float* __restrict__ time_b,
                             const float* __restrict__ Wqt,
                             const float* __restrict__ bqt,
                             const float* __restrict__ bqn) {
    int j = threadIdx.x;
    if (j >= DO_) return;
    float acc = bqt[j] + bqn[j];
    for (int k = 0; k < DT_; k++) acc += cosf(time_b[k]) * Wqt[k * DO_ + j];
    g_biasq[j] = acc;
}

// ---------------- weight split: rows 0..K-1 = W, row K = bias sum, rest 0 ----------------
__global__ void split_w(const float* __restrict__ W,
                        const float* __restrict__ b0, const float* __restrict__ b1,
                        const float* __restrict__ b2,
                        __nv_bfloat16* __restrict__ oh, __nv_bfloat16* __restrict__ ol,
                        int K, int N, int KP, int NP) {
    int idx = blockIdx.x * blockDim.x + threadIdx.x;
    if (idx >= KP * NP) return;
    int k = idx / NP, n = idx - k * NP;
    float val = 0.f;
    if (n < N) {
        if (k < K) val = W[(long)k * N + n];
        else if (k == K) {
            if (b0) val += b0[n];
            if (b1) val += b1[n];
            if (b2) val += b2[n];
        }
    }
    __nv_bfloat16 h = __float2bfloat16(val);
    oh[idx] = h;
    ol[idx] = __float2bfloat16(val - __bfloat162float(h));
}

// ---------------- CSR build ----------------
__global__ void hist_kernel(const int* __restrict__ dsti) {
    int idx = blockIdx.x * blockDim.x + threadIdx.x;
    int stride = gridDim.x * blockDim.x;
    for (int e = idx; e < NE; e += stride) atomicAdd(&g_cnt[dsti[e]], 1);
}

#define NB_SCAN ((NDST + 1023) / 1024)   // 98

// phase 1: block-local exclusive scan (coalesced), block sums out
__global__ __launch_bounds__(1024)
void scan1_kernel() {
    __shared__ int ss[1024];
    int t = threadIdx.x;
    int i = blockIdx.x * 1024 + t;
    int v = (i < NDST) ? g_cnt[i] : 0;
    ss[t] = v;
    __syncthreads();
    for (int off = 1; off < 1024; off <<= 1) {
        int u = (t >= off) ? ss[t - off] : 0;
        __syncthreads();
        ss[t] += u;
        __syncthreads();
    }
    if (i < NDST) g_off[i] = ss[t] - v;   // block-local exclusive
    if (t == 1023) g_bsum[blockIdx.x] = ss[1023];
}

// phase 2: scan the block sums (tiny)
__global__ __launch_bounds__(128)
void scan2_kernel() {
    __shared__ int ss[128];
    int t = threadIdx.x;
    int v = (t < NB_SCAN) ? g_bsum[t] : 0;
    ss[t] = v;
    __syncthreads();
    for (int off = 1; off < 128; off <<= 1) {
        int u = (t >= off) ? ss[t - off] : 0;
        __syncthreads();
        ss[t] += u;
        __syncthreads();
    }
    g_btop[t] = ss[t] - v;   // exclusive
}

// phase 3: add block offsets, fill g_cur, terminator
__global__ __launch_bounds__(1024)
void scan3_kernel() {
    int t = threadIdx.x;
    int i = blockIdx.x * 1024 + t;
    if (i < NDST) {
        int o = g_off[i] + g_btop[blockIdx.x];
        g_off[i] = o;
        g_cur[i] = o;
    }
    if (i == 0) g_off[NDST] = NE;
}

__global__ void scatter_kernel(const int* __restrict__ dsti,
                               const int* __restrict__ node_inv,
                               const int* __restrict__ eids,
                               const int* __restrict__ tids) {
    int idx = blockIdx.x * blockDim.x + threadIdx.x;
    int stride = gridDim.x * blockDim.x;
    for (int e = idx; e < NE; e += stride) {
        int pos = atomicAdd(&g_cur[dsti[e]], 1);
        g_pack[pos] = make_int4(node_inv[e], eids[e], tids[e], 0);
    }
}

// ---------------- bf16x2 GEMM v6: BM=128, 4Mx2N warp grid, 2 N-tiles/warp, sync-free ----------------
// 256 threads (8 warps = 4 M-groups x 2 N-groups), BM=128. A hi/lo staged once across full K.
// TIMEF: A[row,k] = cos(utd[row]*tw[k]+tb[k]) computed inline (kvt path).
template <bool GATHER, bool TIMEF>
__global__ __launch_bounds__(256, 2)
void gemm_bf6(const float* __restrict__ A,
              const __nv_bfloat16* __restrict__ Wh, const __nv_bfloat16* __restrict__ Wl,
              float* __restrict__ C, const int* __restrict__ gidx,
              const float* __restrict__ utd, const float* __restrict__ tw,
              const float* __restrict__ tb,
              int M, int K, int KP, int NP) {
    extern __shared__ char smraw[];
    const int LDA = KP + 8;
    __nv_bfloat16* Ah = (__nv_bfloat16*)smraw;
    __nv_bfloat16* Al = Ah + 128 * LDA;
    int tid = threadIdx.x, wid = tid >> 5;
    int m0 = blockIdx.x * 128;

    // stage A hi/lo, zero-padded; col K = 1.0 (bias row selector)
    int nc4 = KP >> 2;
    for (int idx = tid; idx < 128 * nc4; idx += 256) {
        int r = idx / nc4, c4 = idx - r * nc4;
        int row = m0 + r;
        float4 v = make_float4(0.f, 0.f, 0.f, 0.f);
        if (row < M) {
            int k = c4 * 4;
            if (TIMEF) {
                if (k + 3 < K) {
                    float4 w4 = *(const float4*)(tw + k);
                    float4 b4 = *(const float4*)(tb + k);
                    float td = utd[row];
                    v.x = cosf(td * w4.x + b4.x);
                    v.y = cosf(td * w4.y + b4.y);
                    v.z = cosf(td * w4.z + b4.z);
                    v.w = cosf(td * w4.w + b4.w);
                } else if (K >= k && K < k + 4) {
                    ((float*)&v)[K - k] = 1.0f;
                }
            } else {
                long ab = (long)(GATHER ? gidx[row] : row) * K;
                if (k + 3 < K) {
                    v = *(const float4*)(A + ab + k);
                } else {
                    if (k + 0 < K) v.x = A[ab + k + 0];
                    if (k + 1 < K) v.y = A[ab + k + 1];
                    if (k + 2 < K) v.z = A[ab + k + 2];
                    if (k + 3 < K) v.w = A[ab + k + 3];
                }
                if (K >= k && K < k + 4) ((float*)&v)[K - k] = 1.0f;
            }
        }
        int off = r * LDA + c4 * 4;
        __nv_bfloat16 h; float x;
        x = v.x; h = __float2bfloat16(x); Ah[off + 0] = h; Al[off + 0] = __float2bfloat16(x - __bfloat162float(h));
        x = v.y; h = __float2bfloat16(x); Ah[off + 1] = h; Al[off + 1] = __float2bfloat16(x - __bfloat162float(h));
        x = v.z; h = __float2bfloat16(x); Ah[off + 2] = h; Al[off + 2] = __float2bfloat16(x - __bfloat162float(h));
        x = v.w; h = __float2bfloat16(x); Ah[off + 3] = h; Al[off + 3] = __float2bfloat16(x - __bfloat162float(h));
    }
    __syncthreads();

    int wm = (wid >> 1) * 32;   // 0,32,64,96
    int wt = wid & 1;           // N-group 0..1
    int NT = NP >> 4;           // 13 (kv) or 7 (q)

    for (int pass = 0; pass < 4; pass++) {
        int ta = pass * 4 + wt * 2;     // this warp's first tile this pass
        if (ta >= NT) break;
        bool actB = (ta + 1) < NT;

        wmma::fragment<wmma::accumulator, 16, 16, 16, float> acc00, acc10, acc01, acc11;
        wmma::fill_fragment(acc00, 0.f);
        wmma::fill_fragment(acc10, 0.f);
        wmma::fill_fragment(acc01, 0.f);
        wmma::fill_fragment(acc11, 0.f);

        for (int k0 = 0; k0 < KP; k0 += 16) {
            wmma::fragment<wmma::matrix_a, 16, 16, 16, __nv_bfloat16, wmma::row_major> ah0, ah1, al0, al1;
            wmma::load_matrix_sync(ah0, Ah + (wm +  0) * LDA + k0, LDA);
            wmma::load_matrix_sync(al0, Al + (wm +  0) * LDA + k0, LDA);
            wmma::load_matrix_sync(ah1, Ah + (wm + 16) * LDA + k0, LDA);
            wmma::load_matrix_sync(al1, Al + (wm + 16) * LDA + k0, LDA);

            wmma::fragment<wmma::matrix_b, 16, 16, 16, __nv_bfloat16, wmma::row_major> bh0, bl0, bh1, bl1;
            wmma::load_matrix_sync(bh0, Wh + (long)k0 * NP + ta * 16, NP);
            wmma::load_matrix_sync(bl0, Wl + (long)k0 * NP + ta * 16, NP);
            if (actB) {
                wmma::load_matrix_sync(bh1, Wh + (long)k0 * NP + (ta + 1) * 16, NP);
                wmma::load_matrix_sync(bl1, Wl + (long)k0 * NP + (ta + 1) * 16, NP);
            }

            wmma::mma_sync(acc00, al0, bh0, acc00);
            wmma::mma_sync(acc00, ah0, bl0, acc00);
            wmma::mma_sync(acc00, ah0, bh0, acc00);
            wmma::mma_sync(acc10, al1, bh0, acc10);
            wmma::mma_sync(acc10, ah1, bl0, acc10);
            wmma::mma_sync(acc10, ah1, bh0, acc10);
            if (actB) {
                wmma::mma_sync(acc01, al0, bh1, acc01);
                wmma::mma_sync(acc01, ah0, bl1, acc01);
                wmma::mma_sync(acc01, ah0, bh1, acc01);
                wmma::mma_sync(acc11, al1, bh1, acc11);
                wmma::mma_sync(acc11, ah1, bl1, acc11);
                wmma::mma_sync(acc11, ah1, bh1, acc11);
            }
        }
        wmma::store_matrix_sync(C + (long)(m0 + wm +  0) * NP + ta * 16, acc00, NP, wmma::mem_row_major);
        wmma::store_matrix_sync(C + (long)(m0 + wm + 16) * NP + ta * 16, acc10, NP, wmma::mem_row_major);
        if (actB) {
            wmma::store_matrix_sync(C + (long)(m0 + wm +  0) * NP + (ta + 1) * 16, acc01, NP, wmma::mem_row_major);
            wmma::store_matrix_sync(C + (long)(m0 + wm + 16) * NP + (ta + 1) * 16, acc11, NP, wmma::mem_row_major);
        }
    }
}

// ---------------- attention: one warp per dst, online softmax, 2-edge pipeline ----------------
__device__ __forceinline__ void load_edge(int4 p, int lane, bool act,
                                          float4& k1, float4& k2, float4& k3,
                                          float4& v1, float4& v2, float4& v3) {
    if (act) {
        const float4* kn = (const float4*)(g_KVN + (long)p.x * NP_KV);
        const float4* ke = (const float4*)(g_KVE + (long)p.y * NP_KV);
        const float4* kt = (const float4*)(g_KVT + (long)p.z * NP_KV);
        k1 = kn[lane];      k2 = ke[lane];      k3 = kt[lane];
        v1 = kn[25 + lane]; v2 = ke[25 + lane]; v3 = kt[25 + lane];
    }
}

__global__ __launch_bounds__(256)
void attn_kernel() {
    int w = (int)((blockIdx.x * (long)blockDim.x + threadIdx.x) >> 5);
    int lane = threadIdx.x & 31;
    if (w >= NDST) return;
    int beg = g_off[w], end = g_off[w + 1];

    bool act = lane < 25;
    int base = lane * 4;
    bool h0 = base + 0 < 50, h1 = base + 1 < 50, h2 = base + 2 < 50, h3 = base + 3 < 50;

    float4 q = make_float4(0.f, 0.f, 0.f, 0.f);
    if (act) q = ((const float4*)(g_Q + (long)w * NP_Q))[lane];

    float4 acc = make_float4(0.f, 0.f, 0.f, 0.f);
    float m0 = -1e30f, m1 = -1e30f, s0 = 0.f, s1 = 0.f;
    float4 z4 = make_float4(0.f, 0.f, 0.f, 0.f);

    int j = beg;
    for (; j + 1 < end; j += 2) {
        int4 pA = g_pack[j];
        int4 pB = g_pack[j + 1];
        float4 ka1 = z4, ka2 = z4, ka3 = z4, va1 = z4, va2 = z4, va3 = z4;
        float4 kb1 = z4, kb2 = z4, kb3 = z4, vb1 = z4, vb2 = z4, vb3 = z4;
        load_edge(pA, lane, act, ka1, ka2, ka3, va1, va2, va3);
        load_edge(pB, lane, act, kb1, kb2, kb3, vb1, vb2, vb3);

        float t0a = 0.f, t1a = 0.f, t0b = 0.f, t1b = 0.f;
        float4 vA = z4, vB = z4;
        if (act) {
            float ax = q.x * (ka1.x + ka2.x + ka3.x);
            float ay = q.y * (ka1.y + ka2.y + ka3.y);
            float az = q.z * (ka1.z + ka2.z + ka3.z);
            float aw = q.w * (ka1.w + ka2.w + ka3.w);
            t0a = (h0 ? ax : 0.f) + (h1 ? ay : 0.f) + (h2 ? az : 0.f) + (h3 ? aw : 0.f);
            t1a = (h0 ? 0.f : ax) + (h1 ? 0.f : ay) + (h2 ? 0.f : az) + (h3 ? 0.f : aw);
            float bx = q.x * (kb1.x + kb2.x + kb3.x);
            float by = q.y * (kb1.y + kb2.y + kb3.y);
            float bz = q.z * (kb1.z + kb2.z + kb3.z);
            float bw = q.w * (kb1.w + kb2.w + kb3.w);
            t0b = (h0 ? bx : 0.f) + (h1 ? by : 0.f) + (h2 ? bz : 0.f) + (h3 ? bw : 0.f);
            t1b = (h0 ? 0.f : bx) + (h1 ? 0.f : by) + (h2 ? 0.f : bz) + (h3 ? 0.f : bw);
            vA.x = va1.x + va2.x + va3.x; vA.y = va1.y + va2.y + va3.y;
            vA.z = va1.z + va2.z + va3.z; vA.w = va1.w + va2.w + va3.w;
            vB.x = vb1.x + vb2.x + vb3.x; vB.y = vb1.y + vb2.y + vb3.y;
            vB.z = vb1.z + vb2.z + vb3.z; vB.w = vb1.w + vb2.w + vb3.w;
        }
#pragma unroll
        for (int off = 16; off; off >>= 1) {
            t0a += __shfl_xor_sync(0xffffffffu, t0a, off);
            t1a += __shfl_xor_sync(0xffffffffu, t1a, off);
            t0b += __shfl_xor_sync(0xffffffffu, t0b, off);
            t1b += __shfl_xor_sync(0xffffffffu, t1b, off);
        }
        {
            float a0 = t0a > 0.f ? t0a : NEG_SLOPE * t0a;
            float a1 = t1a > 0.f ? t1a : NEG_SLOPE * t1a;
            float nm0 = fmaxf(m0, a0);
            float c0 = __expf(m0 - nm0), w0 = __expf(a0 - nm0);
            s0 = s0 * c0 + w0; m0 = nm0;
            float nm1 = fmaxf(m1, a1);
            float c1 = __expf(m1 - nm1), w1 = __expf(a1 - nm1);
            s1 = s1 * c1 + w1; m1 = nm1;
            acc.x = acc.x * (h0 ? c0 : c1) + (h0 ? w0 : w1) * vA.x;
            acc.y = acc.y * (h1 ? c0 : c1) + (h1 ? w0 : w1) * vA.y;
            acc.z = acc.z * (h2 ? c0 : c1) + (h2 ? w0 : w1) * vA.z;
            acc.w = acc.w * (h3 ? c0 : c1) + (h3 ? w0 : w1) * vA.w;
        }
        {
            float a0 = t0b > 0.f ? t0b : NEG_SLOPE * t0b;
            float a1 = t1b > 0.f ? t1b : NEG_SLOPE * t1b;
            float nm0 = fmaxf(m0, a0);
            float c0 = __expf(m0 - nm0), w0 = __expf(a0 - nm0);
            s0 = s0 * c0 + w0; m0 = nm0;
            float nm1 = fmaxf(m1, a1);
            float c1 = __expf(m1 - nm1), w1 = __expf(a1 - nm1);
            s1 = s1 * c1 + w1; m1 = nm1;
            acc.x = acc.x * (h0 ? c0 : c1) + (h0 ? w0 : w1) * vB.x;
            acc.y = acc.y * (h1 ? c0 : c1) + (h1 ? w0 : w1) * vB.y;
            acc.z = acc.z * (h2 ? c0 : c1) + (h2 ? w0 : w1) * vB.z;
            acc.w = acc.w * (h3 ? c0 : c1) + (h3 ? w0 : w1) * vB.w;
        }
    }
    if (j < end) {
        int4 p = g_pack[j];
        float4 k1 = z4, k2 = z4, k3 = z4, v1 = z4, v2 = z4, v3 = z4;
        load_edge(p, lane, act, k1, k2, k3, v1, v2, v3);
        float t0 = 0.f, t1 = 0.f;
        float4 vS = z4;
        if (act) {
            float px = q.x * (k1.x + k2.x + k3.x);
            float py = q.y * (k1.y + k2.y + k3.y);
            float pz = q.z * (k1.z + k2.z + k3.z);
            float pw = q.w * (k1.w + k2.w + k3.w);
            t0 = (h0 ? px : 0.f) + (h1 ? py : 0.f) + (h2 ? pz : 0.f) + (h3 ? pw : 0.f);
            t1 = (h0 ? 0.f : px) + (h1 ? 0.f : py) + (h2 ? 0.f : pz) + (h3 ? 0.f : pw);
            vS.x = v1.x + v2.x + v3.x; vS.y = v1.y + v2.y + v3.y;
            vS.z = v1.z + v2.z + v3.z; vS.w = v1.w + v2.w + v3.w;
        }
#pragma unroll
        for (int off = 16; off; off >>= 1) {
            t0 += __shfl_xor_sync(0xffffffffu, t0, off);
            t1 += __shfl_xor_sync(0xffffffffu, t1, off);
        }
        float a0 = t0 > 0.f ? t0 : NEG_SLOPE * t0;
        float a1 = t1 > 0.f ? t1 : NEG_SLOPE * t1;
        float nm0 = fmaxf(m0, a0);
        float c0 = __expf(m0 - nm0), w0 = __expf(a0 - nm0);
        s0 = s0 * c0 + w0; m0 = nm0;
        float nm1 = fmaxf(m1, a1);
        float c1 = __expf(m1 - nm1), w1 = __expf(a1 - nm1);
        s1 = s1 * c1 + w1; m1 = nm1;
        acc.x = acc.x * (h0 ? c0 : c1) + (h0 ? w0 : w1) * vS.x;
        acc.y = acc.y * (h1 ? c0 : c1) + (h1 ? w0 : w1) * vS.y;
        acc.z = acc.z * (h2 ? c0 : c1) + (h2 ? w0 : w1) * vS.z;
        acc.w = acc.w * (h3 ? c0 : c1) + (h3 ? w0 : w1) * vS.w;
    }

    if (act) {
        float r0 = s0 > 0.f ? 1.f / s0 : 0.f;
        float r1 = s1 > 0.f ? 1.f / s1 : 0.f;
        float4 o;
        o.x = acc.x * (h0 ? r0 : r1);
        o.y = acc.y * (h1 ? r0 : r1);
        o.z = acc.z * (h2 ? r0 : r1);
        o.w = acc.w * (h3 ? r0 : r1);
        ((float4*)(g_acc + (long)w * DO_))[lane] = o;
    }
}

// ---------------- finalize: bf16x2 concat-GEMM + relu + LayerNorm ----------------
#define FIN_LDA (KP_OUT + 8)   // 296
#define FIN_SMEM (64 * FIN_LDA * 2 * 2)   // Ah+Al bf16 = 75776 B
#define FIN_LDC 116
__global__ __launch_bounds__(256)
void finalize_bf(const float* __restrict__ nodeData,
                 const int* __restrict__ rev_nids,
                 const __nv_bfloat16* __restrict__ Wh, const __nv_bfloat16* __restrict__ Wl,
                 const float* __restrict__ ln_g, const float* __restrict__ ln_b,
                 float* __restrict__ out) {
    extern __shared__ char smraw[];
    __nv_bfloat16* Ah = (__nv_bfloat16*)smraw;
    __nv_bfloat16* Al = Ah + 64 * FIN_LDA;
    float* Cs = (float*)smraw;           // reused after mainloop (64 x FIN_LDC)
    int tid = threadIdx.x, wid = tid >> 5, lane = tid & 31;
    int m0 = blockIdx.x * 64;

    for (int idx = tid; idx < 64 * 72; idx += 256) {
        int r = idx / 72, c4 = idx - r * 72;
        int row = m0 + r;
        float4 v = make_float4(0.f, 0.f, 0.f, 0.f);
        if (row < NDST) {
            if (c4 < 25) {
                v = *(const float4*)(g_acc + (long)row * DO_ + c4 * 4);
            } else if (c4 < 68) {
                long nb = (long)rev_nids[row] * DN_;
                v = *(const float4*)(nodeData + nb + (c4 * 4 - 100));
            } else if (c4 == 68) {
                v.x = 1.0f;
            }
        }
        int off = r * FIN_LDA + c4 * 4;
        __nv_bfloat16 h; float x;
        x = v.x; h = __float2bfloat16(x); Ah[off + 0] = h; Al[off + 0] = __float2bfloat16(x - __bfloat162float(h));
        x = v.y; h = __float2bfloat16(x); Ah[off + 1] = h; Al[off + 1] = __float2bfloat16(x - __bfloat162float(h));
        x = v.z; h = __float2bfloat16(x); Ah[off + 2] = h; Al[off + 2] = __float2bfloat16(x - __bfloat162float(h));
        x = v.w; h = __float2bfloat16(x); Ah[off + 3] = h; Al[off + 3] = __float2bfloat16(x - __bfloat162float(h));
    }
    __syncthreads();

    int wm = (wid >> 2) * 32;
    int wn = (wid & 3) * 16;

    wmma::fragment<wmma::accumulator, 16, 16, 16, float> acc[2][2];
    bool act1 = (64 + wn + 16) <= NP_Q;
#pragma unroll
    for (int a = 0; a < 2; a++)
#pragma unroll
        for (int i = 0; i < 2; i++) wmma::fill_fragment(acc[a][i], 0.f);

    for (int k0 = 0; k0 < KP_OUT; k0 += 16) {
        wmma::fragment<wmma::matrix_a, 16, 16, 16, __nv_bfloat16, wmma::row_major> ah0, ah1, al0, al1;
        wmma::load_matrix_sync(ah0, Ah + (wm +  0) * FIN_LDA + k0, FIN_LDA);
        wmma::load_matrix_sync(ah1, Ah + (wm + 16) * FIN_LDA + k0, FIN_LDA);
        wmma::load_matrix_sync(al0, Al + (wm +  0) * FIN_LDA + k0, FIN_LDA);
        wmma::load_matrix_sync(al1, Al + (wm + 16) * FIN_LDA + k0, FIN_LDA);
        {
            wmma::fragment<wmma::matrix_b, 16, 16, 16, __nv_bfloat16, wmma::row_major> bh, bl;
            wmma::load_matrix_sync(bh, Wh + (long)k0 * NP_Q + wn, NP_Q);
            wmma::load_matrix_sync(bl, Wl + (long)k0 * NP_Q + wn, NP_Q);
            wmma::mma_sync(acc[0][0], al0, bh, acc[0][0]);
            wmma::mma_sync(acc[0][0], ah0, bl, acc[0][0]);
            wmma::mma_sync(acc[0][0], ah0, bh, acc[0][0]);
            wmma::mma_sync(acc[0][1], al1, bh, acc[0][1]);
            wmma::mma_sync(acc[0][1], ah1, bl, acc[0][1]);
            wmma::mma_sync(acc[0][1], ah1, bh, acc[0][1]);
        }
        if (act1) {
            wmma::fragment<wmma::matrix_b, 16, 16, 16, __nv_bfloat16, wmma::row_major> bh, bl;
            wmma::load_matrix_sync(bh, Wh + (long)k0 * NP_Q + 64 + wn, NP_Q);
            wmma::load_matrix_sync(bl, Wl + (long)k0 * NP_Q + 64 + wn, NP_Q);
            wmma::mma_sync(acc[1][0], al0, bh, acc[1][0]);
            wmma::mma_sync(acc[1][0], ah0, bl, acc[1][0]);
            wmma::mma_sync(acc[1][0], ah0, bh, acc[1][0]);
            wmma::mma_sync(acc[1][1], al1, bh, acc[1][1]);
            wmma::mma_sync(acc[1][1], ah1, bl, acc[1][1]);
            wmma::mma_sync(acc[1][1], ah1, bh, acc[1][1]);
        }
    }
    __syncthreads();

#pragma unroll
    for (int i = 0; i < 2; i++) {
        wmma::store_matrix_sync(Cs + (wm + i * 16) * FIN_LDC + wn, acc[0][i], FIN_LDC, wmma::mem_row_major);
        if (act1)
            wmma::store_matrix_sync(Cs + (wm + i * 16) * FIN_LDC + 64 + wn, acc[1][i], FIN_LDC, wmma::mem_row_major);
    }
    __syncthreads();

    float g0 = ln_g[lane], g1 = ln_g[lane + 32], g2 = ln_g[lane + 64];
    float g3 = lane < 4 ? ln_g[96 + lane] : 0.f;
    float be0 = ln_b[lane], be1 = ln_b[lane + 32], be2 = ln_b[lane + 64];
    float be3 = lane < 4 ? ln_b[96 + lane] : 0.f;

    for (int r = wid * 8; r < wid * 8 + 8; r++) {
        int row = m0 + r;
        if (row >= NDST) continue;
        float* cr = Cs + r * FIN_LDC;
        float x0 = cr[lane];        x0 = x0 > 0.f ? x0 : 0.f;
        float x1 = cr[lane + 32];   x1 = x1 > 0.f ? x1 : 0.f;
        float x2 = cr[lane + 64];   x2 = x2 > 0.f ? x2 : 0.f;
        float x3 = lane < 4 ? cr[96 + lane] : 0.f;  x3 = x3 > 0.f ? x3 : 0.f;
        float s = x0 + x1 + x2 + x3;
        float sq = x0 * x0 + x1 * x1 + x2 * x2 + x3 * x3;
#pragma unroll
        for (int off = 16; off; off >>= 1) {
            s  += __shfl_xor_sync(0xffffffffu, s, off);
            sq += __shfl_xor_sync(0xffffffffu, sq, off);
        }
        float mu = s * 0.01f;
        float var = sq * 0.01f - mu * mu;
        float inv = rsqrtf(var + 1e-5f);
        float* orow = out + (long)row * DO_;
        orow[lane]      = (x0 - mu) * inv * g0 + be0;
        orow[lane + 32] = (x1 - mu) * inv * g1 + be1;
        orow[lane + 64] = (x2 - mu) * inv * g2 + be2;
        if (lane < 4) orow[96 + lane] = (x3 - mu) * inv * g3 + be3;
    }
}

// ---------------- launch ----------------
extern "C" void kernel_launch(void* const* d_in, const int* in_sizes, int n_in,
                              void* d_out, int out_size) {
    const float* nodeData = (const float*)d_in[0];
    const float* efeat    = (const float*)d_in[1];
    const float* utd      = (const float*)d_in[2];
    const int*   rev_nids = (const int*)d_in[3];
    const int*   rev_eids = (const int*)d_in[4];
    const int*   rev_tids = (const int*)d_in[5];
    const int*   dstindex = (const int*)d_in[6];
    const float* time_w   = (const float*)d_in[8];
    const float* time_b   = (const float*)d_in[9];
    const float* Wqn      = (const float*)d_in[10];
    const float* bqn      = (const float*)d_in[11];
    const float* Wqt      = (const float*)d_in[12];
    const float* bqt      = (const float*)d_in[13];
    const float* Wkvn     = (const float*)d_in[14];
    const float* bkvn     = (const float*)d_in[15];
    const float* Wkve     = (const float*)d_in[16];
    const float* bkve     = (const float*)d_in[17];
    const float* Wkvt     = (const float*)d_in[18];
    const float* bkvt     = (const float*)d_in[19];
    const float* Wout     = (const float*)d_in[20];
    const float* bout     = (const float*)d_in[21];
    const float* ln_g     = (const float*)d_in[22];
    const float* ln_b     = (const float*)d_in[23];
    float* out = (float*)d_out;

    float *pQ, *pKVN, *pKVE, *pKVT, *pbiasq;
    __nv_bfloat16* pWS;
    cudaGetSymbolAddress((void**)&pQ,     g_Q);
    cudaGetSymbolAddress((void**)&pKVN,   g_KVN);
    cudaGetSymbolAddress((void**)&pKVE,   g_KVE);
    cudaGetSymbolAddress((void**)&pKVT,   g_KVT);
    cudaGetSymbolAddress((void**)&pbiasq, g_biasq);
    cudaGetSymbolAddress((void**)&pWS,    g_WS);

    const int* node_inv = rev_nids + NDST;

    const int sm_nd = 128 * (KP_ND + 8) * 2 * 2;   // 94208
    const int sm_t  = 128 * (KP_T  + 8) * 2 * 2;   // 61440
    cudaFuncSetAttribute((const void*)gemm_bf6<true,  false>, cudaFuncAttributeMaxDynamicSharedMemorySize, sm_nd);
    cudaFuncSetAttribute((const void*)gemm_bf6<false, false>, cudaFuncAttributeMaxDynamicSharedMemorySize, sm_nd);
    cudaFuncSetAttribute((const void*)gemm_bf6<false, true >, cudaFuncAttributeMaxDynamicSharedMemorySize, sm_nd);
    cudaFuncSetAttribute((const void*)finalize_bf, cudaFuncAttributeMaxDynamicSharedMemorySize, FIN_SMEM);

    init_kernel<<<512, 256>>>();
    hist_kernel<<<2048, 256>>>(dstindex);
    split_w<<<(KP_ND * NP_KV + 255) / 256, 256>>>(Wkvn, bkvn, bkve, bkvt,
        pWS + OFF_KVN_H, pWS + OFF_KVN_L, DN_, 2 * DO_, KP_ND, NP_KV);

    // 4th launch -> profiled
    gemm_bf6<false, false><<<(UN + 127) / 128, 256, sm_nd>>>(
        nodeData, pWS + OFF_KVN_H, pWS + OFF_KVN_L, pKVN, nullptr,
        nullptr, nullptr, nullptr, UN, DN_, KP_ND, NP_KV);

    scan1_kernel<<<NB_SCAN, 1024>>>();
    scan2_kernel<<<1, 128>>>();
    scan3_kernel<<<NB_SCAN, 1024>>>();
    scatter_kernel<<<2048, 256>>>(dstindex, node_inv, rev_eids, rev_tids);
    biasq_kernel<<<1, 128>>>(time_b, Wqt, bqt, bqn);

    split_w<<<(KP_ND * NP_Q + 255) / 256, 256>>>(Wqn, pbiasq, nullptr, nullptr,
        pWS + OFF_QN_H, pWS + OFF_QN_L, DN_, DO_, KP_ND, NP_Q);
    split_w<<<(KP_ND * NP_KV + 255) / 256, 256>>>(Wkve, nullptr, nullptr, nullptr,
        pWS + OFF_KVE_H, pWS + OFF_KVE_L, DN_, 2 * DO_, KP_ND, NP_KV);
    split_w<<<(KP_T * NP_KV + 255) / 256, 256>>>(Wkvt, nullptr, nullptr, nullptr,
        pWS + OFF_KVT_H, pWS + OFF_KVT_L, DT_, 2 * DO_, KP_T, NP_KV);
    split_w<<<(KP_OUT * NP_Q + 255) / 256, 256>>>(Wout, bout, nullptr, nullptr,
        pWS + OFF_OUT_H, pWS + OFF_OUT_L, DN_ + DO_, DO_, KP_OUT, NP_Q);

    gemm_bf6<true, false><<<(NDST + 127) / 128, 256, sm_nd>>>(
        nodeData, pWS + OFF_QN_H, pWS + OFF_QN_L, pQ, rev_nids,
        nullptr, nullptr, nullptr, NDST, DN_, KP_ND, NP_Q);
    gemm_bf6<false, false><<<(UE + 127) / 128, 256, sm_nd>>>(
        efeat, pWS + OFF_KVE_H, pWS + OFF_KVE_L, pKVE, nullptr,
        nullptr, nullptr, nullptr, UE, DN_, KP_ND, NP_KV);
    gemm_bf6<false, true><<<(UT + 127) / 128, 256, sm_t>>>(
        nullptr, pWS + OFF_KVT_H, pWS + OFF_KVT_L, pKVT, nullptr,
        utd, time_w, time_b, UT, DT_, KP_T, NP_KV);

    attn_kernel<<<(NDST + 7) / 8, 256>>>();

    finalize_bf<<<(NDST + 63) / 64, 256, FIN_SMEM>>>(
        nodeData, rev_nids, pWS + OFF_OUT_H, pWS + OFF_OUT_L, ln_g, ln_b, out);
}

// round 14
// speedup vs baseline: 1.1923x; 1.0829x over previous
#include <cuda_runtime.h>
#include <cuda_bf16.h>
#include <mma.h>
using namespace nvcuda;

#define NDST 100000
#define NE   1000000
#define UN   200000
#define UE   100000
#define UT   100000
#define DN_  172
#define DT_  100
#define DO_  100
#define NEG_SLOPE 0.2f

// padded row counts
#define UN_P  200064
#define M1_P  100096

#define NP_KV 208
#define NP_Q  112
#define KP_ND 176
#define KP_T  112
#define KP_OUT 288

// split-weight arena offsets (bf16 elements)
#define OFF_KVN_H 0
#define OFF_KVN_L (OFF_KVN_H + KP_ND * NP_KV)
#define OFF_KVE_H (OFF_KVN_L + KP_ND * NP_KV)
#define OFF_KVE_L (OFF_KVE_H + KP_ND * NP_KV)
#define OFF_KVT_H (OFF_KVE_L + KP_ND * NP_KV)
#define OFF_KVT_L (OFF_KVT_H + KP_T * NP_KV)
#define OFF_QN_H  (OFF_KVT_L + KP_T * NP_KV)
#define OFF_QN_L  (OFF_QN_H + KP_ND * NP_Q)
#define OFF_OUT_H (OFF_QN_L + KP_ND * NP_Q)
#define OFF_OUT_L (OFF_OUT_H + KP_OUT * NP_Q)
#define WSPLIT_TOTAL (OFF_OUT_L + KP_OUT * NP_Q)

// ---------------- scratch (device globals; no allocation) ----------------
__device__ float         g_Q   [M1_P * NP_Q];
__device__ float         g_KVN [UN_P * NP_KV];
__device__ float         g_KVE [M1_P * NP_KV];
__device__ float         g_KVT [M1_P * NP_KV];
__device__ float         g_acc [NDST * DO_];
__device__ float         g_biasq[DO_];
__device__ __nv_bfloat16 g_WS  [WSPLIT_TOTAL];
__device__ int           g_cnt [NDST];
__device__ int           g_off [NDST + 1];
__device__ int           g_cur [NDST];
__device__ int           g_bsum[128];
__device__ int           g_btop[128];
__device__ int4          g_pack[NE];

__global__ void biasq_kernel(const float* __restrict__ time_b,
                             const float* __restrict__ Wqt,
                             const float* __restrict__ bqt,
                             const float* __restrict__ bqn) {
    int j = threadIdx.x;
    if (j >= DO_) return;
    float acc = bqt[j] + bqn[j];
    for (int k = 0; k < DT_; k++) acc += cosf(time_b[k]) * Wqt[k * DO_ + j];
    g_biasq[j] = acc;
}

// ---------------- weight split: rows 0..K-1 = W, row K = bias sum, rest 0 ----------------
__global__ void split_w(const float* __restrict__ W,
                        const float* __restrict__ b0, const float* __restrict__ b1,
                        const float* __restrict__ b2,
                        __nv_bfloat16* __restrict__ oh, __nv_bfloat16* __restrict__ ol,
                        int K, int N, int KP, int NP) {
    int idx = blockIdx.x * blockDim.x + threadIdx.x;
    if (idx >= KP * NP) return;
    int k = idx / NP, n = idx - k * NP;
    float val = 0.f;
    if (n < N) {
        if (k < K) val = W[(long)k * N + n];
        else if (k == K) {
            if (b0) val += b0[n];
            if (b1) val += b1[n];
            if (b2) val += b2[n];
        }
    }
    __nv_bfloat16 h = __float2bfloat16(val);
    oh[idx] = h;
    ol[idx] = __float2bfloat16(val - __bfloat162float(h));
}

// ---------------- CSR build ----------------
__global__ void hist_kernel(const int* __restrict__ dsti) {
    int idx = blockIdx.x * blockDim.x + threadIdx.x;
    int stride = gridDim.x * blockDim.x;
    for (int e = idx; e < NE; e += stride) atomicAdd(&g_cnt[dsti[e]], 1);
}

#define NB_SCAN ((NDST + 1023) / 1024)   // 98

__global__ __launch_bounds__(1024)
void scan1_kernel() {
    __shared__ int ss[1024];
    int t = threadIdx.x;
    int i = blockIdx.x * 1024 + t;
    int v = (i < NDST) ? g_cnt[i] : 0;
    ss[t] = v;
    __syncthreads();
    for (int off = 1; off < 1024; off <<= 1) {
        int u = (t >= off) ? ss[t - off] : 0;
        __syncthreads();
        ss[t] += u;
        __syncthreads();
    }
    if (i < NDST) g_off[i] = ss[t] - v;
    if (t == 1023) g_bsum[blockIdx.x] = ss[1023];
}

__global__ __launch_bounds__(128)
void scan2_kernel() {
    __shared__ int ss[128];
    int t = threadIdx.x;
    int v = (t < NB_SCAN) ? g_bsum[t] : 0;
    ss[t] = v;
    __syncthreads();
    for (int off = 1; off < 128; off <<= 1) {
        int u = (t >= off) ? ss[t - off] : 0;
        __syncthreads();
        ss[t] += u;
        __syncthreads();
    }
    g_btop[t] = ss[t] - v;
}

__global__ __launch_bounds__(1024)
void scan3_kernel() {
    int t = threadIdx.x;
    int i = blockIdx.x * 1024 + t;
    if (i < NDST) {
        int o = g_off[i] + g_btop[blockIdx.x];
        g_off[i] = o;
        g_cur[i] = o;
    }
    if (i == 0) g_off[NDST] = NE;
}

__global__ void scatter_kernel(const int* __restrict__ dsti,
                               const int* __restrict__ node_inv,
                               const int* __restrict__ eids,
                               const int* __restrict__ tids) {
    int idx = blockIdx.x * blockDim.x + threadIdx.x;
    int stride = gridDim.x * blockDim.x;
    for (int e = idx; e < NE; e += stride) {
        int pos = atomicAdd(&g_cur[dsti[e]], 1);
        g_pack[pos] = make_int4(node_inv[e], eids[e], tids[e], 0);
    }
}

// ---------------- bf16x2 GEMM v5: n-pass outer (2 passes), 2 N-tiles/warp, sync-free ----------------
// 256 threads (8 warps = 2M x 4Ngroups x 2 tiles), BM=64. A hi/lo staged once across full K.
// TIMEF: A[row,k] = cos(utd[row]*tw[k]+tb[k]) computed inline (kvt path).
template <bool GATHER, bool TIMEF>
__global__ __launch_bounds__(256, 3)
void gemm_bf5(const float* __restrict__ A,
              const __nv_bfloat16* __restrict__ Wh, const __nv_bfloat16* __restrict__ Wl,
              float* __restrict__ C, const int* __restrict__ gidx,
              const float* __restrict__ utd, const float* __restrict__ tw,
              const float* __restrict__ tb,
              int M, int K, int KP, int NP) {
    extern __shared__ char smraw[];
    const int LDA = KP + 8;
    __nv_bfloat16* Ah = (__nv_bfloat16*)smraw;
    __nv_bfloat16* Al = Ah + 64 * LDA;
    int tid = threadIdx.x, wid = tid >> 5;
    int m0 = blockIdx.x * 64;

    int nc4 = KP >> 2;
    for (int idx = tid; idx < 64 * nc4; idx += 256) {
        int r = idx / nc4, c4 = idx - r * nc4;
        int row = m0 + r;
        float4 v = make_float4(0.f, 0.f, 0.f, 0.f);
        if (row < M) {
            int k = c4 * 4;
            if (TIMEF) {
                if (k + 3 < K) {
                    float4 w4 = *(const float4*)(tw + k);
                    float4 b4 = *(const float4*)(tb + k);
                    float td = utd[row];
                    v.x = cosf(td * w4.x + b4.x);
                    v.y = cosf(td * w4.y + b4.y);
                    v.z = cosf(td * w4.z + b4.z);
                    v.w = cosf(td * w4.w + b4.w);
                } else if (K >= k && K < k + 4) {
                    ((float*)&v)[K - k] = 1.0f;
                }
            } else {
                long ab = (long)(GATHER ? gidx[row] : row) * K;
                if (k + 3 < K) {
                    v = *(const float4*)(A + ab + k);
                } else {
                    if (k + 0 < K) v.x = A[ab + k + 0];
                    if (k + 1 < K) v.y = A[ab + k + 1];
                    if (k + 2 < K) v.z = A[ab + k + 2];
                    if (k + 3 < K) v.w = A[ab + k + 3];
                }
                if (K >= k && K < k + 4) ((float*)&v)[K - k] = 1.0f;
            }
        }
        int off = r * LDA + c4 * 4;
        __nv_bfloat16 h; float x;
        x = v.x; h = __float2bfloat16(x); Ah[off + 0] = h; Al[off + 0] = __float2bfloat16(x - __bfloat162float(h));
        x = v.y; h = __float2bfloat16(x); Ah[off + 1] = h; Al[off + 1] = __float2bfloat16(x - __bfloat162float(h));
        x = v.z; h = __float2bfloat16(x); Ah[off + 2] = h; Al[off + 2] = __float2bfloat16(x - __bfloat162float(h));
        x = v.w; h = __float2bfloat16(x); Ah[off + 3] = h; Al[off + 3] = __float2bfloat16(x - __bfloat162float(h));
    }
    __syncthreads();

    int wm = (wid >> 2) * 32;   // 0 or 32
    int wt = wid & 3;           // N-group 0..3
    int NT = NP >> 4;           // 13 (kv) or 7 (q)

    for (int pass = 0; pass < 2; pass++) {
        int ta = pass * 8 + wt * 2;
        if (ta >= NT) break;
        bool actB = (ta + 1) < NT;

        wmma::fragment<wmma::accumulator, 16, 16, 16, float> acc00, acc10, acc01, acc11;
        wmma::fill_fragment(acc00, 0.f);
        wmma::fill_fragment(acc10, 0.f);
        wmma::fill_fragment(acc01, 0.f);
        wmma::fill_fragment(acc11, 0.f);

        for (int k0 = 0; k0 < KP; k0 += 16) {
            wmma::fragment<wmma::matrix_a, 16, 16, 16, __nv_bfloat16, wmma::row_major> ah0, ah1, al0, al1;
            wmma::load_matrix_sync(ah0, Ah + (wm +  0) * LDA + k0, LDA);
            wmma::load_matrix_sync(al0, Al + (wm +  0) * LDA + k0, LDA);
            wmma::load_matrix_sync(ah1, Ah + (wm + 16) * LDA + k0, LDA);
            wmma::load_matrix_sync(al1, Al + (wm + 16) * LDA + k0, LDA);

            wmma::fragment<wmma::matrix_b, 16, 16, 16, __nv_bfloat16, wmma::row_major> bh0, bl0, bh1, bl1;
            wmma::load_matrix_sync(bh0, Wh + (long)k0 * NP + ta * 16, NP);
            wmma::load_matrix_sync(bl0, Wl + (long)k0 * NP + ta * 16, NP);
            if (actB) {
                wmma::load_matrix_sync(bh1, Wh + (long)k0 * NP + (ta + 1) * 16, NP);
                wmma::load_matrix_sync(bl1, Wl + (long)k0 * NP + (ta + 1) * 16, NP);
            }

            wmma::mma_sync(acc00, al0, bh0, acc00);
            wmma::mma_sync(acc00, ah0, bl0, acc00);
            wmma::mma_sync(acc00, ah0, bh0, acc00);
            wmma::mma_sync(acc10, al1, bh0, acc10);
            wmma::mma_sync(acc10, ah1, bl0, acc10);
            wmma::mma_sync(acc10, ah1, bh0, acc10);
            if (actB) {
                wmma::mma_sync(acc01, al0, bh1, acc01);
                wmma::mma_sync(acc01, ah0, bl1, acc01);
                wmma::mma_sync(acc01, ah0, bh1, acc01);
                wmma::mma_sync(acc11, al1, bh1, acc11);
                wmma::mma_sync(acc11, ah1, bl1, acc11);
                wmma::mma_sync(acc11, ah1, bh1, acc11);
            }
        }
        wmma::store_matrix_sync(C + (long)(m0 + wm +  0) * NP + ta * 16, acc00, NP, wmma::mem_row_major);
        wmma::store_matrix_sync(C + (long)(m0 + wm + 16) * NP + ta * 16, acc10, NP, wmma::mem_row_major);
        if (actB) {
            wmma::store_matrix_sync(C + (long)(m0 + wm +  0) * NP + (ta + 1) * 16, acc01, NP, wmma::mem_row_major);
            wmma::store_matrix_sync(C + (long)(m0 + wm + 16) * NP + (ta + 1) * 16, acc11, NP, wmma::mem_row_major);
        }
    }
}

// ---------------- attention: one warp per dst, online softmax, 2-edge pipeline ----------------
__device__ __forceinline__ void load_edge(int4 p, int lane, bool act,
                                          float4& k1, float4& k2, float4& k3,
                                          float4& v1, float4& v2, float4& v3) {
    if (act) {
        const float4* kn = (const float4*)(g_KVN + (long)p.x * NP_KV);
        const float4* ke = (const float4*)(g_KVE + (long)p.y * NP_KV);
        const float4* kt = (const float4*)(g_KVT + (long)p.z * NP_KV);
        k1 = kn[lane];      k2 = ke[lane];      k3 = kt[lane];
        v1 = kn[25 + lane]; v2 = ke[25 + lane]; v3 = kt[25 + lane];
    }
}

__global__ __launch_bounds__(256)
void attn_kernel() {
    int w = (int)((blockIdx.x * (long)blockDim.x + threadIdx.x) >> 5);
    int lane = threadIdx.x & 31;
    if (w >= NDST) return;
    int beg = g_off[w], end = g_off[w + 1];

    bool act = lane < 25;
    int base = lane * 4;
    bool h0 = base + 0 < 50, h1 = base + 1 < 50, h2 = base + 2 < 50, h3 = base + 3 < 50;

    float4 q = make_float4(0.f, 0.f, 0.f, 0.f);
    if (act) q = ((const float4*)(g_Q + (long)w * NP_Q))[lane];

    float4 acc = make_float4(0.f, 0.f, 0.f, 0.f);
    float m0 = -1e30f, m1 = -1e30f, s0 = 0.f, s1 = 0.f;
    float4 z4 = make_float4(0.f, 0.f, 0.f, 0.f);

    int j = beg;
    for (; j + 1 < end; j += 2) {
        int4 pA = g_pack[j];
        int4 pB = g_pack[j + 1];
        float4 ka1 = z4, ka2 = z4, ka3 = z4, va1 = z4, va2 = z4, va3 = z4;
        float4 kb1 = z4, kb2 = z4, kb3 = z4, vb1 = z4, vb2 = z4, vb3 = z4;
        load_edge(pA, lane, act, ka1, ka2, ka3, va1, va2, va3);
        load_edge(pB, lane, act, kb1, kb2, kb3, vb1, vb2, vb3);

        float t0a = 0.f, t1a = 0.f, t0b = 0.f, t1b = 0.f;
        float4 vA = z4, vB = z4;
        if (act) {
            float ax = q.x * (ka1.x + ka2.x + ka3.x);
            float ay = q.y * (ka1.y + ka2.y + ka3.y);
            float az = q.z * (ka1.z + ka2.z + ka3.z);
            float aw = q.w * (ka1.w + ka2.w + ka3.w);
            t0a = (h0 ? ax : 0.f) + (h1 ? ay : 0.f) + (h2 ? az : 0.f) + (h3 ? aw : 0.f);
            t1a = (h0 ? 0.f : ax) + (h1 ? 0.f : ay) + (h2 ? 0.f : az) + (h3 ? 0.f : aw);
            float bx = q.x * (kb1.x + kb2.x + kb3.x);
            float by = q.y * (kb1.y + kb2.y + kb3.y);
            float bz = q.z * (kb1.z + kb2.z + kb3.z);
            float bw = q.w * (kb1.w + kb2.w + kb3.w);
            t0b = (h0 ? bx : 0.f) + (h1 ? by : 0.f) + (h2 ? bz : 0.f) + (h3 ? bw : 0.f);
            t1b = (h0 ? 0.f : bx) + (h1 ? 0.f : by) + (h2 ? 0.f : bz) + (h3 ? 0.f : bw);
            vA.x = va1.x + va2.x + va3.x; vA.y = va1.y + va2.y + va3.y;
            vA.z = va1.z + va2.z + va3.z; vA.w = va1.w + va2.w + va3.w;
            vB.x = vb1.x + vb2.x + vb3.x; vB.y = vb1.y + vb2.y + vb3.y;
            vB.z = vb1.z + vb2.z + vb3.z; vB.w = vb1.w + vb2.w + vb3.w;
        }
#pragma unroll
        for (int off = 16; off; off >>= 1) {
            t0a += __shfl_xor_sync(0xffffffffu, t0a, off);
            t1a += __shfl_xor_sync(0xffffffffu, t1a, off);
            t0b += __shfl_xor_sync(0xffffffffu, t0b, off);
            t1b += __shfl_xor_sync(0xffffffffu, t1b, off);
        }
        {
            float a0 = t0a > 0.f ? t0a : NEG_SLOPE * t0a;
            float a1 = t1a > 0.f ? t1a : NEG_SLOPE * t1a;
            float nm0 = fmaxf(m0, a0);
            float c0 = __expf(m0 - nm0), w0 = __expf(a0 - nm0);
            s0 = s0 * c0 + w0; m0 = nm0;
            float nm1 = fmaxf(m1, a1);
            float c1 = __expf(m1 - nm1), w1 = __expf(a1 - nm1);
            s1 = s1 * c1 + w1; m1 = nm1;
            acc.x = acc.x * (h0 ? c0 : c1) + (h0 ? w0 : w1) * vA.x;
            acc.y = acc.y * (h1 ? c0 : c1) + (h1 ? w0 : w1) * vA.y;
            acc.z = acc.z * (h2 ? c0 : c1) + (h2 ? w0 : w1) * vA.z;
            acc.w = acc.w * (h3 ? c0 : c1) + (h3 ? w0 : w1) * vA.w;
        }
        {
            float a0 = t0b > 0.f ? t0b : NEG_SLOPE * t0b;
            float a1 = t1b > 0.f ? t1b : NEG_SLOPE * t1b;
            float nm0 = fmaxf(m0, a0);
            float c0 = __expf(m0 - nm0), w0 = __expf(a0 - nm0);
            s0 = s0 * c0 + w0; m0 = nm0;
            float nm1 = fmaxf(m1, a1);
            float c1 = __expf(m1 - nm1), w1 = __expf(a1 - nm1);
            s1 = s1 * c1 + w1; m1 = nm1;
            acc.x = acc.x * (h0 ? c0 : c1) + (h0 ? w0 : w1) * vB.x;
            acc.y = acc.y * (h1 ? c0 : c1) + (h1 ? w0 : w1) * vB.y;
            acc.z = acc.z * (h2 ? c0 : c1) + (h2 ? w0 : w1) * vB.z;
            acc.w = acc.w * (h3 ? c0 : c1) + (h3 ? w0 : w1) * vB.w;
        }
    }
    if (j < end) {
        int4 p = g_pack[j];
        float4 k1 = z4, k2 = z4, k3 = z4, v1 = z4, v2 = z4, v3 = z4;
        load_edge(p, lane, act, k1, k2, k3, v1, v2, v3);
        float t0 = 0.f, t1 = 0.f;
        float4 vS = z4;
        if (act) {
            float px = q.x * (k1.x + k2.x + k3.x);
            float py = q.y * (k1.y + k2.y + k3.y);
            float pz = q.z * (k1.z + k2.z + k3.z);
            float pw = q.w * (k1.w + k2.w + k3.w);
            t0 = (h0 ? px : 0.f) + (h1 ? py : 0.f) + (h2 ? pz : 0.f) + (h3 ? pw : 0.f);
            t1 = (h0 ? 0.f : px) + (h1 ? 0.f : py) + (h2 ? 0.f : pz) + (h3 ? 0.f : pw);
            vS.x = v1.x + v2.x + v3.x; vS.y = v1.y + v2.y + v3.y;
            vS.z = v1.z + v2.z + v3.z; vS.w = v1.w + v2.w + v3.w;
        }
#pragma unroll
        for (int off = 16; off; off >>= 1) {
            t0 += __shfl_xor_sync(0xffffffffu, t0, off);
            t1 += __shfl_xor_sync(0xffffffffu, t1, off);
        }
        float a0 = t0 > 0.f ? t0 : NEG_SLOPE * t0;
        float a1 = t1 > 0.f ? t1 : NEG_SLOPE * t1;
        float nm0 = fmaxf(m0, a0);
        float c0 = __expf(m0 - nm0), w0 = __expf(a0 - nm0);
        s0 = s0 * c0 + w0; m0 = nm0;
        float nm1 = fmaxf(m1, a1);
        float c1 = __expf(m1 - nm1), w1 = __expf(a1 - nm1);
        s1 = s1 * c1 + w1; m1 = nm1;
        acc.x = acc.x * (h0 ? c0 : c1) + (h0 ? w0 : w1) * vS.x;
        acc.y = acc.y * (h1 ? c0 : c1) + (h1 ? w0 : w1) * vS.y;
        acc.z = acc.z * (h2 ? c0 : c1) + (h2 ? w0 : w1) * vS.z;
        acc.w = acc.w * (h3 ? c0 : c1) + (h3 ? w0 : w1) * vS.w;
    }

    if (act) {
        float r0 = s0 > 0.f ? 1.f / s0 : 0.f;
        float r1 = s1 > 0.f ? 1.f / s1 : 0.f;
        float4 o;
        o.x = acc.x * (h0 ? r0 : r1);
        o.y = acc.y * (h1 ? r0 : r1);
        o.z = acc.z * (h2 ? r0 : r1);
        o.w = acc.w * (h3 ? r0 : r1);
        ((float4*)(g_acc + (long)w * DO_))[lane] = o;
    }
}

// ---------------- finalize: bf16x2 concat-GEMM + relu + LayerNorm ----------------
#define FIN_LDA (KP_OUT + 8)   // 296
#define FIN_SMEM (64 * FIN_LDA * 2 * 2)   // Ah+Al bf16 = 75776 B
#define FIN_LDC 116
__global__ __launch_bounds__(256)
void finalize_bf(const float* __restrict__ nodeData,
                 const int* __restrict__ rev_nids,
                 const __nv_bfloat16* __restrict__ Wh, const __nv_bfloat16* __restrict__ Wl,
                 const float* __restrict__ ln_g, const float* __restrict__ ln_b,
                 float* __restrict__ out) {
    extern __shared__ char smraw[];
    __nv_bfloat16* Ah = (__nv_bfloat16*)smraw;
    __nv_bfloat16* Al = Ah + 64 * FIN_LDA;
    float* Cs = (float*)smraw;
    int tid = threadIdx.x, wid = tid >> 5, lane = tid & 31;
    int m0 = blockIdx.x * 64;

    for (int idx = tid; idx < 64 * 72; idx += 256) {
        int r = idx / 72, c4 = idx - r * 72;
        int row = m0 + r;
        float4 v = make_float4(0.f, 0.f, 0.f, 0.f);
        if (row < NDST) {
            if (c4 < 25) {
                v = *(const float4*)(g_acc + (long)row * DO_ + c4 * 4);
            } else if (c4 < 68) {
                long nb = (long)rev_nids[row] * DN_;
                v = *(const float4*)(nodeData + nb + (c4 * 4 - 100));
            } else if (c4 == 68) {
                v.x = 1.0f;
            }
        }
        int off = r * FIN_LDA + c4 * 4;
        __nv_bfloat16 h; float x;
        x = v.x; h = __float2bfloat16(x); Ah[off + 0] = h; Al[off + 0] = __float2bfloat16(x - __bfloat162float(h));
        x = v.y; h = __float2bfloat16(x); Ah[off + 1] = h; Al[off + 1] = __float2bfloat16(x - __bfloat162float(h));
        x = v.z; h = __float2bfloat16(x); Ah[off + 2] = h; Al[off + 2] = __float2bfloat16(x - __bfloat162float(h));
        x = v.w; h = __float2bfloat16(x); Ah[off + 3] = h; Al[off + 3] = __float2bfloat16(x - __bfloat162float(h));
    }
    __syncthreads();

    int wm = (wid >> 2) * 32;
    int wn = (wid & 3) * 16;

    wmma::fragment<wmma::accumulator, 16, 16, 16, float> acc[2][2];
    bool act1 = (64 + wn + 16) <= NP_Q;
#pragma unroll
    for (int a = 0; a < 2; a++)
#pragma unroll
        for (int i = 0; i < 2; i++) wmma::fill_fragment(acc[a][i], 0.f);

    for (int k0 = 0; k0 < KP_OUT; k0 += 16) {
        wmma::fragment<wmma::matrix_a, 16, 16, 16, __nv_bfloat16, wmma::row_major> ah0, ah1, al0, al1;
        wmma::load_matrix_sync(ah0, Ah + (wm +  0) * FIN_LDA + k0, FIN_LDA);
        wmma::load_matrix_sync(ah1, Ah + (wm + 16) * FIN_LDA + k0, FIN_LDA);
        wmma::load_matrix_sync(al0, Al + (wm +  0) * FIN_LDA + k0, FIN_LDA);
        wmma::load_matrix_sync(al1, Al + (wm + 16) * FIN_LDA + k0, FIN_LDA);
        {
            wmma::fragment<wmma::matrix_b, 16, 16, 16, __nv_bfloat16, wmma::row_major> bh, bl;
            wmma::load_matrix_sync(bh, Wh + (long)k0 * NP_Q + wn, NP_Q);
            wmma::load_matrix_sync(bl, Wl + (long)k0 * NP_Q + wn, NP_Q);
            wmma::mma_sync(acc[0][0], al0, bh, acc[0][0]);
            wmma::mma_sync(acc[0][0], ah0, bl, acc[0][0]);
            wmma::mma_sync(acc[0][0], ah0, bh, acc[0][0]);
            wmma::mma_sync(acc[0][1], al1, bh, acc[0][1]);
            wmma::mma_sync(acc[0][1], ah1, bl, acc[0][1]);
            wmma::mma_sync(acc[0][1], ah1, bh, acc[0][1]);
        }
        if (act1) {
            wmma::fragment<wmma::matrix_b, 16, 16, 16, __nv_bfloat16, wmma::row_major> bh, bl;
            wmma::load_matrix_sync(bh, Wh + (long)k0 * NP_Q + 64 + wn, NP_Q);
            wmma::load_matrix_sync(bl, Wl + (long)k0 * NP_Q + 64 + wn, NP_Q);
            wmma::mma_sync(acc[1][0], al0, bh, acc[1][0]);
            wmma::mma_sync(acc[1][0], ah0, bl, acc[1][0]);
            wmma::mma_sync(acc[1][0], ah0, bh, acc[1][0]);
            wmma::mma_sync(acc[1][1], al1, bh, acc[1][1]);
            wmma::mma_sync(acc[1][1], ah1, bl, acc[1][1]);
            wmma::mma_sync(acc[1][1], ah1, bh, acc[1][1]);
        }
    }
    __syncthreads();

#pragma unroll
    for (int i = 0; i < 2; i++) {
        wmma::store_matrix_sync(Cs + (wm + i * 16) * FIN_LDC + wn, acc[0][i], FIN_LDC, wmma::mem_row_major);
        if (act1)
            wmma::store_matrix_sync(Cs + (wm + i * 16) * FIN_LDC + 64 + wn, acc[1][i], FIN_LDC, wmma::mem_row_major);
    }
    __syncthreads();

    float g0 = ln_g[lane], g1 = ln_g[lane + 32], g2 = ln_g[lane + 64];
    float g3 = lane < 4 ? ln_g[96 + lane] : 0.f;
    float be0 = ln_b[lane], be1 = ln_b[lane + 32], be2 = ln_b[lane + 64];
    float be3 = lane < 4 ? ln_b[96 + lane] : 0.f;

    for (int r = wid * 8; r < wid * 8 + 8; r++) {
        int row = m0 + r;
        if (row >= NDST) continue;
        float* cr = Cs + r * FIN_LDC;
        float x0 = cr[lane];        x0 = x0 > 0.f ? x0 : 0.f;
        float x1 = cr[lane + 32];   x1 = x1 > 0.f ? x1 : 0.f;
        float x2 = cr[lane + 64];   x2 = x2 > 0.f ? x2 : 0.f;
        float x3 = lane < 4 ? cr[96 + lane] : 0.f;  x3 = x3 > 0.f ? x3 : 0.f;
        float s = x0 + x1 + x2 + x3;
        float sq = x0 * x0 + x1 * x1 + x2 * x2 + x3 * x3;
#pragma unroll
        for (int off = 16; off; off >>= 1) {
            s  += __shfl_xor_sync(0xffffffffu, s, off);
            sq += __shfl_xor_sync(0xffffffffu, sq, off);
        }
        float mu = s * 0.01f;
        float var = sq * 0.01f - mu * mu;
        float inv = rsqrtf(var + 1e-5f);
        float* orow = out + (long)row * DO_;
        orow[lane]      = (x0 - mu) * inv * g0 + be0;
        orow[lane + 32] = (x1 - mu) * inv * g1 + be1;
        orow[lane + 64] = (x2 - mu) * inv * g2 + be2;
        if (lane < 4) orow[96 + lane] = (x3 - mu) * inv * g3 + be3;
    }
}

// ---------------- launch ----------------
extern "C" void kernel_launch(void* const* d_in, const int* in_sizes, int n_in,
                              void* d_out, int out_size) {
    const float* nodeData = (const float*)d_in[0];
    const float* efeat    = (const float*)d_in[1];
    const float* utd      = (const float*)d_in[2];
    const int*   rev_nids = (const int*)d_in[3];
    const int*   rev_eids = (const int*)d_in[4];
    const int*   rev_tids = (const int*)d_in[5];
    const int*   dstindex = (const int*)d_in[6];
    const float* time_w   = (const float*)d_in[8];
    const float* time_b   = (const float*)d_in[9];
    const float* Wqn      = (const float*)d_in[10];
    const float* bqn      = (const float*)d_in[11];
    const float* Wqt      = (const float*)d_in[12];
    const float* bqt      = (const float*)d_in[13];
    const float* Wkvn     = (const float*)d_in[14];
    const float* bkvn     = (const float*)d_in[15];
    const float* Wkve     = (const float*)d_in[16];
    const float* bkve     = (const float*)d_in[17];
    const float* Wkvt     = (const float*)d_in[18];
    const float* bkvt     = (const float*)d_in[19];
    const float* Wout     = (const float*)d_in[20];
    const float* bout     = (const float*)d_in[21];
    const float* ln_g     = (const float*)d_in[22];
    const float* ln_b     = (const float*)d_in[23];
    float* out = (float*)d_out;

    float *pQ, *pKVN, *pKVE, *pKVT, *pbiasq;
    __nv_bfloat16* pWS;
    int* pCnt;
    cudaGetSymbolAddress((void**)&pQ,     g_Q);
    cudaGetSymbolAddress((void**)&pKVN,   g_KVN);
    cudaGetSymbolAddress((void**)&pKVE,   g_KVE);
    cudaGetSymbolAddress((void**)&pKVT,   g_KVT);
    cudaGetSymbolAddress((void**)&pbiasq, g_biasq);
    cudaGetSymbolAddress((void**)&pWS,    g_WS);
    cudaGetSymbolAddress((void**)&pCnt,   g_cnt);

    const int* node_inv = rev_nids + NDST;

    const int sm_nd = 64 * (KP_ND + 8) * 2 * 2;   // 47104
    const int sm_t  = 64 * (KP_T  + 8) * 2 * 2;   // 30720
    cudaFuncSetAttribute((const void*)gemm_bf5<true,  false>, cudaFuncAttributeMaxDynamicSharedMemorySize, sm_nd);
    cudaFuncSetAttribute((const void*)gemm_bf5<false, false>, cudaFuncAttributeMaxDynamicSharedMemorySize, sm_nd);
    cudaFuncSetAttribute((const void*)gemm_bf5<false, true >, cudaFuncAttributeMaxDynamicSharedMemorySize, sm_nd);
    cudaFuncSetAttribute((const void*)finalize_bf, cudaFuncAttributeMaxDynamicSharedMemorySize, FIN_SMEM);

    cudaMemsetAsync(pCnt, 0, NDST * sizeof(int));

    // kernel launches: 1 hist, 2 split_w(kvn), 3 scan1, 4 gemm_kvn (profiled)
    hist_kernel<<<2048, 256>>>(dstindex);
    split_w<<<(KP_ND * NP_KV + 255) / 256, 256>>>(Wkvn, bkvn, bkve, bkvt,
        pWS + OFF_KVN_H, pWS + OFF_KVN_L, DN_, 2 * DO_, KP_ND, NP_KV);
    scan1_kernel<<<NB_SCAN, 1024>>>();

    gemm_bf5<false, false><<<UN / 64, 256, sm_nd>>>(
        nodeData, pWS + OFF_KVN_H, pWS + OFF_KVN_L, pKVN, nullptr,
        nullptr, nullptr, nullptr, UN, DN_, KP_ND, NP_KV);

    scan2_kernel<<<1, 128>>>();
    scan3_kernel<<<NB_SCAN, 1024>>>();
    scatter_kernel<<<2048, 256>>>(dstindex, node_inv, rev_eids, rev_tids);
    biasq_kernel<<<1, 128>>>(time_b, Wqt, bqt, bqn);

    split_w<<<(KP_ND * NP_Q + 255) / 256, 256>>>(Wqn, pbiasq, nullptr, nullptr,
        pWS + OFF_QN_H, pWS + OFF_QN_L, DN_, DO_, KP_ND, NP_Q);
    split_w<<<(KP_ND * NP_KV + 255) / 256, 256>>>(Wkve, nullptr, nullptr, nullptr,
        pWS + OFF_KVE_H, pWS + OFF_KVE_L, DN_, 2 * DO_, KP_ND, NP_KV);
    split_w<<<(KP_T * NP_KV + 255) / 256, 256>>>(Wkvt, nullptr, nullptr, nullptr,
        pWS + OFF_KVT_H, pWS + OFF_KVT_L, DT_, 2 * DO_, KP_T, NP_KV);
    split_w<<<(KP_OUT * NP_Q + 255) / 256, 256>>>(Wout, bout, nullptr, nullptr,
        pWS + OFF_OUT_H, pWS + OFF_OUT_L, DN_ + DO_, DO_, KP_OUT, NP_Q);

    gemm_bf5<true, false><<<(NDST + 63) / 64, 256, sm_nd>>>(
        nodeData, pWS + OFF_QN_H, pWS + OFF_QN_L, pQ, rev_nids,
        nullptr, nullptr, nullptr, NDST, DN_, KP_ND, NP_Q);
    gemm_bf5<false, false><<<(UE + 63) / 64, 256, sm_nd>>>(
        efeat, pWS + OFF_KVE_H, pWS + OFF_KVE_L, pKVE, nullptr,
        nullptr, nullptr, nullptr, UE, DN_, KP_ND, NP_KV);
    gemm_bf5<false, true><<<(UT + 63) / 64, 256, sm_t>>>(
        nullptr, pWS + OFF_KVT_H, pWS + OFF_KVT_L, pKVT, nullptr,
        utd, time_w, time_b, UT, DT_, KP_T, NP_KV);

    attn_kernel<<<(NDST + 7) / 8, 256>>>();

    finalize_bf<<<(NDST + 63) / 64, 256, FIN_SMEM>>>(
        nodeData, rev_nids, pWS + OFF_OUT_H, pWS + OFF_OUT_L, ln_g, ln_b, out);
}

// round 15
// speedup vs baseline: 1.2577x; 1.0548x over previous
#include <cuda_runtime.h>
#include <cuda_bf16.h>
#include <mma.h>
using namespace nvcuda;

#define NDST 100000
#define NE   1000000
#define UN   200000
#define UE   100000
#define UT   100000
#define DN_  172
#define DT_  100
#define DO_  100
#define NEG_SLOPE 0.2f

// padded row counts
#define UN_P  200064
#define M1_P  100096

#define NP_KV 208
#define NP_Q  112
#define KP_ND 176
#define KP_T  112
#define KP_OUT 288

// split-weight arena offsets (bf16 elements)
#define OFF_KVN_H 0
#define OFF_KVN_L (OFF_KVN_H + KP_ND * NP_KV)
#define OFF_KVE_H (OFF_KVN_L + KP_ND * NP_KV)
#define OFF_KVE_L (OFF_KVE_H + KP_ND * NP_KV)
#define OFF_KVT_H (OFF_KVE_L + KP_ND * NP_KV)
#define OFF_KVT_L (OFF_KVT_H + KP_T * NP_KV)
#define OFF_QN_H  (OFF_KVT_L + KP_T * NP_KV)
#define OFF_QN_L  (OFF_QN_H + KP_ND * NP_Q)
#define OFF_OUT_H (OFF_QN_L + KP_ND * NP_Q)
#define OFF_OUT_L (OFF_OUT_H + KP_OUT * NP_Q)
#define WSPLIT_TOTAL (OFF_OUT_L + KP_OUT * NP_Q)

// ---------------- scratch (device globals; no allocation) ----------------
__device__ float         g_Q   [M1_P * NP_Q];
__device__ float         g_KVN [UN_P * NP_KV];
__device__ float         g_KVE [M1_P * NP_KV];
__device__ float         g_KVT [M1_P * NP_KV];
__device__ float         g_acc [NDST * DO_];
__device__ float         g_biasq[DO_];
__device__ __nv_bfloat16 g_WS  [WSPLIT_TOTAL];
__device__ int           g_cnt [NDST];
__device__ int           g_off [NDST + 1];
__device__ int           g_cur [NDST];
__device__ int           g_bsum[128];
__device__ int           g_btop[128];
__device__ int4          g_pack[NE];

__global__ void biasq_kernel(const float* __restrict__ time_b,
                             const float* __restrict__ Wqt,
                             const float* __restrict__ bqt,
                             const float* __restrict__ bqn) {
    int j = threadIdx.x;
    if (j >= DO_) return;
    float acc = bqt[j] + bqn[j];
    for (int k = 0; k < DT_; k++) acc += cosf(time_b[k]) * Wqt[k * DO_ + j];
    g_biasq[j] = acc;
}

// ---------------- weight split: tile-major layout ----------------
// out[((k/16)*(NP/16) + n/16)*256 + (k%16)*16 + (n%16)]
// rows 0..K-1 = W, row K = bias sum, rest 0
__global__ void split_w(const float* __restrict__ W,
                        const float* __restrict__ b0, const float* __restrict__ b1,
                        const float* __restrict__ b2,
                        __nv_bfloat16* __restrict__ oh, __nv_bfloat16* __restrict__ ol,
                        int K, int N, int KP, int NP) {
    int idx = blockIdx.x * blockDim.x + threadIdx.x;
    if (idx >= KP * NP) return;
    int k = idx / NP, n = idx - k * NP;
    float val = 0.f;
    if (n < N) {
        if (k < K) val = W[(long)k * N + n];
        else if (k == K) {
            if (b0) val += b0[n];
            if (b1) val += b1[n];
            if (b2) val += b2[n];
        }
    }
    int off = (((k >> 4) * (NP >> 4) + (n >> 4)) << 8) + ((k & 15) << 4) + (n & 15);
    __nv_bfloat16 h = __float2bfloat16(val);
    oh[off] = h;
    ol[off] = __float2bfloat16(val - __bfloat162float(h));
}

// ---------------- CSR build ----------------
__global__ void hist_kernel(const int* __restrict__ dsti) {
    int idx = blockIdx.x * blockDim.x + threadIdx.x;
    int stride = gridDim.x * blockDim.x;
    for (int e = idx; e < NE; e += stride) atomicAdd(&g_cnt[dsti[e]], 1);
}

#define NB_SCAN ((NDST + 1023) / 1024)   // 98

__global__ __launch_bounds__(1024)
void scan1_kernel() {
    __shared__ int ss[1024];
    int t = threadIdx.x;
    int i = blockIdx.x * 1024 + t;
    int v = (i < NDST) ? g_cnt[i] : 0;
    ss[t] = v;
    __syncthreads();
    for (int off = 1; off < 1024; off <<= 1) {
        int u = (t >= off) ? ss[t - off] : 0;
        __syncthreads();
        ss[t] += u;
        __syncthreads();
    }
    if (i < NDST) g_off[i] = ss[t] - v;
    if (t == 1023) g_bsum[blockIdx.x] = ss[1023];
}

__global__ __launch_bounds__(128)
void scan2_kernel() {
    __shared__ int ss[128];
    int t = threadIdx.x;
    int v = (t < NB_SCAN) ? g_bsum[t] : 0;
    ss[t] = v;
    __syncthreads();
    for (int off = 1; off < 128; off <<= 1) {
        int u = (t >= off) ? ss[t - off] : 0;
        __syncthreads();
        ss[t] += u;
        __syncthreads();
    }
    g_btop[t] = ss[t] - v;
}

__global__ __launch_bounds__(1024)
void scan3_kernel() {
    int t = threadIdx.x;
    int i = blockIdx.x * 1024 + t;
    if (i < NDST) {
        int o = g_off[i] + g_btop[blockIdx.x];
        g_off[i] = o;
        g_cur[i] = o;
    }
    if (i == 0) g_off[NDST] = NE;
}

__global__ void scatter_kernel(const int* __restrict__ dsti,
                               const int* __restrict__ node_inv,
                               const int* __restrict__ eids,
                               const int* __restrict__ tids) {
    int idx = blockIdx.x * blockDim.x + threadIdx.x;
    int stride = gridDim.x * blockDim.x;
    for (int e = idx; e < NE; e += stride) {
        int pos = atomicAdd(&g_cur[dsti[e]], 1);
        g_pack[pos] = make_int4(node_inv[e], eids[e], tids[e], 0);
    }
}

// ---------------- bf16x2 GEMM v7: tile-major operands (A smem + B global), sync-free ----------------
// 256 threads (8 warps = 2M x 4Ngroups x 2 tiles), BM=64. A hi/lo staged tile-major across full K.
// TIMEF: A[row,k] = cos(utd[row]*tw[k]+tb[k]) computed inline (kvt path).
template <bool GATHER, bool TIMEF>
__global__ __launch_bounds__(256, 3)
void gemm_bf7(const float* __restrict__ A,
              const __nv_bfloat16* __restrict__ Wh, const __nv_bfloat16* __restrict__ Wl,
              float* __restrict__ C, const int* __restrict__ gidx,
              const float* __restrict__ utd, const float* __restrict__ tw,
              const float* __restrict__ tb,
              int M, int K, int KP, int NP) {
    extern __shared__ char smraw[];
    __nv_bfloat16* Ah = (__nv_bfloat16*)smraw;          // 64*KP tile-major
    __nv_bfloat16* Al = Ah + 64 * KP;
    int tid = threadIdx.x, wid = tid >> 5;
    int m0 = blockIdx.x * 64;
    int KT = KP >> 4;

    // stage A hi/lo tile-major: tile (r/16, k/16) at ((r>>4)*KT + (k>>4))*256 + (r&15)*16 + (k&15)
    int nc4 = KP >> 2;
    for (int idx = tid; idx < 64 * nc4; idx += 256) {
        int r = idx / nc4, c4 = idx - r * nc4;
        int row = m0 + r;
        int k = c4 * 4;
        float4 v = make_float4(0.f, 0.f, 0.f, 0.f);
        if (row < M) {
            if (TIMEF) {
                if (k + 3 < K) {
                    float4 w4 = *(const float4*)(tw + k);
                    float4 b4 = *(const float4*)(tb + k);
                    float td = utd[row];
                    v.x = cosf(td * w4.x + b4.x);
                    v.y = cosf(td * w4.y + b4.y);
                    v.z = cosf(td * w4.z + b4.z);
                    v.w = cosf(td * w4.w + b4.w);
                } else if (K >= k && K < k + 4) {
                    ((float*)&v)[K - k] = 1.0f;
                }
            } else {
                long ab = (long)(GATHER ? gidx[row] : row) * K;
                if (k + 3 < K) {
                    v = *(const float4*)(A + ab + k);
                } else {
                    if (k + 0 < K) v.x = A[ab + k + 0];
                    if (k + 1 < K) v.y = A[ab + k + 1];
                    if (k + 2 < K) v.z = A[ab + k + 2];
                    if (k + 3 < K) v.w = A[ab + k + 3];
                }
                if (K >= k && K < k + 4) ((float*)&v)[K - k] = 1.0f;
            }
        }
        int off = (((r >> 4) * KT + (k >> 4)) << 8) + ((r & 15) << 4) + (k & 15);
        __nv_bfloat16 h; float x;
        x = v.x; h = __float2bfloat16(x); Ah[off + 0] = h; Al[off + 0] = __float2bfloat16(x - __bfloat162float(h));
        x = v.y; h = __float2bfloat16(x); Ah[off + 1] = h; Al[off + 1] = __float2bfloat16(x - __bfloat162float(h));
        x = v.z; h = __float2bfloat16(x); Ah[off + 2] = h; Al[off + 2] = __float2bfloat16(x - __bfloat162float(h));
        x = v.w; h = __float2bfloat16(x); Ah[off + 3] = h; Al[off + 3] = __float2bfloat16(x - __bfloat162float(h));
    }
    __syncthreads();

    int wm = (wid >> 2) * 32;   // 0 or 32
    int wt = wid & 3;           // N-group 0..3
    int NT = NP >> 4;           // 13 (kv) or 7 (q)
    int mt0 = wm >> 4;          // A tile row index for wm, wm+16 -> mt0, mt0+1

    for (int pass = 0; pass < 2; pass++) {
        int ta = pass * 8 + wt * 2;
        if (ta >= NT) break;
        bool actB = (ta + 1) < NT;

        wmma::fragment<wmma::accumulator, 16, 16, 16, float> acc00, acc10, acc01, acc11;
        wmma::fill_fragment(acc00, 0.f);
        wmma::fill_fragment(acc10, 0.f);
        wmma::fill_fragment(acc01, 0.f);
        wmma::fill_fragment(acc11, 0.f);

        for (int kt = 0; kt < KT; kt++) {
            wmma::fragment<wmma::matrix_a, 16, 16, 16, __nv_bfloat16, wmma::row_major> ah0, ah1, al0, al1;
            wmma::load_matrix_sync(ah0, Ah + (((mt0 + 0) * KT + kt) << 8), 16);
            wmma::load_matrix_sync(al0, Al + (((mt0 + 0) * KT + kt) << 8), 16);
            wmma::load_matrix_sync(ah1, Ah + (((mt0 + 1) * KT + kt) << 8), 16);
            wmma::load_matrix_sync(al1, Al + (((mt0 + 1) * KT + kt) << 8), 16);

            wmma::fragment<wmma::matrix_b, 16, 16, 16, __nv_bfloat16, wmma::row_major> bh0, bl0, bh1, bl1;
            long bofs0 = ((long)kt * NT + ta) << 8;
            wmma::load_matrix_sync(bh0, Wh + bofs0, 16);
            wmma::load_matrix_sync(bl0, Wl + bofs0, 16);
            if (actB) {
                wmma::load_matrix_sync(bh1, Wh + bofs0 + 256, 16);
                wmma::load_matrix_sync(bl1, Wl + bofs0 + 256, 16);
            }

            wmma::mma_sync(acc00, al0, bh0, acc00);
            wmma::mma_sync(acc00, ah0, bl0, acc00);
            wmma::mma_sync(acc00, ah0, bh0, acc00);
            wmma::mma_sync(acc10, al1, bh0, acc10);
            wmma::mma_sync(acc10, ah1, bl0, acc10);
            wmma::mma_sync(acc10, ah1, bh0, acc10);
            if (actB) {
                wmma::mma_sync(acc01, al0, bh1, acc01);
                wmma::mma_sync(acc01, ah0, bl1, acc01);
                wmma::mma_sync(acc01, ah0, bh1, acc01);
                wmma::mma_sync(acc11, al1, bh1, acc11);
                wmma::mma_sync(acc11, ah1, bl1, acc11);
                wmma::mma_sync(acc11, ah1, bh1, acc11);
            }
        }
        wmma::store_matrix_sync(C + (long)(m0 + wm +  0) * NP + ta * 16, acc00, NP, wmma::mem_row_major);
        wmma::store_matrix_sync(C + (long)(m0 + wm + 16) * NP + ta * 16, acc10, NP, wmma::mem_row_major);
        if (actB) {
            wmma::store_matrix_sync(C + (long)(m0 + wm +  0) * NP + (ta + 1) * 16, acc01, NP, wmma::mem_row_major);
            wmma::store_matrix_sync(C + (long)(m0 + wm + 16) * NP + (ta + 1) * 16, acc11, NP, wmma::mem_row_major);
        }
    }
}

// ---------------- attention: one warp per dst, online softmax, 2-edge pipeline ----------------
__device__ __forceinline__ void load_edge(int4 p, int lane, bool act,
                                          float4& k1, float4& k2, float4& k3,
                                          float4& v1, float4& v2, float4& v3) {
    if (act) {
        const float4* kn = (const float4*)(g_KVN + (long)p.x * NP_KV);
        const float4* ke = (const float4*)(g_KVE + (long)p.y * NP_KV);
        const float4* kt = (const float4*)(g_KVT + (long)p.z * NP_KV);
        k1 = kn[lane];      k2 = ke[lane];      k3 = kt[lane];
        v1 = kn[25 + lane]; v2 = ke[25 + lane]; v3 = kt[25 + lane];
    }
}

__global__ __launch_bounds__(256)
void attn_kernel() {
    int w = (int)((blockIdx.x * (long)blockDim.x + threadIdx.x) >> 5);
    int lane = threadIdx.x & 31;
    if (w >= NDST) return;
    int beg = g_off[w], end = g_off[w + 1];

    bool act = lane < 25;
    int base = lane * 4;
    bool h0 = base + 0 < 50, h1 = base + 1 < 50, h2 = base + 2 < 50, h3 = base + 3 < 50;

    float4 q = make_float4(0.f, 0.f, 0.f, 0.f);
    if (act) q = ((const float4*)(g_Q + (long)w * NP_Q))[lane];

    float4 acc = make_float4(0.f, 0.f, 0.f, 0.f);
    float m0 = -1e30f, m1 = -1e30f, s0 = 0.f, s1 = 0.f;
    float4 z4 = make_float4(0.f, 0.f, 0.f, 0.f);

    int j = beg;
    for (; j + 1 < end; j += 2) {
        int4 pA = g_pack[j];
        int4 pB = g_pack[j + 1];
        float4 ka1 = z4, ka2 = z4, ka3 = z4, va1 = z4, va2 = z4, va3 = z4;
        float4 kb1 = z4, kb2 = z4, kb3 = z4, vb1 = z4, vb2 = z4, vb3 = z4;
        load_edge(pA, lane, act, ka1, ka2, ka3, va1, va2, va3);
        load_edge(pB, lane, act, kb1, kb2, kb3, vb1, vb2, vb3);

        float t0a = 0.f, t1a = 0.f, t0b = 0.f, t1b = 0.f;
        float4 vA = z4, vB = z4;
        if (act) {
            float ax = q.x * (ka1.x + ka2.x + ka3.x);
            float ay = q.y * (ka1.y + ka2.y + ka3.y);
            float az = q.z * (ka1.z + ka2.z + ka3.z);
            float aw = q.w * (ka1.w + ka2.w + ka3.w);
            t0a = (h0 ? ax : 0.f) + (h1 ? ay : 0.f) + (h2 ? az : 0.f) + (h3 ? aw : 0.f);
            t1a = (h0 ? 0.f : ax) + (h1 ? 0.f : ay) + (h2 ? 0.f : az) + (h3 ? 0.f : aw);
            float bx = q.x * (kb1.x + kb2.x + kb3.x);
            float by = q.y * (kb1.y + kb2.y + kb3.y);
            float bz = q.z * (kb1.z + kb2.z + kb3.z);
            float bw = q.w * (kb1.w + kb2.w + kb3.w);
            t0b = (h0 ? bx : 0.f) + (h1 ? by : 0.f) + (h2 ? bz : 0.f) + (h3 ? bw : 0.f);
            t1b = (h0 ? 0.f : bx) + (h1 ? 0.f : by) + (h2 ? 0.f : bz) + (h3 ? 0.f : bw);
            vA.x = va1.x + va2.x + va3.x; vA.y = va1.y + va2.y + va3.y;
            vA.z = va1.z + va2.z + va3.z; vA.w = va1.w + va2.w + va3.w;
            vB.x = vb1.x + vb2.x + vb3.x; vB.y = vb1.y + vb2.y + vb3.y;
            vB.z = vb1.z + vb2.z + vb3.z; vB.w = vb1.w + vb2.w + vb3.w;
        }
#pragma unroll
        for (int off = 16; off; off >>= 1) {
            t0a += __shfl_xor_sync(0xffffffffu, t0a, off);
            t1a += __shfl_xor_sync(0xffffffffu, t1a, off);
            t0b += __shfl_xor_sync(0xffffffffu, t0b, off);
            t1b += __shfl_xor_sync(0xffffffffu, t1b, off);
        }
        {
            float a0 = t0a > 0.f ? t0a : NEG_SLOPE * t0a;
            float a1 = t1a > 0.f ? t1a : NEG_SLOPE * t1a;
            float nm0 = fmaxf(m0, a0);
            float c0 = __expf(m0 - nm0), w0 = __expf(a0 - nm0);
            s0 = s0 * c0 + w0; m0 = nm0;
            float nm1 = fmaxf(m1, a1);
            float c1 = __expf(m1 - nm1), w1 = __expf(a1 - nm1);
            s1 = s1 * c1 + w1; m1 = nm1;
            acc.x = acc.x * (h0 ? c0 : c1) + (h0 ? w0 : w1) * vA.x;
            acc.y = acc.y * (h1 ? c0 : c1) + (h1 ? w0 : w1) * vA.y;
            acc.z = acc.z * (h2 ? c0 : c1) + (h2 ? w0 : w1) * vA.z;
            acc.w = acc.w * (h3 ? c0 : c1) + (h3 ? w0 : w1) * vA.w;
        }
        {
            float a0 = t0b > 0.f ? t0b : NEG_SLOPE * t0b;
            float a1 = t1b > 0.f ? t1b : NEG_SLOPE * t1b;
            float nm0 = fmaxf(m0, a0);
            float c0 = __expf(m0 - nm0), w0 = __expf(a0 - nm0);
            s0 = s0 * c0 + w0; m0 = nm0;
            float nm1 = fmaxf(m1, a1);
            float c1 = __expf(m1 - nm1), w1 = __expf(a1 - nm1);
            s1 = s1 * c1 + w1; m1 = nm1;
            acc.x = acc.x * (h0 ? c0 : c1) + (h0 ? w0 : w1) * vB.x;
            acc.y = acc.y * (h1 ? c0 : c1) + (h1 ? w0 : w1) * vB.y;
            acc.z = acc.z * (h2 ? c0 : c1) + (h2 ? w0 : w1) * vB.z;
            acc.w = acc.w * (h3 ? c0 : c1) + (h3 ? w0 : w1) * vB.w;
        }
    }
    if (j < end) {
        int4 p = g_pack[j];
        float4 k1 = z4, k2 = z4, k3 = z4, v1 = z4, v2 = z4, v3 = z4;
        load_edge(p, lane, act, k1, k2, k3, v1, v2, v3);
        float t0 = 0.f, t1 = 0.f;
        float4 vS = z4;
        if (act) {
            float px = q.x * (k1.x + k2.x + k3.x);
            float py = q.y * (k1.y + k2.y + k3.y);
            float pz = q.z * (k1.z + k2.z + k3.z);
            float pw = q.w * (k1.w + k2.w + k3.w);
            t0 = (h0 ? px : 0.f) + (h1 ? py : 0.f) + (h2 ? pz : 0.f) + (h3 ? pw : 0.f);
            t1 = (h0 ? 0.f : px) + (h1 ? 0.f : py) + (h2 ? 0.f : pz) + (h3 ? 0.f : pw);
            vS.x = v1.x + v2.x + v3.x; vS.y = v1.y + v2.y + v3.y;
            vS.z = v1.z + v2.z + v3.z; vS.w = v1.w + v2.w + v3.w;
        }
#pragma unroll
        for (int off = 16; off; off >>= 1) {
            t0 += __shfl_xor_sync(0xffffffffu, t0, off);
            t1 += __shfl_xor_sync(0xffffffffu, t1, off);
        }
        float a0 = t0 > 0.f ? t0 : NEG_SLOPE * t0;
        float a1 = t1 > 0.f ? t1 : NEG_SLOPE * t1;
        float nm0 = fmaxf(m0, a0);
        float c0 = __expf(m0 - nm0), w0 = __expf(a0 - nm0);
        s0 = s0 * c0 + w0; m0 = nm0;
        float nm1 = fmaxf(m1, a1);
        float c1 = __expf(m1 - nm1), w1 = __expf(a1 - nm1);
        s1 = s1 * c1 + w1; m1 = nm1;
        acc.x = acc.x * (h0 ? c0 : c1) + (h0 ? w0 : w1) * vS.x;
        acc.y = acc.y * (h1 ? c0 : c1) + (h1 ? w0 : w1) * vS.y;
        acc.z = acc.z * (h2 ? c0 : c1) + (h2 ? w0 : w1) * vS.z;
        acc.w = acc.w * (h3 ? c0 : c1) + (h3 ? w0 : w1) * vS.w;
    }

    if (act) {
        float r0 = s0 > 0.f ? 1.f / s0 : 0.f;
        float r1 = s1 > 0.f ? 1.f / s1 : 0.f;
        float4 o;
        o.x = acc.x * (h0 ? r0 : r1);
        o.y = acc.y * (h1 ? r0 : r1);
        o.z = acc.z * (h2 ? r0 : r1);
        o.w = acc.w * (h3 ? r0 : r1);
        ((float4*)(g_acc + (long)w * DO_))[lane] = o;
    }
}

// ---------------- finalize: bf16x2 concat-GEMM (tile-major) + relu + LayerNorm ----------------
#define FIN_KT (KP_OUT / 16)     // 18
#define FIN_NT (NP_Q / 16)       // 7
#define FIN_SMEM (64 * KP_OUT * 2 * 2)   // Ah+Al bf16 = 73728 B
#define FIN_LDC 116
__global__ __launch_bounds__(256)
void finalize_bf(const float* __restrict__ nodeData,
                 const int* __restrict__ rev_nids,
                 const __nv_bfloat16* __restrict__ Wh, const __nv_bfloat16* __restrict__ Wl,
                 const float* __restrict__ ln_g, const float* __restrict__ ln_b,
                 float* __restrict__ out) {
    extern __shared__ char smraw[];
    __nv_bfloat16* Ah = (__nv_bfloat16*)smraw;       // 64*288 tile-major
    __nv_bfloat16* Al = Ah + 64 * KP_OUT;
    float* Cs = (float*)smraw;                        // reused after mainloop (64 x FIN_LDC)
    int tid = threadIdx.x, wid = tid >> 5, lane = tid & 31;
    int m0 = blockIdx.x * 64;

    for (int idx = tid; idx < 64 * 72; idx += 256) {
        int r = idx / 72, c4 = idx - r * 72;
        int row = m0 + r;
        int k = c4 * 4;
        float4 v = make_float4(0.f, 0.f, 0.f, 0.f);
        if (row < NDST) {
            if (c4 < 25) {
                v = *(const float4*)(g_acc + (long)row * DO_ + k);
            } else if (c4 < 68) {
                long nb = (long)rev_nids[row] * DN_;
                v = *(const float4*)(nodeData + nb + (k - 100));
            } else if (c4 == 68) {
                v.x = 1.0f;
            }
        }
        int off = (((r >> 4) * FIN_KT + (k >> 4)) << 8) + ((r & 15) << 4) + (k & 15);
        __nv_bfloat16 h; float x;
        x = v.x; h = __float2bfloat16(x); Ah[off + 0] = h; Al[off + 0] = __float2bfloat16(x - __bfloat162float(h));
        x = v.y; h = __float2bfloat16(x); Ah[off + 1] = h; Al[off + 1] = __float2bfloat16(x - __bfloat162float(h));
        x = v.z; h = __float2bfloat16(x); Ah[off + 2] = h; Al[off + 2] = __float2bfloat16(x - __bfloat162float(h));
        x = v.w; h = __float2bfloat16(x); Ah[off + 3] = h; Al[off + 3] = __float2bfloat16(x - __bfloat162float(h));
    }
    __syncthreads();

    int wm = (wid >> 2) * 32;
    int wn = (wid & 3) * 16;
    int mt0 = wm >> 4;
    int nt0 = wn >> 4;

    wmma::fragment<wmma::accumulator, 16, 16, 16, float> acc[2][2];
    bool act1 = (4 + nt0) < FIN_NT;     // second N tile (cols 64+wn)
#pragma unroll
    for (int a = 0; a < 2; a++)
#pragma unroll
        for (int i = 0; i < 2; i++) wmma::fill_fragment(acc[a][i], 0.f);

    for (int kt = 0; kt < FIN_KT; kt++) {
        wmma::fragment<wmma::matrix_a, 16, 16, 16, __nv_bfloat16, wmma::row_major> ah0, ah1, al0, al1;
        wmma::load_matrix_sync(ah0, Ah + (((mt0 + 0) * FIN_KT + kt) << 8), 16);
        wmma::load_matrix_sync(ah1, Ah + (((mt0 + 1) * FIN_KT + kt) << 8), 16);
        wmma::load_matrix_sync(al0, Al + (((mt0 + 0) * FIN_KT + kt) << 8), 16);
        wmma::load_matrix_sync(al1, Al + (((mt0 + 1) * FIN_KT + kt) << 8), 16);
        {
            wmma::fragment<wmma::matrix_b, 16, 16, 16, __nv_bfloat16, wmma::row_major> bh, bl;
            long bo = ((long)kt * FIN_NT + nt0) << 8;
            wmma::load_matrix_sync(bh, Wh + bo, 16);
            wmma::load_matrix_sync(bl, Wl + bo, 16);
            wmma::mma_sync(acc[0][0], al0, bh, acc[0][0]);
            wmma::mma_sync(acc[0][0], ah0, bl, acc[0][0]);
            wmma::mma_sync(acc[0][0], ah0, bh, acc[0][0]);
            wmma::mma_sync(acc[0][1], al1, bh, acc[0][1]);
            wmma::mma_sync(acc[0][1], ah1, bl, acc[0][1]);
            wmma::mma_sync(acc[0][1], ah1, bh, acc[0][1]);
        }
        if (act1) {
            wmma::fragment<wmma::matrix_b, 16, 16, 16, __nv_bfloat16, wmma::row_major> bh, bl;
            long bo = ((long)kt * FIN_NT + 4 + nt0) << 8;
            wmma::load_matrix_sync(bh, Wh + bo, 16);
            wmma::load_matrix_sync(bl, Wl + bo, 16);
            wmma::mma_sync(acc[1][0], al0, bh, acc[1][0]);
            wmma::mma_sync(acc[1][0], ah0, bl, acc[1][0]);
            wmma::mma_sync(acc[1][0], ah0, bh, acc[1][0]);
            wmma::mma_sync(acc[1][1], al1, bh, acc[1][1]);
            wmma::mma_sync(acc[1][1], ah1, bl, acc[1][1]);
            wmma::mma_sync(acc[1][1], ah1, bh, acc[1][1]);
        }
    }
    __syncthreads();

#pragma unroll
    for (int i = 0; i < 2; i++) {
        wmma::store_matrix_sync(Cs + (wm + i * 16) * FIN_LDC + wn, acc[0][i], FIN_LDC, wmma::mem_row_major);
        if (act1)
            wmma::store_matrix_sync(Cs + (wm + i * 16) * FIN_LDC + 64 + wn, acc[1][i], FIN_LDC, wmma::mem_row_major);
    }
    __syncthreads();

    float g0 = ln_g[lane], g1 = ln_g[lane + 32], g2 = ln_g[lane + 64];
    float g3 = lane < 4 ? ln_g[96 + lane] : 0.f;
    float be0 = ln_b[lane], be1 = ln_b[lane + 32], be2 = ln_b[lane + 64];
    float be3 = lane < 4 ? ln_b[96 + lane] : 0.f;

    for (int r = wid * 8; r < wid * 8 + 8; r++) {
        int row = m0 + r;
        if (row >= NDST) continue;
        float* cr = Cs + r * FIN_LDC;
        float x0 = cr[lane];        x0 = x0 > 0.f ? x0 : 0.f;
        float x1 = cr[lane + 32];   x1 = x1 > 0.f ? x1 : 0.f;
        float x2 = cr[lane + 64];   x2 = x2 > 0.f ? x2 : 0.f;
        float x3 = lane < 4 ? cr[96 + lane] : 0.f;  x3 = x3 > 0.f ? x3 : 0.f;
        float s = x0 + x1 + x2 + x3;
        float sq = x0 * x0 + x1 * x1 + x2 * x2 + x3 * x3;
#pragma unroll
        for (int off = 16; off; off >>= 1) {
            s  += __shfl_xor_sync(0xffffffffu, s, off);
            sq += __shfl_xor_sync(0xffffffffu, sq, off);
        }
        float mu = s * 0.01f;
        float var = sq * 0.01f - mu * mu;
        float inv = rsqrtf(var + 1e-5f);
        float* orow = out + (long)row * DO_;
        orow[lane]      = (x0 - mu) * inv * g0 + be0;
        orow[lane + 32] = (x1 - mu) * inv * g1 + be1;
        orow[lane + 64] = (x2 - mu) * inv * g2 + be2;
        if (lane < 4) orow[96 + lane] = (x3 - mu) * inv * g3 + be3;
    }
}

// ---------------- launch ----------------
extern "C" void kernel_launch(void* const* d_in, const int* in_sizes, int n_in,
                              void* d_out, int out_size) {
    const float* nodeData = (const float*)d_in[0];
    const float* efeat    = (const float*)d_in[1];
    const float* utd      = (const float*)d_in[2];
    const int*   rev_nids = (const int*)d_in[3];
    const int*   rev_eids = (const int*)d_in[4];
    const int*   rev_tids = (const int*)d_in[5];
    const int*   dstindex = (const int*)d_in[6];
    const float* time_w   = (const float*)d_in[8];
    const float* time_b   = (const float*)d_in[9];
    const float* Wqn      = (const float*)d_in[10];
    const float* bqn      = (const float*)d_in[11];
    const float* Wqt      = (const float*)d_in[12];
    const float* bqt      = (const float*)d_in[13];
    const float* Wkvn     = (const float*)d_in[14];
    const float* bkvn     = (const float*)d_in[15];
    const float* Wkve     = (const float*)d_in[16];
    const float* bkve     = (const float*)d_in[17];
    const float* Wkvt     = (const float*)d_in[18];
    const float* bkvt     = (const float*)d_in[19];
    const float* Wout     = (const float*)d_in[20];
    const float* bout     = (const float*)d_in[21];
    const float* ln_g     = (const float*)d_in[22];
    const float* ln_b     = (const float*)d_in[23];
    float* out = (float*)d_out;

    float *pQ, *pKVN, *pKVE, *pKVT, *pbiasq;
    __nv_bfloat16* pWS;
    int* pCnt;
    cudaGetSymbolAddress((void**)&pQ,     g_Q);
    cudaGetSymbolAddress((void**)&pKVN,   g_KVN);
    cudaGetSymbolAddress((void**)&pKVE,   g_KVE);
    cudaGetSymbolAddress((void**)&pKVT,   g_KVT);
    cudaGetSymbolAddress((void**)&pbiasq, g_biasq);
    cudaGetSymbolAddress((void**)&pWS,    g_WS);
    cudaGetSymbolAddress((void**)&pCnt,   g_cnt);

    const int* node_inv = rev_nids + NDST;

    const int sm_nd = 64 * KP_ND * 2 * 2;   // 45056
    const int sm_t  = 64 * KP_T  * 2 * 2;   // 28672
    cudaFuncSetAttribute((const void*)gemm_bf7<true,  false>, cudaFuncAttributeMaxDynamicSharedMemorySize, sm_nd);
    cudaFuncSetAttribute((const void*)gemm_bf7<false, false>, cudaFuncAttributeMaxDynamicSharedMemorySize, sm_nd);
    cudaFuncSetAttribute((const void*)gemm_bf7<false, true >, cudaFuncAttributeMaxDynamicSharedMemorySize, sm_nd);
    cudaFuncSetAttribute((const void*)finalize_bf, cudaFuncAttributeMaxDynamicSharedMemorySize, FIN_SMEM);

    cudaMemsetAsync(pCnt, 0, NDST * sizeof(int));

    // kernel launches: 1 hist, 2 split_w(kvn), 3 scan1, 4 gemm_kvn (profiled)
    hist_kernel<<<2048, 256>>>(dstindex);
    split_w<<<(KP_ND * NP_KV + 255) / 256, 256>>>(Wkvn, bkvn, bkve, bkvt,
        pWS + OFF_KVN_H, pWS + OFF_KVN_L, DN_, 2 * DO_, KP_ND, NP_KV);
    scan1_kernel<<<NB_SCAN, 1024>>>();

    gemm_bf7<false, false><<<UN / 64, 256, sm_nd>>>(
        nodeData, pWS + OFF_KVN_H, pWS + OFF_KVN_L, pKVN, nullptr,
        nullptr, nullptr, nullptr, UN, DN_, KP_ND, NP_KV);

    scan2_kernel<<<1, 128>>>();
    scan3_kernel<<<NB_SCAN, 1024>>>();
    scatter_kernel<<<2048, 256>>>(dstindex, node_inv, rev_eids, rev_tids);
    biasq_kernel<<<1, 128>>>(time_b, Wqt, bqt, bqn);

    split_w<<<(KP_ND * NP_Q + 255) / 256, 256>>>(Wqn, pbiasq, nullptr, nullptr,
        pWS + OFF_QN_H, pWS + OFF_QN_L, DN_, DO_, KP_ND, NP_Q);
    split_w<<<(KP_ND * NP_KV + 255) / 256, 256>>>(Wkve, nullptr, nullptr, nullptr,
        pWS + OFF_KVE_H, pWS + OFF_KVE_L, DN_, 2 * DO_, KP_ND, NP_KV);
    split_w<<<(KP_T * NP_KV + 255) / 256, 256>>>(Wkvt, nullptr, nullptr, nullptr,
        pWS + OFF_KVT_H, pWS + OFF_KVT_L, DT_, 2 * DO_, KP_T, NP_KV);
    split_w<<<(KP_OUT * NP_Q + 255) / 256, 256>>>(Wout, bout, nullptr, nullptr,
        pWS + OFF_OUT_H, pWS + OFF_OUT_L, DN_ + DO_, DO_, KP_OUT, NP_Q);

    gemm_bf7<true, false><<<(NDST + 63) / 64, 256, sm_nd>>>(
        nodeData, pWS + OFF_QN_H, pWS + OFF_QN_L, pQ, rev_nids,
        nullptr, nullptr, nullptr, NDST, DN_, KP_ND, NP_Q);
    gemm_bf7<false, false><<<(UE + 63) / 64, 256, sm_nd>>>(
        efeat, pWS + OFF_KVE_H, pWS + OFF_KVE_L, pKVE, nullptr,
        nullptr, nullptr, nullptr, UE, DN_, KP_ND, NP_KV);
    gemm_bf7<false, true><<<(UT + 63) / 64, 256, sm_t>>>(
        nullptr, pWS + OFF_KVT_H, pWS + OFF_KVT_L, pKVT, nullptr,
        utd, time_w, time_b, UT, DT_, KP_T, NP_KV);

    attn_kernel<<<(NDST + 7) / 8, 256>>>();

    finalize_bf<<<(NDST + 63) / 64, 256, FIN_SMEM>>>(
        nodeData, rev_nids, pWS + OFF_OUT_H, pWS + OFF_OUT_L, ln_g, ln_b, out);
}

// round 16
// speedup vs baseline: 1.3407x; 1.0660x over previous
#include <cuda_runtime.h>
#include <cuda_bf16.h>
#include <mma.h>
using namespace nvcuda;

#define NDST 100000
#define NE   1000000
#define UN   200000
#define UE   100000
#define UT   100000
#define DN_  172
#define DT_  100
#define DO_  100
#define NEG_SLOPE 0.2f

// padded row counts
#define UN_P  200064
#define M1_P  100096

#define NP_KV 208
#define NP_Q  112
#define KP_ND 176
#define KP_T  112
#define KP_OUT 288

// split-weight arena offsets (bf16 elements)
#define OFF_KVN_H 0
#define OFF_KVN_L (OFF_KVN_H + KP_ND * NP_KV)
#define OFF_KVE_H (OFF_KVN_L + KP_ND * NP_KV)
#define OFF_KVE_L (OFF_KVE_H + KP_ND * NP_KV)
#define OFF_KVT_H (OFF_KVE_L + KP_ND * NP_KV)
#define OFF_KVT_L (OFF_KVT_H + KP_T * NP_KV)
#define OFF_QN_H  (OFF_KVT_L + KP_T * NP_KV)
#define OFF_QN_L  (OFF_QN_H + KP_ND * NP_Q)
#define OFF_OUT_H (OFF_QN_L + KP_ND * NP_Q)
#define OFF_OUT_L (OFF_OUT_H + KP_OUT * NP_Q)
#define WSPLIT_TOTAL (OFF_OUT_L + KP_OUT * NP_Q)

// ---------------- scratch (device globals; no allocation) ----------------
__device__ float         g_Q   [M1_P * NP_Q];
__device__ float         g_KVN [UN_P * NP_KV];
__device__ float         g_KVE [M1_P * NP_KV];
__device__ float         g_KVT [M1_P * NP_KV];
__device__ float         g_acc [NDST * DO_];
__device__ float         g_biasq[DO_];
__device__ __nv_bfloat16 g_WS  [WSPLIT_TOTAL];
__device__ int           g_cnt [NDST];
__device__ int           g_off [NDST + 1];
__device__ int           g_cur [NDST];
__device__ int           g_bsum[128];
__device__ int           g_btop[128];
__device__ int4          g_pack[NE];

__global__ void biasq_kernel(const float* __restrict__ time_b,
                             const float* __restrict__ Wqt,
                             const float* __restrict__ bqt,
                             const float* __restrict__ bqn) {
    int j = threadIdx.x;
    if (j >= DO_) return;
    float acc = bqt[j] + bqn[j];
    for (int k = 0; k < DT_; k++) acc += cosf(time_b[k]) * Wqt[k * DO_ + j];
    g_biasq[j] = acc;
}

// ---------------- weight split: tile-major layout ----------------
__global__ void split_w(const float* __restrict__ W,
                        const float* __restrict__ b0, const float* __restrict__ b1,
                        const float* __restrict__ b2,
                        __nv_bfloat16* __restrict__ oh, __nv_bfloat16* __restrict__ ol,
                        int K, int N, int KP, int NP) {
    int idx = blockIdx.x * blockDim.x + threadIdx.x;
    if (idx >= KP * NP) return;
    int k = idx / NP, n = idx - k * NP;
    float val = 0.f;
    if (n < N) {
        if (k < K) val = W[(long)k * N + n];
        else if (k == K) {
            if (b0) val += b0[n];
            if (b1) val += b1[n];
            if (b2) val += b2[n];
        }
    }
    int off = (((k >> 4) * (NP >> 4) + (n >> 4)) << 8) + ((k & 15) << 4) + (n & 15);
    __nv_bfloat16 h = __float2bfloat16(val);
    oh[off] = h;
    ol[off] = __float2bfloat16(val - __bfloat162float(h));
}

// ---------------- CSR build ----------------
__global__ void hist_kernel(const int* __restrict__ dsti) {
    int idx = blockIdx.x * blockDim.x + threadIdx.x;
    int stride = gridDim.x * blockDim.x;
    for (int e = idx; e < NE; e += stride) atomicAdd(&g_cnt[dsti[e]], 1);
}

#define NB_SCAN ((NDST + 1023) / 1024)   // 98

__global__ __launch_bounds__(1024)
void scan1_kernel() {
    __shared__ int ss[1024];
    int t = threadIdx.x;
    int i = blockIdx.x * 1024 + t;
    int v = (i < NDST) ? g_cnt[i] : 0;
    ss[t] = v;
    __syncthreads();
    for (int off = 1; off < 1024; off <<= 1) {
        int u = (t >= off) ? ss[t - off] : 0;
        __syncthreads();
        ss[t] += u;
        __syncthreads();
    }
    if (i < NDST) g_off[i] = ss[t] - v;
    if (t == 1023) g_bsum[blockIdx.x] = ss[1023];
}

__global__ __launch_bounds__(128)
void scan2_kernel() {
    __shared__ int ss[128];
    int t = threadIdx.x;
    int v = (t < NB_SCAN) ? g_bsum[t] : 0;
    ss[t] = v;
    __syncthreads();
    for (int off = 1; off < 128; off <<= 1) {
        int u = (t >= off) ? ss[t - off] : 0;
        __syncthreads();
        ss[t] += u;
        __syncthreads();
    }
    g_btop[t] = ss[t] - v;
}

__global__ __launch_bounds__(1024)
void scan3_kernel() {
    int t = threadIdx.x;
    int i = blockIdx.x * 1024 + t;
    if (i < NDST) {
        int o = g_off[i] + g_btop[blockIdx.x];
        g_off[i] = o;
        g_cur[i] = o;
    }
    if (i == 0) g_off[NDST] = NE;
}

__global__ void scatter_kernel(const int* __restrict__ dsti,
                               const int* __restrict__ node_inv,
                               const int* __restrict__ eids,
                               const int* __restrict__ tids) {
    int idx = blockIdx.x * blockDim.x + threadIdx.x;
    int stride = gridDim.x * blockDim.x;
    for (int e = idx; e < NE; e += stride) {
        int pos = atomicAdd(&g_cur[dsti[e]], 1);
        g_pack[pos] = make_int4(node_inv[e], eids[e], tids[e], 0);
    }
}

// ---------------- bf16x2 GEMM v9: tile-major, 4M x 1N per warp (halved global B loads) ----------------
// 256 threads (8 warps); warp wid owns N-tile pass*8+wid, all 4 M-tiles. BM=64.
// TIMEF: A[row,k] = cos(utd[row]*tw[k]+tb[k]) computed inline (kvt path).
template <bool GATHER, bool TIMEF>
__global__ __launch_bounds__(256, 3)
void gemm_bf9(const float* __restrict__ A,
              const __nv_bfloat16* __restrict__ Wh, const __nv_bfloat16* __restrict__ Wl,
              float* __restrict__ C, const int* __restrict__ gidx,
              const float* __restrict__ utd, const float* __restrict__ tw,
              const float* __restrict__ tb,
              int M, int K, int KP, int NP) {
    extern __shared__ char smraw[];
    __nv_bfloat16* Ah = (__nv_bfloat16*)smraw;          // 64*KP tile-major
    __nv_bfloat16* Al = Ah + 64 * KP;
    int tid = threadIdx.x, wid = tid >> 5;
    int m0 = blockIdx.x * 64;
    int KT = KP >> 4;

    // stage A hi/lo tile-major: tile (r/16, k/16) at ((r>>4)*KT + (k>>4))*256 + (r&15)*16 + (k&15)
    int nc4 = KP >> 2;
    for (int idx = tid; idx < 64 * nc4; idx += 256) {
        int r = idx / nc4, c4 = idx - r * nc4;
        int row = m0 + r;
        int k = c4 * 4;
        float4 v = make_float4(0.f, 0.f, 0.f, 0.f);
        if (row < M) {
            if (TIMEF) {
                if (k + 3 < K) {
                    float4 w4 = *(const float4*)(tw + k);
                    float4 b4 = *(const float4*)(tb + k);
                    float td = utd[row];
                    v.x = cosf(td * w4.x + b4.x);
                    v.y = cosf(td * w4.y + b4.y);
                    v.z = cosf(td * w4.z + b4.z);
                    v.w = cosf(td * w4.w + b4.w);
                } else if (K >= k && K < k + 4) {
                    ((float*)&v)[K - k] = 1.0f;
                }
            } else {
                long ab = (long)(GATHER ? gidx[row] : row) * K;
                if (k + 3 < K) {
                    v = *(const float4*)(A + ab + k);
                } else {
                    if (k + 0 < K) v.x = A[ab + k + 0];
                    if (k + 1 < K) v.y = A[ab + k + 1];
                    if (k + 2 < K) v.z = A[ab + k + 2];
                    if (k + 3 < K) v.w = A[ab + k + 3];
                }
                if (K >= k && K < k + 4) ((float*)&v)[K - k] = 1.0f;
            }
        }
        int off = (((r >> 4) * KT + (k >> 4)) << 8) + ((r & 15) << 4) + (k & 15);
        __nv_bfloat16 h; float x;
        x = v.x; h = __float2bfloat16(x); Ah[off + 0] = h; Al[off + 0] = __float2bfloat16(x - __bfloat162float(h));
        x = v.y; h = __float2bfloat16(x); Ah[off + 1] = h; Al[off + 1] = __float2bfloat16(x - __bfloat162float(h));
        x = v.z; h = __float2bfloat16(x); Ah[off + 2] = h; Al[off + 2] = __float2bfloat16(x - __bfloat162float(h));
        x = v.w; h = __float2bfloat16(x); Ah[off + 3] = h; Al[off + 3] = __float2bfloat16(x - __bfloat162float(h));
    }
    __syncthreads();

    int NT = NP >> 4;           // 13 (kv) or 7 (q)

    for (int pass = 0; pass < 2; pass++) {
        int ta = pass * 8 + wid;         // this warp's N tile
        if (ta >= NT) continue;

        wmma::fragment<wmma::accumulator, 16, 16, 16, float> acc0, acc1, acc2, acc3;
        wmma::fill_fragment(acc0, 0.f);
        wmma::fill_fragment(acc1, 0.f);
        wmma::fill_fragment(acc2, 0.f);
        wmma::fill_fragment(acc3, 0.f);

        for (int kt = 0; kt < KT; kt++) {
            wmma::fragment<wmma::matrix_b, 16, 16, 16, __nv_bfloat16, wmma::row_major> bh, bl;
            long bo = ((long)kt * NT + ta) << 8;
            wmma::load_matrix_sync(bh, Wh + bo, 16);
            wmma::load_matrix_sync(bl, Wl + bo, 16);

            {
                wmma::fragment<wmma::matrix_a, 16, 16, 16, __nv_bfloat16, wmma::row_major> ah, al;
                wmma::load_matrix_sync(ah, Ah + ((0 * KT + kt) << 8), 16);
                wmma::load_matrix_sync(al, Al + ((0 * KT + kt) << 8), 16);
                wmma::mma_sync(acc0, al, bh, acc0);
                wmma::mma_sync(acc0, ah, bl, acc0);
                wmma::mma_sync(acc0, ah, bh, acc0);
            }
            {
                wmma::fragment<wmma::matrix_a, 16, 16, 16, __nv_bfloat16, wmma::row_major> ah, al;
                wmma::load_matrix_sync(ah, Ah + ((1 * KT + kt) << 8), 16);
                wmma::load_matrix_sync(al, Al + ((1 * KT + kt) << 8), 16);
                wmma::mma_sync(acc1, al, bh, acc1);
                wmma::mma_sync(acc1, ah, bl, acc1);
                wmma::mma_sync(acc1, ah, bh, acc1);
            }
            {
                wmma::fragment<wmma::matrix_a, 16, 16, 16, __nv_bfloat16, wmma::row_major> ah, al;
                wmma::load_matrix_sync(ah, Ah + ((2 * KT + kt) << 8), 16);
                wmma::load_matrix_sync(al, Al + ((2 * KT + kt) << 8), 16);
                wmma::mma_sync(acc2, al, bh, acc2);
                wmma::mma_sync(acc2, ah, bl, acc2);
                wmma::mma_sync(acc2, ah, bh, acc2);
            }
            {
                wmma::fragment<wmma::matrix_a, 16, 16, 16, __nv_bfloat16, wmma::row_major> ah, al;
                wmma::load_matrix_sync(ah, Ah + ((3 * KT + kt) << 8), 16);
                wmma::load_matrix_sync(al, Al + ((3 * KT + kt) << 8), 16);
                wmma::mma_sync(acc3, al, bh, acc3);
                wmma::mma_sync(acc3, ah, bl, acc3);
                wmma::mma_sync(acc3, ah, bh, acc3);
            }
        }
        wmma::store_matrix_sync(C + (long)(m0 +  0) * NP + ta * 16, acc0, NP, wmma::mem_row_major);
        wmma::store_matrix_sync(C + (long)(m0 + 16) * NP + ta * 16, acc1, NP, wmma::mem_row_major);
        wmma::store_matrix_sync(C + (long)(m0 + 32) * NP + ta * 16, acc2, NP, wmma::mem_row_major);
        wmma::store_matrix_sync(C + (long)(m0 + 48) * NP + ta * 16, acc3, NP, wmma::mem_row_major);
    }
}

// ---------------- attention: one warp per dst, online softmax, 2-edge pipeline ----------------
__device__ __forceinline__ void load_edge(int4 p, int lane, bool act,
                                          float4& k1, float4& k2, float4& k3,
                                          float4& v1, float4& v2, float4& v3) {
    if (act) {
        const float4* kn = (const float4*)(g_KVN + (long)p.x * NP_KV);
        const float4* ke = (const float4*)(g_KVE + (long)p.y * NP_KV);
        const float4* kt = (const float4*)(g_KVT + (long)p.z * NP_KV);
        k1 = kn[lane];      k2 = ke[lane];      k3 = kt[lane];
        v1 = kn[25 + lane]; v2 = ke[25 + lane]; v3 = kt[25 + lane];
    }
}

__global__ __launch_bounds__(256)
void attn_kernel() {
    int w = (int)((blockIdx.x * (long)blockDim.x + threadIdx.x) >> 5);
    int lane = threadIdx.x & 31;
    if (w >= NDST) return;
    int beg = g_off[w], end = g_off[w + 1];

    bool act = lane < 25;
    int base = lane * 4;
    bool h0 = base + 0 < 50, h1 = base + 1 < 50, h2 = base + 2 < 50, h3 = base + 3 < 50;

    float4 q = make_float4(0.f, 0.f, 0.f, 0.f);
    if (act) q = ((const float4*)(g_Q + (long)w * NP_Q))[lane];

    float4 acc = make_float4(0.f, 0.f, 0.f, 0.f);
    float m0 = -1e30f, m1 = -1e30f, s0 = 0.f, s1 = 0.f;
    float4 z4 = make_float4(0.f, 0.f, 0.f, 0.f);

    int j = beg;
    for (; j + 1 < end; j += 2) {
        int4 pA = g_pack[j];
        int4 pB = g_pack[j + 1];
        float4 ka1 = z4, ka2 = z4, ka3 = z4, va1 = z4, va2 = z4, va3 = z4;
        float4 kb1 = z4, kb2 = z4, kb3 = z4, vb1 = z4, vb2 = z4, vb3 = z4;
        load_edge(pA, lane, act, ka1, ka2, ka3, va1, va2, va3);
        load_edge(pB, lane, act, kb1, kb2, kb3, vb1, vb2, vb3);

        float t0a = 0.f, t1a = 0.f, t0b = 0.f, t1b = 0.f;
        float4 vA = z4, vB = z4;
        if (act) {
            float ax = q.x * (ka1.x + ka2.x + ka3.x);
            float ay = q.y * (ka1.y + ka2.y + ka3.y);
            float az = q.z * (ka1.z + ka2.z + ka3.z);
            float aw = q.w * (ka1.w + ka2.w + ka3.w);
            t0a = (h0 ? ax : 0.f) + (h1 ? ay : 0.f) + (h2 ? az : 0.f) + (h3 ? aw : 0.f);
            t1a = (h0 ? 0.f : ax) + (h1 ? 0.f : ay) + (h2 ? 0.f : az) + (h3 ? 0.f : aw);
            float bx = q.x * (kb1.x + kb2.x + kb3.x);
            float by = q.y * (kb1.y + kb2.y + kb3.y);
            float bz = q.z * (kb1.z + kb2.z + kb3.z);
            float bw = q.w * (kb1.w + kb2.w + kb3.w);
            t0b = (h0 ? bx : 0.f) + (h1 ? by : 0.f) + (h2 ? bz : 0.f) + (h3 ? bw : 0.f);
            t1b = (h0 ? 0.f : bx) + (h1 ? 0.f : by) + (h2 ? 0.f : bz) + (h3 ? 0.f : bw);
            vA.x = va1.x + va2.x + va3.x; vA.y = va1.y + va2.y + va3.y;
            vA.z = va1.z + va2.z + va3.z; vA.w = va1.w + va2.w + va3.w;
            vB.x = vb1.x + vb2.x + vb3.x; vB.y = vb1.y + vb2.y + vb3.y;
            vB.z = vb1.z + vb2.z + vb3.z; vB.w = vb1.w + vb2.w + vb3.w;
        }
#pragma unroll
        for (int off = 16; off; off >>= 1) {
            t0a += __shfl_xor_sync(0xffffffffu, t0a, off);
            t1a += __shfl_xor_sync(0xffffffffu, t1a, off);
            t0b += __shfl_xor_sync(0xffffffffu, t0b, off);
            t1b += __shfl_xor_sync(0xffffffffu, t1b, off);
        }
        {
            float a0 = t0a > 0.f ? t0a : NEG_SLOPE * t0a;
            float a1 = t1a > 0.f ? t1a : NEG_SLOPE * t1a;
            float nm0 = fmaxf(m0, a0);
            float c0 = __expf(m0 - nm0), w0 = __expf(a0 - nm0);
            s0 = s0 * c0 + w0; m0 = nm0;
            float nm1 = fmaxf(m1, a1);
            float c1 = __expf(m1 - nm1), w1 = __expf(a1 - nm1);
            s1 = s1 * c1 + w1; m1 = nm1;
            acc.x = acc.x * (h0 ? c0 : c1) + (h0 ? w0 : w1) * vA.x;
            acc.y = acc.y * (h1 ? c0 : c1) + (h1 ? w0 : w1) * vA.y;
            acc.z = acc.z * (h2 ? c0 : c1) + (h2 ? w0 : w1) * vA.z;
            acc.w = acc.w * (h3 ? c0 : c1) + (h3 ? w0 : w1) * vA.w;
        }
        {
            float a0 = t0b > 0.f ? t0b : NEG_SLOPE * t0b;
            float a1 = t1b > 0.f ? t1b : NEG_SLOPE * t1b;
            float nm0 = fmaxf(m0, a0);
            float c0 = __expf(m0 - nm0), w0 = __expf(a0 - nm0);
            s0 = s0 * c0 + w0; m0 = nm0;
            float nm1 = fmaxf(m1, a1);
            float c1 = __expf(m1 - nm1), w1 = __expf(a1 - nm1);
            s1 = s1 * c1 + w1; m1 = nm1;
            acc.x = acc.x * (h0 ? c0 : c1) + (h0 ? w0 : w1) * vB.x;
            acc.y = acc.y * (h1 ? c0 : c1) + (h1 ? w0 : w1) * vB.y;
            acc.z = acc.z * (h2 ? c0 : c1) + (h2 ? w0 : w1) * vB.z;
            acc.w = acc.w * (h3 ? c0 : c1) + (h3 ? w0 : w1) * vB.w;
        }
    }
    if (j < end) {
        int4 p = g_pack[j];
        float4 k1 = z4, k2 = z4, k3 = z4, v1 = z4, v2 = z4, v3 = z4;
        load_edge(p, lane, act, k1, k2, k3, v1, v2, v3);
        float t0 = 0.f, t1 = 0.f;
        float4 vS = z4;
        if (act) {
            float px = q.x * (k1.x + k2.x + k3.x);
            float py = q.y * (k1.y + k2.y + k3.y);
            float pz = q.z * (k1.z + k2.z + k3.z);
            float pw = q.w * (k1.w + k2.w + k3.w);
            t0 = (h0 ? px : 0.f) + (h1 ? py : 0.f) + (h2 ? pz : 0.f) + (h3 ? pw : 0.f);
            t1 = (h0 ? 0.f : px) + (h1 ? 0.f : py) + (h2 ? 0.f : pz) + (h3 ? 0.f : pw);
            vS.x = v1.x + v2.x + v3.x; vS.y = v1.y + v2.y + v3.y;
            vS.z = v1.z + v2.z + v3.z; vS.w = v1.w + v2.w + v3.w;
        }
#pragma unroll
        for (int off = 16; off; off >>= 1) {
            t0 += __shfl_xor_sync(0xffffffffu, t0, off);
            t1 += __shfl_xor_sync(0xffffffffu, t1, off);
        }
        float a0 = t0 > 0.f ? t0 : NEG_SLOPE * t0;
        float a1 = t1 > 0.f ? t1 : NEG_SLOPE * t1;
        float nm0 = fmaxf(m0, a0);
        float c0 = __expf(m0 - nm0), w0 = __expf(a0 - nm0);
        s0 = s0 * c0 + w0; m0 = nm0;
        float nm1 = fmaxf(m1, a1);
        float c1 = __expf(m1 - nm1), w1 = __expf(a1 - nm1);
        s1 = s1 * c1 + w1; m1 = nm1;
        acc.x = acc.x * (h0 ? c0 : c1) + (h0 ? w0 : w1) * vS.x;
        acc.y = acc.y * (h1 ? c0 : c1) + (h1 ? w0 : w1) * vS.y;
        acc.z = acc.z * (h2 ? c0 : c1) + (h2 ? w0 : w1) * vS.z;
        acc.w = acc.w * (h3 ? c0 : c1) + (h3 ? w0 : w1) * vS.w;
    }

    if (act) {
        float r0 = s0 > 0.f ? 1.f / s0 : 0.f;
        float r1 = s1 > 0.f ? 1.f / s1 : 0.f;
        float4 o;
        o.x = acc.x * (h0 ? r0 : r1);
        o.y = acc.y * (h1 ? r0 : r1);
        o.z = acc.z * (h2 ? r0 : r1);
        o.w = acc.w * (h3 ? r0 : r1);
        ((float4*)(g_acc + (long)w * DO_))[lane] = o;
    }
}

// ---------------- finalize: bf16x2 concat-GEMM (tile-major) + relu + LayerNorm ----------------
#define FIN_KT (KP_OUT / 16)     // 18
#define FIN_NT (NP_Q / 16)       // 7
#define FIN_SMEM (64 * KP_OUT * 2 * 2)   // Ah+Al bf16 = 73728 B
#define FIN_LDC 116
__global__ __launch_bounds__(256)
void finalize_bf(const float* __restrict__ nodeData,
                 const int* __restrict__ rev_nids,
                 const __nv_bfloat16* __restrict__ Wh, const __nv_bfloat16* __restrict__ Wl,
                 const float* __restrict__ ln_g, const float* __restrict__ ln_b,
                 float* __restrict__ out) {
    extern __shared__ char smraw[];
    __nv_bfloat16* Ah = (__nv_bfloat16*)smraw;       // 64*288 tile-major
    __nv_bfloat16* Al = Ah + 64 * KP_OUT;
    float* Cs = (float*)smraw;                        // reused after mainloop (64 x FIN_LDC)
    int tid = threadIdx.x, wid = tid >> 5, lane = tid & 31;
    int m0 = blockIdx.x * 64;

    for (int idx = tid; idx < 64 * 72; idx += 256) {
        int r = idx / 72, c4 = idx - r * 72;
        int row = m0 + r;
        int k = c4 * 4;
        float4 v = make_float4(0.f, 0.f, 0.f, 0.f);
        if (row < NDST) {
            if (c4 < 25) {
                v = *(const float4*)(g_acc + (long)row * DO_ + k);
            } else if (c4 < 68) {
                long nb = (long)rev_nids[row] * DN_;
                v = *(const float4*)(nodeData + nb + (k - 100));
            } else if (c4 == 68) {
                v.x = 1.0f;
            }
        }
        int off = (((r >> 4) * FIN_KT + (k >> 4)) << 8) + ((r & 15) << 4) + (k & 15);
        __nv_bfloat16 h; float x;
        x = v.x; h = __float2bfloat16(x); Ah[off + 0] = h; Al[off + 0] = __float2bfloat16(x - __bfloat162float(h));
        x = v.y; h = __float2bfloat16(x); Ah[off + 1] = h; Al[off + 1] = __float2bfloat16(x - __bfloat162float(h));
        x = v.z; h = __float2bfloat16(x); Ah[off + 2] = h; Al[off + 2] = __float2bfloat16(x - __bfloat162float(h));
        x = v.w; h = __float2bfloat16(x); Ah[off + 3] = h; Al[off + 3] = __float2bfloat16(x - __bfloat162float(h));
    }
    __syncthreads();

    int wm = (wid >> 2) * 32;
    int wn = (wid & 3) * 16;
    int mt0 = wm >> 4;
    int nt0 = wn >> 4;

    wmma::fragment<wmma::accumulator, 16, 16, 16, float> acc[2][2];
    bool act1 = (4 + nt0) < FIN_NT;     // second N tile (cols 64+wn)
#pragma unroll
    for (int a = 0; a < 2; a++)
#pragma unroll
        for (int i = 0; i < 2; i++) wmma::fill_fragment(acc[a][i], 0.f);

    for (int kt = 0; kt < FIN_KT; kt++) {
        wmma::fragment<wmma::matrix_a, 16, 16, 16, __nv_bfloat16, wmma::row_major> ah0, ah1, al0, al1;
        wmma::load_matrix_sync(ah0, Ah + (((mt0 + 0) * FIN_KT + kt) << 8), 16);
        wmma::load_matrix_sync(ah1, Ah + (((mt0 + 1) * FIN_KT + kt) << 8), 16);
        wmma::load_matrix_sync(al0, Al + (((mt0 + 0) * FIN_KT + kt) << 8), 16);
        wmma::load_matrix_sync(al1, Al + (((mt0 + 1) * FIN_KT + kt) << 8), 16);
        {
            wmma::fragment<wmma::matrix_b, 16, 16, 16, __nv_bfloat16, wmma::row_major> bh, bl;
            long bo = ((long)kt * FIN_NT + nt0) << 8;
            wmma::load_matrix_sync(bh, Wh + bo, 16);
            wmma::load_matrix_sync(bl, Wl + bo, 16);
            wmma::mma_sync(acc[0][0], al0, bh, acc[0][0]);
            wmma::mma_sync(acc[0][0], ah0, bl, acc[0][0]);
            wmma::mma_sync(acc[0][0], ah0, bh, acc[0][0]);
            wmma::mma_sync(acc[0][1], al1, bh, acc[0][1]);
            wmma::mma_sync(acc[0][1], ah1, bl, acc[0][1]);
            wmma::mma_sync(acc[0][1], ah1, bh, acc[0][1]);
        }
        if (act1) {
            wmma::fragment<wmma::matrix_b, 16, 16, 16, __nv_bfloat16, wmma::row_major> bh, bl;
            long bo = ((long)kt * FIN_NT + 4 + nt0) << 8;
            wmma::load_matrix_sync(bh, Wh + bo, 16);
            wmma::load_matrix_sync(bl, Wl + bo, 16);
            wmma::mma_sync(acc[1][0], al0, bh, acc[1][0]);
            wmma::mma_sync(acc[1][0], ah0, bl, acc[1][0]);
            wmma::mma_sync(acc[1][0], ah0, bh, acc[1][0]);
            wmma::mma_sync(acc[1][1], al1, bh, acc[1][1]);
            wmma::mma_sync(acc[1][1], ah1, bl, acc[1][1]);
            wmma::mma_sync(acc[1][1], ah1, bh, acc[1][1]);
        }
    }
    __syncthreads();

#pragma unroll
    for (int i = 0; i < 2; i++) {
        wmma::store_matrix_sync(Cs + (wm + i * 16) * FIN_LDC + wn, acc[0][i], FIN_LDC, wmma::mem_row_major);
        if (act1)
            wmma::store_matrix_sync(Cs + (wm + i * 16) * FIN_LDC + 64 + wn, acc[1][i], FIN_LDC, wmma::mem_row_major);
    }
    __syncthreads();

    float g0 = ln_g[lane], g1 = ln_g[lane + 32], g2 = ln_g[lane + 64];
    float g3 = lane < 4 ? ln_g[96 + lane] : 0.f;
    float be0 = ln_b[lane], be1 = ln_b[lane + 32], be2 = ln_b[lane + 64];
    float be3 = lane < 4 ? ln_b[96 + lane] : 0.f;

    for (int r = wid * 8; r < wid * 8 + 8; r++) {
        int row = m0 + r;
        if (row >= NDST) continue;
        float* cr = Cs + r * FIN_LDC;
        float x0 = cr[lane];        x0 = x0 > 0.f ? x0 : 0.f;
        float x1 = cr[lane + 32];   x1 = x1 > 0.f ? x1 : 0.f;
        float x2 = cr[lane + 64];   x2 = x2 > 0.f ? x2 : 0.f;
        float x3 = lane < 4 ? cr[96 + lane] : 0.f;  x3 = x3 > 0.f ? x3 : 0.f;
        float s = x0 + x1 + x2 + x3;
        float sq = x0 * x0 + x1 * x1 + x2 * x2 + x3 * x3;
#pragma unroll
        for (int off = 16; off; off >>= 1) {
            s  += __shfl_xor_sync(0xffffffffu, s, off);
            sq += __shfl_xor_sync(0xffffffffu, sq, off);
        }
        float mu = s * 0.01f;
        float var = sq * 0.01f - mu * mu;
        float inv = rsqrtf(var + 1e-5f);
        float* orow = out + (long)row * DO_;
        orow[lane]      = (x0 - mu) * inv * g0 + be0;
        orow[lane + 32] = (x1 - mu) * inv * g1 + be1;
        orow[lane + 64] = (x2 - mu) * inv * g2 + be2;
        if (lane < 4) orow[96 + lane] = (x3 - mu) * inv * g3 + be3;
    }
}

// ---------------- launch ----------------
extern "C" void kernel_launch(void* const* d_in, const int* in_sizes, int n_in,
                              void* d_out, int out_size) {
    const float* nodeData = (const float*)d_in[0];
    const float* efeat    = (const float*)d_in[1];
    const float* utd      = (const float*)d_in[2];
    const int*   rev_nids = (const int*)d_in[3];
    const int*   rev_eids = (const int*)d_in[4];
    const int*   rev_tids = (const int*)d_in[5];
    const int*   dstindex = (const int*)d_in[6];
    const float* time_w   = (const float*)d_in[8];
    const float* time_b   = (const float*)d_in[9];
    const float* Wqn      = (const float*)d_in[10];
    const float* bqn      = (const float*)d_in[11];
    const float* Wqt      = (const float*)d_in[12];
    const float* bqt      = (const float*)d_in[13];
    const float* Wkvn     = (const float*)d_in[14];
    const float* bkvn     = (const float*)d_in[15];
    const float* Wkve     = (const float*)d_in[16];
    const float* bkve     = (const float*)d_in[17];
    const float* Wkvt     = (const float*)d_in[18];
    const float* bkvt     = (const float*)d_in[19];
    const float* Wout     = (const float*)d_in[20];
    const float* bout     = (const float*)d_in[21];
    const float* ln_g     = (const float*)d_in[22];
    const float* ln_b     = (const float*)d_in[23];
    float* out = (float*)d_out;

    float *pQ, *pKVN, *pKVE, *pKVT, *pbiasq;
    __nv_bfloat16* pWS;
    int* pCnt;
    cudaGetSymbolAddress((void**)&pQ,     g_Q);
    cudaGetSymbolAddress((void**)&pKVN,   g_KVN);
    cudaGetSymbolAddress((void**)&pKVE,   g_KVE);
    cudaGetSymbolAddress((void**)&pKVT,   g_KVT);
    cudaGetSymbolAddress((void**)&pbiasq, g_biasq);
    cudaGetSymbolAddress((void**)&pWS,    g_WS);
    cudaGetSymbolAddress((void**)&pCnt,   g_cnt);

    const int* node_inv = rev_nids + NDST;

    const int sm_nd = 64 * KP_ND * 2 * 2;   // 45056
    const int sm_t  = 64 * KP_T  * 2 * 2;   // 28672
    cudaFuncSetAttribute((const void*)gemm_bf9<true,  false>, cudaFuncAttributeMaxDynamicSharedMemorySize, sm_nd);
    cudaFuncSetAttribute((const void*)gemm_bf9<false, false>, cudaFuncAttributeMaxDynamicSharedMemorySize, sm_nd);
    cudaFuncSetAttribute((const void*)gemm_bf9<false, true >, cudaFuncAttributeMaxDynamicSharedMemorySize, sm_nd);
    cudaFuncSetAttribute((const void*)finalize_bf, cudaFuncAttributeMaxDynamicSharedMemorySize, FIN_SMEM);

    cudaMemsetAsync(pCnt, 0, NDST * sizeof(int));

    // kernel launches: 1 hist, 2 split_w(kvn), 3 scan1, 4 gemm_kvn (profiled)
    hist_kernel<<<2048, 256>>>(dstindex);
    split_w<<<(KP_ND * NP_KV + 255) / 256, 256>>>(Wkvn, bkvn, bkve, bkvt,
        pWS + OFF_KVN_H, pWS + OFF_KVN_L, DN_, 2 * DO_, KP_ND, NP_KV);
    scan1_kernel<<<NB_SCAN, 1024>>>();

    gemm_bf9<false, false><<<UN / 64, 256, sm_nd>>>(
        nodeData, pWS + OFF_KVN_H, pWS + OFF_KVN_L, pKVN, nullptr,
        nullptr, nullptr, nullptr, UN, DN_, KP_ND, NP_KV);

    scan2_kernel<<<1, 128>>>();
    scan3_kernel<<<NB_SCAN, 1024>>>();
    scatter_kernel<<<2048, 256>>>(dstindex, node_inv, rev_eids, rev_tids);
    biasq_kernel<<<1, 128>>>(time_b, Wqt, bqt, bqn);

    split_w<<<(KP_ND * NP_Q + 255) / 256, 256>>>(Wqn, pbiasq, nullptr, nullptr,
        pWS + OFF_QN_H, pWS + OFF_QN_L, DN_, DO_, KP_ND, NP_Q);
    split_w<<<(KP_ND * NP_KV + 255) / 256, 256>>>(Wkve, nullptr, nullptr, nullptr,
        pWS + OFF_KVE_H, pWS + OFF_KVE_L, DN_, 2 * DO_, KP_ND, NP_KV);
    split_w<<<(KP_T * NP_KV + 255) / 256, 256>>>(Wkvt, nullptr, nullptr, nullptr,
        pWS + OFF_KVT_H, pWS + OFF_KVT_L, DT_, 2 * DO_, KP_T, NP_KV);
    split_w<<<(KP_OUT * NP_Q + 255) / 256, 256>>>(Wout, bout, nullptr, nullptr,
        pWS + OFF_OUT_H, pWS + OFF_OUT_L, DN_ + DO_, DO_, KP_OUT, NP_Q);

    gemm_bf9<true, false><<<(NDST + 63) / 64, 256, sm_nd>>>(
        nodeData, pWS + OFF_QN_H, pWS + OFF_QN_L, pQ, rev_nids,
        nullptr, nullptr, nullptr, NDST, DN_, KP_ND, NP_Q);
    gemm_bf9<false, false><<<(UE + 63) / 64, 256, sm_nd>>>(
        efeat, pWS + OFF_KVE_H, pWS + OFF_KVE_L, pKVE, nullptr,
        nullptr, nullptr, nullptr, UE, DN_, KP_ND, NP_KV);
    gemm_bf9<false, true><<<(UT + 63) / 64, 256, sm_t>>>(
        nullptr, pWS + OFF_KVT_H, pWS + OFF_KVT_L, pKVT, nullptr,
        utd, time_w, time_b, UT, DT_, KP_T, NP_KV);

    attn_kernel<<<(NDST + 7) / 8, 256>>>();

    finalize_bf<<<(NDST + 63) / 64, 256, FIN_SMEM>>>(
        nodeData, rev_nids, pWS + OFF_OUT_H, pWS + OFF_OUT_L, ln_g, ln_b, out);
}

// round 17
// speedup vs baseline: 1.6066x; 1.1983x over previous
#include <cuda_runtime.h>
#include <cuda_bf16.h>
#include <cuda_fp16.h>
#include <mma.h>
using namespace nvcuda;

#define NDST 100000
#define NE   1000000
#define UN   200000
#define UE   100000
#define UT   100000
#define DN_  172
#define DT_  100
#define DO_  100
#define NEG_SLOPE 0.2f

// padded row counts
#define UN_P  200064
#define M1_P  100096

#define NP_KV 208
#define NP_Q  112
#define KP_ND 176
#define KP_T  112
#define KP_OUT 288

// split-weight arena offsets (bf16 elements)
#define OFF_KVN_H 0
#define OFF_KVN_L (OFF_KVN_H + KP_ND * NP_KV)
#define OFF_KVE_H (OFF_KVN_L + KP_ND * NP_KV)
#define OFF_KVE_L (OFF_KVE_H + KP_ND * NP_KV)
#define OFF_KVT_H (OFF_KVE_L + KP_ND * NP_KV)
#define OFF_KVT_L (OFF_KVT_H + KP_T * NP_KV)
#define OFF_QN_H  (OFF_KVT_L + KP_T * NP_KV)
#define OFF_QN_L  (OFF_QN_H + KP_ND * NP_Q)
#define OFF_OUT_H (OFF_QN_L + KP_ND * NP_Q)
#define OFF_OUT_L (OFF_OUT_H + KP_OUT * NP_Q)
#define WSPLIT_TOTAL (OFF_OUT_L + KP_OUT * NP_Q)

// ---------------- scratch (device globals; no allocation) ----------------
__device__ float         g_Q   [M1_P * NP_Q];
__device__ __half        g_KVN [UN_P * NP_KV];     // fp16 KV tables
__device__ __half        g_KVE [M1_P * NP_KV];
__device__ __half        g_KVT [M1_P * NP_KV];
__device__ float         g_acc [NDST * DO_];
__device__ float         g_biasq[DO_];
__device__ __nv_bfloat16 g_WS  [WSPLIT_TOTAL];
__device__ int           g_cnt [NDST];
__device__ int           g_off [NDST + 1];
__device__ int           g_cur [NDST];
__device__ int           g_bsum[128];
__device__ int           g_btop[128];
__device__ int4          g_pack[NE];

__global__ void biasq_kernel(const float* __restrict__ time_b,
                             const float* __restrict__ Wqt,
                             const float* __restrict__ bqt,
                             const float* __restrict__ bqn) {
    int j = threadIdx.x;
    if (j >= DO_) return;
    float acc = bqt[j] + bqn[j];
    for (int k = 0; k < DT_; k++) acc += cosf(time_b[k]) * Wqt[k * DO_ + j];
    g_biasq[j] = acc;
}

// ---------------- weight split: tile-major layout ----------------
__global__ void split_w(const float* __restrict__ W,
                        const float* __restrict__ b0, const float* __restrict__ b1,
                        const float* __restrict__ b2,
                        __nv_bfloat16* __restrict__ oh, __nv_bfloat16* __restrict__ ol,
                        int K, int N, int KP, int NP) {
    int idx = blockIdx.x * blockDim.x + threadIdx.x;
    if (idx >= KP * NP) return;
    int k = idx / NP, n = idx - k * NP;
    float val = 0.f;
    if (n < N) {
        if (k < K) val = W[(long)k * N + n];
        else if (k == K) {
            if (b0) val += b0[n];
            if (b1) val += b1[n];
            if (b2) val += b2[n];
        }
    }
    int off = (((k >> 4) * (NP >> 4) + (n >> 4)) << 8) + ((k & 15) << 4) + (n & 15);
    __nv_bfloat16 h = __float2bfloat16(val);
    oh[off] = h;
    ol[off] = __float2bfloat16(val - __bfloat162float(h));
}

// ---------------- CSR build ----------------
__global__ void hist_kernel(const int* __restrict__ dsti) {
    int idx = blockIdx.x * blockDim.x + threadIdx.x;
    int stride = gridDim.x * blockDim.x;
    for (int e = idx; e < NE; e += stride) atomicAdd(&g_cnt[dsti[e]], 1);
}

#define NB_SCAN ((NDST + 1023) / 1024)   // 98

__global__ __launch_bounds__(1024)
void scan1_kernel() {
    __shared__ int ss[1024];
    int t = threadIdx.x;
    int i = blockIdx.x * 1024 + t;
    int v = (i < NDST) ? g_cnt[i] : 0;
    ss[t] = v;
    __syncthreads();
    for (int off = 1; off < 1024; off <<= 1) {
        int u = (t >= off) ? ss[t - off] : 0;
        __syncthreads();
        ss[t] += u;
        __syncthreads();
    }
    if (i < NDST) g_off[i] = ss[t] - v;
    if (t == 1023) g_bsum[blockIdx.x] = ss[1023];
}

__global__ __launch_bounds__(128)
void scan2_kernel() {
    __shared__ int ss[128];
    int t = threadIdx.x;
    int v = (t < NB_SCAN) ? g_bsum[t] : 0;
    ss[t] = v;
    __syncthreads();
    for (int off = 1; off < 128; off <<= 1) {
        int u = (t >= off) ? ss[t - off] : 0;
        __syncthreads();
        ss[t] += u;
        __syncthreads();
    }
    g_btop[t] = ss[t] - v;
}

__global__ __launch_bounds__(1024)
void scan3_kernel() {
    int t = threadIdx.x;
    int i = blockIdx.x * 1024 + t;
    if (i < NDST) {
        int o = g_off[i] + g_btop[blockIdx.x];
        g_off[i] = o;
        g_cur[i] = o;
    }
    if (i == 0) g_off[NDST] = NE;
}

__global__ void scatter_kernel(const int* __restrict__ dsti,
                               const int* __restrict__ node_inv,
                               const int* __restrict__ eids,
                               const int* __restrict__ tids) {
    int idx = blockIdx.x * blockDim.x + threadIdx.x;
    int stride = gridDim.x * blockDim.x;
    for (int e = idx; e < NE; e += stride) {
        int pos = atomicAdd(&g_cur[dsti[e]], 1);
        g_pack[pos] = make_int4(node_inv[e], eids[e], tids[e], 0);
    }
}

// ---------------- bf16x2 GEMM v10: tile-major, 4M x 1N per warp; optional fp16 C ----------------
// 256 threads (8 warps); warp wid owns N-tile pass*8+wid, all 4 M-tiles. BM=64.
// TIMEF: A[row,k] = cos(utd[row]*tw[k]+tb[k]) inline. STOREH: C stored as __half via smem staging.
template <bool GATHER, bool TIMEF, bool STOREH>
__global__ __launch_bounds__(256, 3)
void gemm_bf10(const float* __restrict__ A,
               const __nv_bfloat16* __restrict__ Wh, const __nv_bfloat16* __restrict__ Wl,
               float* __restrict__ Cf, __half* __restrict__ Ch,
               const int* __restrict__ gidx,
               const float* __restrict__ utd, const float* __restrict__ tw,
               const float* __restrict__ tb,
               int M, int K, int KP, int NP) {
    extern __shared__ char smraw[];
    __nv_bfloat16* Ah = (__nv_bfloat16*)smraw;          // 64*KP tile-major
    __nv_bfloat16* Al = Ah + 64 * KP;
    float* stg = (float*)(Al + 64 * KP);                // 8 warps x 256 floats
    int tid = threadIdx.x, wid = tid >> 5, lane = tid & 31;
    int m0 = blockIdx.x * 64;
    int KT = KP >> 4;

    // stage A hi/lo tile-major
    int nc4 = KP >> 2;
    for (int idx = tid; idx < 64 * nc4; idx += 256) {
        int r = idx / nc4, c4 = idx - r * nc4;
        int row = m0 + r;
        int k = c4 * 4;
        float4 v = make_float4(0.f, 0.f, 0.f, 0.f);
        if (row < M) {
            if (TIMEF) {
                if (k + 3 < K) {
                    float4 w4 = *(const float4*)(tw + k);
                    float4 b4 = *(const float4*)(tb + k);
                    float td = utd[row];
                    v.x = cosf(td * w4.x + b4.x);
                    v.y = cosf(td * w4.y + b4.y);
                    v.z = cosf(td * w4.z + b4.z);
                    v.w = cosf(td * w4.w + b4.w);
                } else if (K >= k && K < k + 4) {
                    ((float*)&v)[K - k] = 1.0f;
                }
            } else {
                long ab = (long)(GATHER ? gidx[row] : row) * K;
                if (k + 3 < K) {
                    v = *(const float4*)(A + ab + k);
                } else {
                    if (k + 0 < K) v.x = A[ab + k + 0];
                    if (k + 1 < K) v.y = A[ab + k + 1];
                    if (k + 2 < K) v.z = A[ab + k + 2];
                    if (k + 3 < K) v.w = A[ab + k + 3];
                }
                if (K >= k && K < k + 4) ((float*)&v)[K - k] = 1.0f;
            }
        }
        int off = (((r >> 4) * KT + (k >> 4)) << 8) + ((r & 15) << 4) + (k & 15);
        __nv_bfloat16 h; float x;
        x = v.x; h = __float2bfloat16(x); Ah[off + 0] = h; Al[off + 0] = __float2bfloat16(x - __bfloat162float(h));
        x = v.y; h = __float2bfloat16(x); Ah[off + 1] = h; Al[off + 1] = __float2bfloat16(x - __bfloat162float(h));
        x = v.z; h = __float2bfloat16(x); Ah[off + 2] = h; Al[off + 2] = __float2bfloat16(x - __bfloat162float(h));
        x = v.w; h = __float2bfloat16(x); Ah[off + 3] = h; Al[off + 3] = __float2bfloat16(x - __bfloat162float(h));
    }
    __syncthreads();

    int NT = NP >> 4;           // 13 (kv) or 7 (q)
    float* ws = stg + wid * 256;
    int sr = lane >> 1, sc = (lane & 1) * 8;

    for (int pass = 0; pass < 2; pass++) {
        int ta = pass * 8 + wid;
        if (ta >= NT) continue;

        wmma::fragment<wmma::accumulator, 16, 16, 16, float> acc0, acc1, acc2, acc3;
        wmma::fill_fragment(acc0, 0.f);
        wmma::fill_fragment(acc1, 0.f);
        wmma::fill_fragment(acc2, 0.f);
        wmma::fill_fragment(acc3, 0.f);

        for (int kt = 0; kt < KT; kt++) {
            wmma::fragment<wmma::matrix_b, 16, 16, 16, __nv_bfloat16, wmma::row_major> bh, bl;
            long bo = ((long)kt * NT + ta) << 8;
            wmma::load_matrix_sync(bh, Wh + bo, 16);
            wmma::load_matrix_sync(bl, Wl + bo, 16);

            {
                wmma::fragment<wmma::matrix_a, 16, 16, 16, __nv_bfloat16, wmma::row_major> ah, al;
                wmma::load_matrix_sync(ah, Ah + ((0 * KT + kt) << 8), 16);
                wmma::load_matrix_sync(al, Al + ((0 * KT + kt) << 8), 16);
                wmma::mma_sync(acc0, al, bh, acc0);
                wmma::mma_sync(acc0, ah, bl, acc0);
                wmma::mma_sync(acc0, ah, bh, acc0);
            }
            {
                wmma::fragment<wmma::matrix_a, 16, 16, 16, __nv_bfloat16, wmma::row_major> ah, al;
                wmma::load_matrix_sync(ah, Ah + ((1 * KT + kt) << 8), 16);
                wmma::load_matrix_sync(al, Al + ((1 * KT + kt) << 8), 16);
                wmma::mma_sync(acc1, al, bh, acc1);
                wmma::mma_sync(acc1, ah, bl, acc1);
                wmma::mma_sync(acc1, ah, bh, acc1);
            }
            {
                wmma::fragment<wmma::matrix_a, 16, 16, 16, __nv_bfloat16, wmma::row_major> ah, al;
                wmma::load_matrix_sync(ah, Ah + ((2 * KT + kt) << 8), 16);
                wmma::load_matrix_sync(al, Al + ((2 * KT + kt) << 8), 16);
                wmma::mma_sync(acc2, al, bh, acc2);
                wmma::mma_sync(acc2, ah, bl, acc2);
                wmma::mma_sync(acc2, ah, bh, acc2);
            }
            {
                wmma::fragment<wmma::matrix_a, 16, 16, 16, __nv_bfloat16, wmma::row_major> ah, al;
                wmma::load_matrix_sync(ah, Ah + ((3 * KT + kt) << 8), 16);
                wmma::load_matrix_sync(al, Al + ((3 * KT + kt) << 8), 16);
                wmma::mma_sync(acc3, al, bh, acc3);
                wmma::mma_sync(acc3, ah, bl, acc3);
                wmma::mma_sync(acc3, ah, bh, acc3);
            }
        }
        if (STOREH) {
#pragma unroll
            for (int t = 0; t < 4; t++) {
                wmma::fragment<wmma::accumulator, 16, 16, 16, float>& a =
                    (t == 0) ? acc0 : (t == 1) ? acc1 : (t == 2) ? acc2 : acc3;
                wmma::store_matrix_sync(ws, a, 16, wmma::mem_row_major);
                __syncwarp();
                float4 f0 = *(float4*)(ws + sr * 16 + sc);
                float4 f1 = *(float4*)(ws + sr * 16 + sc + 4);
                __half o8[8];
                o8[0] = __float2half_rn(f0.x); o8[1] = __float2half_rn(f0.y);
                o8[2] = __float2half_rn(f0.z); o8[3] = __float2half_rn(f0.w);
                o8[4] = __float2half_rn(f1.x); o8[5] = __float2half_rn(f1.y);
                o8[6] = __float2half_rn(f1.z); o8[7] = __float2half_rn(f1.w);
                *(uint4*)(Ch + (long)(m0 + t * 16 + sr) * NP + ta * 16 + sc) = *(uint4*)o8;
                __syncwarp();
            }
        } else {
            wmma::store_matrix_sync(Cf + (long)(m0 +  0) * NP + ta * 16, acc0, NP, wmma::mem_row_major);
            wmma::store_matrix_sync(Cf + (long)(m0 + 16) * NP + ta * 16, acc1, NP, wmma::mem_row_major);
            wmma::store_matrix_sync(Cf + (long)(m0 + 32) * NP + ta * 16, acc2, NP, wmma::mem_row_major);
            wmma::store_matrix_sync(Cf + (long)(m0 + 48) * NP + ta * 16, acc3, NP, wmma::mem_row_major);
        }
    }
}

// ---------------- attention: one warp per dst, online softmax, fp16 KV tables ----------------
__device__ __forceinline__ float4 h4tof4(uint2 u) {
    __half2 a = *(__half2*)&u.x, b = *(__half2*)&u.y;
    float2 fa = __half22float2(a), fb = __half22float2(b);
    return make_float4(fa.x, fa.y, fb.x, fb.y);
}

__device__ __forceinline__ void load_edge(int4 p, int lane, bool act,
                                          float4& k1, float4& k2, float4& k3,
                                          float4& v1, float4& v2, float4& v3) {
    if (act) {
        const uint2* kn = (const uint2*)(g_KVN + (long)p.x * NP_KV);
        const uint2* ke = (const uint2*)(g_KVE + (long)p.y * NP_KV);
        const uint2* kt = (const uint2*)(g_KVT + (long)p.z * NP_KV);
        k1 = h4tof4(kn[lane]);      k2 = h4tof4(ke[lane]);      k3 = h4tof4(kt[lane]);
        v1 = h4tof4(kn[25 + lane]); v2 = h4tof4(ke[25 + lane]); v3 = h4tof4(kt[25 + lane]);
    }
}

__global__ __launch_bounds__(256)
void attn_kernel() {
    int w = (int)((blockIdx.x * (long)blockDim.x + threadIdx.x) >> 5);
    int lane = threadIdx.x & 31;
    if (w >= NDST) return;
    int beg = g_off[w], end = g_off[w + 1];

    bool act = lane < 25;
    int base = lane * 4;
    bool h0 = base + 0 < 50, h1 = base + 1 < 50, h2 = base + 2 < 50, h3 = base + 3 < 50;

    float4 q = make_float4(0.f, 0.f, 0.f, 0.f);
    if (act) q = ((const float4*)(g_Q + (long)w * NP_Q))[lane];

    float4 acc = make_float4(0.f, 0.f, 0.f, 0.f);
    float m0 = -1e30f, m1 = -1e30f, s0 = 0.f, s1 = 0.f;
    float4 z4 = make_float4(0.f, 0.f, 0.f, 0.f);

    int j = beg;
    for (; j + 1 < end; j += 2) {
        int4 pA = g_pack[j];
        int4 pB = g_pack[j + 1];
        float4 ka1 = z4, ka2 = z4, ka3 = z4, va1 = z4, va2 = z4, va3 = z4;
        float4 kb1 = z4, kb2 = z4, kb3 = z4, vb1 = z4, vb2 = z4, vb3 = z4;
        load_edge(pA, lane, act, ka1, ka2, ka3, va1, va2, va3);
        load_edge(pB, lane, act, kb1, kb2, kb3, vb1, vb2, vb3);

        float t0a = 0.f, t1a = 0.f, t0b = 0.f, t1b = 0.f;
        float4 vA = z4, vB = z4;
        if (act) {
            float ax = q.x * (ka1.x + ka2.x + ka3.x);
            float ay = q.y * (ka1.y + ka2.y + ka3.y);
            float az = q.z * (ka1.z + ka2.z + ka3.z);
            float aw = q.w * (ka1.w + ka2.w + ka3.w);
            t0a = (h0 ? ax : 0.f) + (h1 ? ay : 0.f) + (h2 ? az : 0.f) + (h3 ? aw : 0.f);
            t1a = (h0 ? 0.f : ax) + (h1 ? 0.f : ay) + (h2 ? 0.f : az) + (h3 ? 0.f : aw);
            float bx = q.x * (kb1.x + kb2.x + kb3.x);
            float by = q.y * (kb1.y + kb2.y + kb3.y);
            float bz = q.z * (kb1.z + kb2.z + kb3.z);
            float bw = q.w * (kb1.w + kb2.w + kb3.w);
            t0b = (h0 ? bx : 0.f) + (h1 ? by : 0.f) + (h2 ? bz : 0.f) + (h3 ? bw : 0.f);
            t1b = (h0 ? 0.f : bx) + (h1 ? 0.f : by) + (h2 ? 0.f : bz) + (h3 ? 0.f : bw);
            vA.x = va1.x + va2.x + va3.x; vA.y = va1.y + va2.y + va3.y;
            vA.z = va1.z + va2.z + va3.z; vA.w = va1.w + va2.w + va3.w;
            vB.x = vb1.x + vb2.x + vb3.x; vB.y = vb1.y + vb2.y + vb3.y;
            vB.z = vb1.z + vb2.z + vb3.z; vB.w = vb1.w + vb2.w + vb3.w;
        }
#pragma unroll
        for (int off = 16; off; off >>= 1) {
            t0a += __shfl_xor_sync(0xffffffffu, t0a, off);
            t1a += __shfl_xor_sync(0xffffffffu, t1a, off);
            t0b += __shfl_xor_sync(0xffffffffu, t0b, off);
            t1b += __shfl_xor_sync(0xffffffffu, t1b, off);
        }
        {
            float a0 = t0a > 0.f ? t0a : NEG_SLOPE * t0a;
            float a1 = t1a > 0.f ? t1a : NEG_SLOPE * t1a;
            float nm0 = fmaxf(m0, a0);
            float c0 = __expf(m0 - nm0), w0 = __expf(a0 - nm0);
            s0 = s0 * c0 + w0; m0 = nm0;
            float nm1 = fmaxf(m1, a1);
            float c1 = __expf(m1 - nm1), w1 = __expf(a1 - nm1);
            s1 = s1 * c1 + w1; m1 = nm1;
            acc.x = acc.x * (h0 ? c0 : c1) + (h0 ? w0 : w1) * vA.x;
            acc.y = acc.y * (h1 ? c0 : c1) + (h1 ? w0 : w1) * vA.y;
            acc.z = acc.z * (h2 ? c0 : c1) + (h2 ? w0 : w1) * vA.z;
            acc.w = acc.w * (h3 ? c0 : c1) + (h3 ? w0 : w1) * vA.w;
        }
        {
            float a0 = t0b > 0.f ? t0b : NEG_SLOPE * t0b;
            float a1 = t1b > 0.f ? t1b : NEG_SLOPE * t1b;
            float nm0 = fmaxf(m0, a0);
            float c0 = __expf(m0 - nm0), w0 = __expf(a0 - nm0);
            s0 = s0 * c0 + w0; m0 = nm0;
            float nm1 = fmaxf(m1, a1);
            float c1 = __expf(m1 - nm1), w1 = __expf(a1 - nm1);
            s1 = s1 * c1 + w1; m1 = nm1;
            acc.x = acc.x * (h0 ? c0 : c1) + (h0 ? w0 : w1) * vB.x;
            acc.y = acc.y * (h1 ? c0 : c1) + (h1 ? w0 : w1) * vB.y;
            acc.z = acc.z * (h2 ? c0 : c1) + (h2 ? w0 : w1) * vB.z;
            acc.w = acc.w * (h3 ? c0 : c1) + (h3 ? w0 : w1) * vB.w;
        }
    }
    if (j < end) {
        int4 p = g_pack[j];
        float4 k1 = z4, k2 = z4, k3 = z4, v1 = z4, v2 = z4, v3 = z4;
        load_edge(p, lane, act, k1, k2, k3, v1, v2, v3);
        float t0 = 0.f, t1 = 0.f;
        float4 vS = z4;
        if (act) {
            float px = q.x * (k1.x + k2.x + k3.x);
            float py = q.y * (k1.y + k2.y + k3.y);
            float pz = q.z * (k1.z + k2.z + k3.z);
            float pw = q.w * (k1.w + k2.w + k3.w);
            t0 = (h0 ? px : 0.f) + (h1 ? py : 0.f) + (h2 ? pz : 0.f) + (h3 ? pw : 0.f);
            t1 = (h0 ? 0.f : px) + (h1 ? 0.f : py) + (h2 ? 0.f : pz) + (h3 ? 0.f : pw);
            vS.x = v1.x + v2.x + v3.x; vS.y = v1.y + v2.y + v3.y;
            vS.z = v1.z + v2.z + v3.z; vS.w = v1.w + v2.w + v3.w;
        }
#pragma unroll
        for (int off = 16; off; off >>= 1) {
            t0 += __shfl_xor_sync(0xffffffffu, t0, off);
            t1 += __shfl_xor_sync(0xffffffffu, t1, off);
        }
        float a0 = t0 > 0.f ? t0 : NEG_SLOPE * t0;
        float a1 = t1 > 0.f ? t1 : NEG_SLOPE * t1;
        float nm0 = fmaxf(m0, a0);
        float c0 = __expf(m0 - nm0), w0 = __expf(a0 - nm0);
        s0 = s0 * c0 + w0; m0 = nm0;
        float nm1 = fmaxf(m1, a1);
        float c1 = __expf(m1 - nm1), w1 = __expf(a1 - nm1);
        s1 = s1 * c1 + w1; m1 = nm1;
        acc.x = acc.x * (h0 ? c0 : c1) + (h0 ? w0 : w1) * vS.x;
        acc.y = acc.y * (h1 ? c0 : c1) + (h1 ? w0 : w1) * vS.y;
        acc.z = acc.z * (h2 ? c0 : c1) + (h2 ? w0 : w1) * vS.z;
        acc.w = acc.w * (h3 ? c0 : c1) + (h3 ? w0 : w1) * vS.w;
    }

    if (act) {
        float r0 = s0 > 0.f ? 1.f / s0 : 0.f;
        float r1 = s1 > 0.f ? 1.f / s1 : 0.f;
        float4 o;
        o.x = acc.x * (h0 ? r0 : r1);
        o.y = acc.y * (h1 ? r0 : r1);
        o.z = acc.z * (h2 ? r0 : r1);
        o.w = acc.w * (h3 ? r0 : r1);
        ((float4*)(g_acc + (long)w * DO_))[lane] = o;
    }
}

// ---------------- finalize: bf16x2 concat-GEMM (tile-major) + relu + LayerNorm ----------------
#define FIN_KT (KP_OUT / 16)     // 18
#define FIN_NT (NP_Q / 16)       // 7
#define FIN_SMEM (64 * KP_OUT * 2 * 2)   // Ah+Al bf16 = 73728 B
#define FIN_LDC 116
__global__ __launch_bounds__(256)
void finalize_bf(const float* __restrict__ nodeData,
                 const int* __restrict__ rev_nids,
                 const __nv_bfloat16* __restrict__ Wh, const __nv_bfloat16* __restrict__ Wl,
                 const float* __restrict__ ln_g, const float* __restrict__ ln_b,
                 float* __restrict__ out) {
    extern __shared__ char smraw[];
    __nv_bfloat16* Ah = (__nv_bfloat16*)smraw;       // 64*288 tile-major
    __nv_bfloat16* Al = Ah + 64 * KP_OUT;
    float* Cs = (float*)smraw;                        // reused after mainloop (64 x FIN_LDC)
    int tid = threadIdx.x, wid = tid >> 5, lane = tid & 31;
    int m0 = blockIdx.x * 64;

    for (int idx = tid; idx < 64 * 72; idx += 256) {
        int r = idx / 72, c4 = idx - r * 72;
        int row = m0 + r;
        int k = c4 * 4;
        float4 v = make_float4(0.f, 0.f, 0.f, 0.f);
        if (row < NDST) {
            if (c4 < 25) {
                v = *(const float4*)(g_acc + (long)row * DO_ + k);
            } else if (c4 < 68) {
                long nb = (long)rev_nids[row] * DN_;
                v = *(const float4*)(nodeData + nb + (k - 100));
            } else if (c4 == 68) {
                v.x = 1.0f;
            }
        }
        int off = (((r >> 4) * FIN_KT + (k >> 4)) << 8) + ((r & 15) << 4) + (k & 15);
        __nv_bfloat16 h; float x;
        x = v.x; h = __float2bfloat16(x); Ah[off + 0] = h; Al[off + 0] = __float2bfloat16(x - __bfloat162float(h));
        x = v.y; h = __float2bfloat16(x); Ah[off + 1] = h; Al[off + 1] = __float2bfloat16(x - __bfloat162float(h));
        x = v.z; h = __float2bfloat16(x); Ah[off + 2] = h; Al[off + 2] = __float2bfloat16(x - __bfloat162float(h));
        x = v.w; h = __float2bfloat16(x); Ah[off + 3] = h; Al[off + 3] = __float2bfloat16(x - __bfloat162float(h));
    }
    __syncthreads();

    int wm = (wid >> 2) * 32;
    int wn = (wid & 3) * 16;
    int mt0 = wm >> 4;
    int nt0 = wn >> 4;

    wmma::fragment<wmma::accumulator, 16, 16, 16, float> acc[2][2];
    bool act1 = (4 + nt0) < FIN_NT;     // second N tile (cols 64+wn)
#pragma unroll
    for (int a = 0; a < 2; a++)
#pragma unroll
        for (int i = 0; i < 2; i++) wmma::fill_fragment(acc[a][i], 0.f);

    for (int kt = 0; kt < FIN_KT; kt++) {
        wmma::fragment<wmma::matrix_a, 16, 16, 16, __nv_bfloat16, wmma::row_major> ah0, ah1, al0, al1;
        wmma::load_matrix_sync(ah0, Ah + (((mt0 + 0) * FIN_KT + kt) << 8), 16);
        wmma::load_matrix_sync(ah1, Ah + (((mt0 + 1) * FIN_KT + kt) << 8), 16);
        wmma::load_matrix_sync(al0, Al + (((mt0 + 0) * FIN_KT + kt) << 8), 16);
        wmma::load_matrix_sync(al1, Al + (((mt0 + 1) * FIN_KT + kt) << 8), 16);
        {
            wmma::fragment<wmma::matrix_b, 16, 16, 16, __nv_bfloat16, wmma::row_major> bh, bl;
            long bo = ((long)kt * FIN_NT + nt0) << 8;
            wmma::load_matrix_sync(bh, Wh + bo, 16);
            wmma::load_matrix_sync(bl, Wl + bo, 16);
            wmma::mma_sync(acc[0][0], al0, bh, acc[0][0]);
            wmma::mma_sync(acc[0][0], ah0, bl, acc[0][0]);
            wmma::mma_sync(acc[0][0], ah0, bh, acc[0][0]);
            wmma::mma_sync(acc[0][1], al1, bh, acc[0][1]);
            wmma::mma_sync(acc[0][1], ah1, bl, acc[0][1]);
            wmma::mma_sync(acc[0][1], ah1, bh, acc[0][1]);
        }
        if (act1) {
            wmma::fragment<wmma::matrix_b, 16, 16, 16, __nv_bfloat16, wmma::row_major> bh, bl;
            long bo = ((long)kt * FIN_NT + 4 + nt0) << 8;
            wmma::load_matrix_sync(bh, Wh + bo, 16);
            wmma::load_matrix_sync(bl, Wl + bo, 16);
            wmma::mma_sync(acc[1][0], al0, bh, acc[1][0]);
            wmma::mma_sync(acc[1][0], ah0, bl, acc[1][0]);
            wmma::mma_sync(acc[1][0], ah0, bh, acc[1][0]);
            wmma::mma_sync(acc[1][1], al1, bh, acc[1][1]);
            wmma::mma_sync(acc[1][1], ah1, bl, acc[1][1]);
            wmma::mma_sync(acc[1][1], ah1, bh, acc[1][1]);
        }
    }
    __syncthreads();

#pragma unroll
    for (int i = 0; i < 2; i++) {
        wmma::store_matrix_sync(Cs + (wm + i * 16) * FIN_LDC + wn, acc[0][i], FIN_LDC, wmma::mem_row_major);
        if (act1)
            wmma::store_matrix_sync(Cs + (wm + i * 16) * FIN_LDC + 64 + wn, acc[1][i], FIN_LDC, wmma::mem_row_major);
    }
    __syncthreads();

    float g0 = ln_g[lane], g1 = ln_g[lane + 32], g2 = ln_g[lane + 64];
    float g3 = lane < 4 ? ln_g[96 + lane] : 0.f;
    float be0 = ln_b[lane], be1 = ln_b[lane + 32], be2 = ln_b[lane + 64];
    float be3 = lane < 4 ? ln_b[96 + lane] : 0.f;

    for (int r = wid * 8; r < wid * 8 + 8; r++) {
        int row = m0 + r;
        if (row >= NDST) continue;
        float* cr = Cs + r * FIN_LDC;
        float x0 = cr[lane];        x0 = x0 > 0.f ? x0 : 0.f;
        float x1 = cr[lane + 32];   x1 = x1 > 0.f ? x1 : 0.f;
        float x2 = cr[lane + 64];   x2 = x2 > 0.f ? x2 : 0.f;
        float x3 = lane < 4 ? cr[96 + lane] : 0.f;  x3 = x3 > 0.f ? x3 : 0.f;
        float s = x0 + x1 + x2 + x3;
        float sq = x0 * x0 + x1 * x1 + x2 * x2 + x3 * x3;
#pragma unroll
        for (int off = 16; off; off >>= 1) {
            s  += __shfl_xor_sync(0xffffffffu, s, off);
            sq += __shfl_xor_sync(0xffffffffu, sq, off);
        }
        float mu = s * 0.01f;
        float var = sq * 0.01f - mu * mu;
        float inv = rsqrtf(var + 1e-5f);
        float* orow = out + (long)row * DO_;
        orow[lane]      = (x0 - mu) * inv * g0 + be0;
        orow[lane + 32] = (x1 - mu) * inv * g1 + be1;
        orow[lane + 64] = (x2 - mu) * inv * g2 + be2;
        if (lane < 4) orow[96 + lane] = (x3 - mu) * inv * g3 + be3;
    }
}

// ---------------- launch ----------------
extern "C" void kernel_launch(void* const* d_in, const int* in_sizes, int n_in,
                              void* d_out, int out_size) {
    const float* nodeData = (const float*)d_in[0];
    const float* efeat    = (const float*)d_in[1];
    const float* utd      = (const float*)d_in[2];
    const int*   rev_nids = (const int*)d_in[3];
    const int*   rev_eids = (const int*)d_in[4];
    const int*   rev_tids = (const int*)d_in[5];
    const int*   dstindex = (const int*)d_in[6];
    const float* time_w   = (const float*)d_in[8];
    const float* time_b   = (const float*)d_in[9];
    const float* Wqn      = (const float*)d_in[10];
    const float* bqn      = (const float*)d_in[11];
    const float* Wqt      = (const float*)d_in[12];
    const float* bqt      = (const float*)d_in[13];
    const float* Wkvn     = (const float*)d_in[14];
    const float* bkvn     = (const float*)d_in[15];
    const float* Wkve     = (const float*)d_in[16];
    const float* bkve     = (const float*)d_in[17];
    const float* Wkvt     = (const float*)d_in[18];
    const float* bkvt     = (const float*)d_in[19];
    const float* Wout     = (const float*)d_in[20];
    const float* bout     = (const float*)d_in[21];
    const float* ln_g     = (const float*)d_in[22];
    const float* ln_b     = (const float*)d_in[23];
    float* out = (float*)d_out;

    float *pQ, *pbiasq;
    __half *pKVN, *pKVE, *pKVT;
    __nv_bfloat16* pWS;
    int* pCnt;
    cudaGetSymbolAddress((void**)&pQ,     g_Q);
    cudaGetSymbolAddress((void**)&pKVN,   g_KVN);
    cudaGetSymbolAddress((void**)&pKVE,   g_KVE);
    cudaGetSymbolAddress((void**)&pKVT,   g_KVT);
    cudaGetSymbolAddress((void**)&pbiasq, g_biasq);
    cudaGetSymbolAddress((void**)&pWS,    g_WS);
    cudaGetSymbolAddress((void**)&pCnt,   g_cnt);

    const int* node_inv = rev_nids + NDST;

    const int sm_nd = 64 * KP_ND * 2 * 2 + 8 * 256 * 4;   // 45056 + 8192 = 53248
    const int sm_t  = 64 * KP_T  * 2 * 2 + 8 * 256 * 4;   // 28672 + 8192 = 36864
    cudaFuncSetAttribute((const void*)gemm_bf10<true,  false, false>, cudaFuncAttributeMaxDynamicSharedMemorySize, sm_nd);
    cudaFuncSetAttribute((const void*)gemm_bf10<false, false, true >, cudaFuncAttributeMaxDynamicSharedMemorySize, sm_nd);
    cudaFuncSetAttribute((const void*)gemm_bf10<false, true,  true >, cudaFuncAttributeMaxDynamicSharedMemorySize, sm_nd);
    cudaFuncSetAttribute((const void*)finalize_bf, cudaFuncAttributeMaxDynamicSharedMemorySize, FIN_SMEM);

    cudaMemsetAsync(pCnt, 0, NDST * sizeof(int));

    // kernel launches: 1 hist, 2 split_w(kvn), 3 scan1, 4 gemm_kvn (profiled)
    hist_kernel<<<2048, 256>>>(dstindex);
    split_w<<<(KP_ND * NP_KV + 255) / 256, 256>>>(Wkvn, bkvn, bkve, bkvt,
        pWS + OFF_KVN_H, pWS + OFF_KVN_L, DN_, 2 * DO_, KP_ND, NP_KV);
    scan1_kernel<<<NB_SCAN, 1024>>>();

    gemm_bf10<false, false, true><<<UN / 64, 256, sm_nd>>>(
        nodeData, pWS + OFF_KVN_H, pWS + OFF_KVN_L, nullptr, pKVN, nullptr,
        nullptr, nullptr, nullptr, UN, DN_, KP_ND, NP_KV);

    scan2_kernel<<<1, 128>>>();
    scan3_kernel<<<NB_SCAN, 1024>>>();
    scatter_kernel<<<2048, 256>>>(dstindex, node_inv, rev_eids, rev_tids);
    biasq_kernel<<<1, 128>>>(time_b, Wqt, bqt, bqn);

    split_w<<<(KP_ND * NP_Q + 255) / 256, 256>>>(Wqn, pbiasq, nullptr, nullptr,
        pWS + OFF_QN_H, pWS + OFF_QN_L, DN_, DO_, KP_ND, NP_Q);
    split_w<<<(KP_ND * NP_KV + 255) / 256, 256>>>(Wkve, nullptr, nullptr, nullptr,
        pWS + OFF_KVE_H, pWS + OFF_KVE_L, DN_, 2 * DO_, KP_ND, NP_KV);
    split_w<<<(KP_T * NP_KV + 255) / 256, 256>>>(Wkvt, nullptr, nullptr, nullptr,
        pWS + OFF_KVT_H, pWS + OFF_KVT_L, DT_, 2 * DO_, KP_T, NP_KV);
    split_w<<<(KP_OUT * NP_Q + 255) / 256, 256>>>(Wout, bout, nullptr, nullptr,
        pWS + OFF_OUT_H, pWS + OFF_OUT_L, DN_ + DO_, DO_, KP_OUT, NP_Q);

    gemm_bf10<true, false, false><<<(NDST + 63) / 64, 256, sm_nd>>>(
        nodeData, pWS + OFF_QN_H, pWS + OFF_QN_L, pQ, nullptr, rev_nids,
        nullptr, nullptr, nullptr, NDST, DN_, KP_ND, NP_Q);
    gemm_bf10<false, false, true><<<(UE + 63) / 64, 256, sm_nd>>>(
        efeat, pWS + OFF_KVE_H, pWS + OFF_KVE_L, nullptr, pKVE, nullptr,
        nullptr, nullptr, nullptr, UE, DN_, KP_ND, NP_KV);
    gemm_bf10<false, true, true><<<(UT + 63) / 64, 256, sm_t>>>(
        nullptr, pWS + OFF_KVT_H, pWS + OFF_KVT_L, nullptr, pKVT, nullptr,
        utd, time_w, time_b, UT, DT_, KP_T, NP_KV);

    attn_kernel<<<(NDST + 7) / 8, 256>>>();

    finalize_bf<<<(NDST + 63) / 64, 256, FIN_SMEM>>>(
        nodeData, rev_nids, pWS + OFF_OUT_H, pWS + OFF_OUT_L, ln_g, ln_b, out);
}